// round 6
// baseline (speedup 1.0000x reference)
#include <cuda_runtime.h>
#include <math.h>
#include <stdint.h>
#include <stddef.h>

typedef unsigned long long u64;

#define NB   100
#define TT   512
#define IND  256
#define HD   1024
#define H3   3072
#define NDB  (HD * NB)   // 102400

// ---------------- scratch ----------------
__device__ float g_xp [(size_t)NB * TT * H3];   // xp [b][t][g]; later reused as S [u][(d,b)]
__device__ float g_xpt[(size_t)TT * H3 * NB];   // xp transposed [t][g][b]
__device__ float g_hst[(size_t)TT * HD * NB];   // h states [t][d][b]
__device__ float g_vt  [NDB];
__device__ float g_hpt [NDB];
__device__ float g_innert[NDB];
__device__ float g_catv8[HD * 8];
__device__ float g_hp2t [HD * 8];
__device__ float g_catot[HD * 5];
__device__ float g_as[NB];
__device__ float g_ad[NB];
__device__ float g_as2[8];
__device__ float g_ad2[8];
__device__ float g_fint[H3 * NB];
__device__ float g_ft  [HD * NB];
__device__ unsigned g_cnt;
__device__ unsigned g_gen;

// ---------------- f32x2 helpers ----------------
__device__ __forceinline__ u64 bcast2(float x) {
    u64 r; unsigned u = __float_as_uint(x);
    asm("mov.b64 %0, {%1, %1};" : "=l"(r) : "r"(u));
    return r;
}
__device__ __forceinline__ void fma2(u64& d, u64 a, u64 b) {
    asm("fma.rn.f32x2 %0, %1, %2, %0;" : "+l"(d) : "l"(a), "l"(b));
}
__device__ __forceinline__ float2 unpk(u64 v) {
    unsigned lo, hi;
    asm("mov.b64 {%0, %1}, %2;" : "=r"(lo), "=r"(hi) : "l"(v));
    return make_float2(__uint_as_float(lo), __uint_as_float(hi));
}
__device__ __forceinline__ float sigf(float x) { return 1.f / (1.f + expf(-x)); }

// =================================================================
// SGEMM NT: C[M,N] = A[M,K] @ B[N,K]^T + colbias[N]
// =================================================================
__global__ __launch_bounds__(256) void gemm_nt(
    const float* __restrict__ A, const float* __restrict__ B,
    const float* __restrict__ colbias, float* __restrict__ C,
    int M, int N, int K, int act)
{
    __shared__ float As[16][128];
    __shared__ float Bs[16][128];
    int tid = threadIdx.x;
    int tx = tid & 15, ty = tid >> 4;
    int row0 = blockIdx.y * 128, col0 = blockIdx.x * 128;

    u64 acc[8][4];
#pragma unroll
    for (int i = 0; i < 8; i++)
#pragma unroll
        for (int j = 0; j < 4; j++) acc[i][j] = 0ull;

    int lr = tid >> 2, lc = tid & 3;
    for (int k0 = 0; k0 < K; k0 += 16) {
#pragma unroll
        for (int p = 0; p < 2; p++) {
            int r = lr + p * 64, gr = row0 + r;
            float4 v = make_float4(0.f, 0.f, 0.f, 0.f);
            if (gr < M) v = *(const float4*)(A + (size_t)gr * K + k0 + lc * 4);
            As[lc*4+0][r] = v.x; As[lc*4+1][r] = v.y; As[lc*4+2][r] = v.z; As[lc*4+3][r] = v.w;
        }
#pragma unroll
        for (int p = 0; p < 2; p++) {
            int r = lr + p * 64, gc = col0 + r;
            float4 v = make_float4(0.f, 0.f, 0.f, 0.f);
            if (gc < N) v = *(const float4*)(B + (size_t)gc * K + k0 + lc * 4);
            Bs[lc*4+0][r] = v.x; Bs[lc*4+1][r] = v.y; Bs[lc*4+2][r] = v.z; Bs[lc*4+3][r] = v.w;
        }
        __syncthreads();
#pragma unroll
        for (int kk = 0; kk < 16; kk++) {
            float a[8];
            *(float4*)&a[0] = *(const float4*)&As[kk][ty * 8];
            *(float4*)&a[4] = *(const float4*)&As[kk][ty * 8 + 4];
            u64 b4[4];
#pragma unroll
            for (int j = 0; j < 4; j++) b4[j] = *(const u64*)&Bs[kk][tx * 8 + 2 * j];
#pragma unroll
            for (int i = 0; i < 8; i++) {
                u64 ai = bcast2(a[i]);
#pragma unroll
                for (int j = 0; j < 4; j++) fma2(acc[i][j], ai, b4[j]);
            }
        }
        __syncthreads();
    }
#pragma unroll
    for (int i = 0; i < 8; i++) {
        int gm = row0 + ty * 8 + i;
        if (gm >= M) continue;
#pragma unroll
        for (int j = 0; j < 4; j++) {
            float2 c2 = unpk(acc[i][j]);
            int gn = col0 + tx * 8 + 2 * j;
            float v0 = c2.x, v1 = c2.y;
            if (colbias) { v0 += colbias[gn]; v1 += colbias[gn + 1]; }
            if (act == 1) { v0 = fmaxf(v0, 0.f); v1 = fmaxf(v1, 0.f); }
            if (gn < N)     C[(size_t)gm * N + gn]     = v0;
            if (gn + 1 < N) C[(size_t)gm * N + gn + 1] = v1;
        }
    }
}

// =================================================================
// SGEMM NN: C[M,N] = A[M,K] @ B[K,N] (+ rowbias[M]) (+relu). N%4==0.
// =================================================================
__global__ __launch_bounds__(256) void gemm_nn(
    const float* __restrict__ A, const float* __restrict__ B,
    const float* __restrict__ rowbias, float* __restrict__ C,
    int M, int N, int K, int act)
{
    __shared__ float As[16][128];
    __shared__ float Bs[16][128];
    int tid = threadIdx.x;
    int tx = tid & 15, ty = tid >> 4;
    int row0 = blockIdx.y * 128, col0 = blockIdx.x * 128;

    u64 acc[8][4];
#pragma unroll
    for (int i = 0; i < 8; i++)
#pragma unroll
        for (int j = 0; j < 4; j++) acc[i][j] = 0ull;

    int lr = tid >> 2, lc = tid & 3;
    int br = tid >> 5, bc = tid & 31;
    for (int k0 = 0; k0 < K; k0 += 16) {
#pragma unroll
        for (int p = 0; p < 2; p++) {
            int r = lr + p * 64, gr = row0 + r;
            float4 v = make_float4(0.f, 0.f, 0.f, 0.f);
            if (gr < M) v = *(const float4*)(A + (size_t)gr * K + k0 + lc * 4);
            As[lc*4+0][r] = v.x; As[lc*4+1][r] = v.y; As[lc*4+2][r] = v.z; As[lc*4+3][r] = v.w;
        }
#pragma unroll
        for (int p = 0; p < 2; p++) {
            int k = br + p * 8;
            int gc = col0 + bc * 4;
            float4 v = make_float4(0.f, 0.f, 0.f, 0.f);
            if (gc < N) v = *(const float4*)(B + (size_t)(k0 + k) * N + gc);
            *(float4*)&Bs[k][bc * 4] = v;
        }
        __syncthreads();
#pragma unroll
        for (int kk = 0; kk < 16; kk++) {
            float a[8];
            *(float4*)&a[0] = *(const float4*)&As[kk][ty * 8];
            *(float4*)&a[4] = *(const float4*)&As[kk][ty * 8 + 4];
            u64 b4[4];
#pragma unroll
            for (int j = 0; j < 4; j++) b4[j] = *(const u64*)&Bs[kk][tx * 8 + 2 * j];
#pragma unroll
            for (int i = 0; i < 8; i++) {
                u64 ai = bcast2(a[i]);
#pragma unroll
                for (int j = 0; j < 4; j++) fma2(acc[i][j], ai, b4[j]);
            }
        }
        __syncthreads();
    }
#pragma unroll
    for (int i = 0; i < 8; i++) {
        int gm = row0 + ty * 8 + i;
        if (gm >= M) continue;
        float rb = rowbias ? rowbias[gm] : 0.f;
#pragma unroll
        for (int j = 0; j < 4; j++) {
            float2 c2 = unpk(acc[i][j]);
            int gn = col0 + tx * 8 + 2 * j;
            float v0 = c2.x + rb, v1 = c2.y + rb;
            if (act == 1) { v0 = fmaxf(v0, 0.f); v1 = fmaxf(v1, 0.f); }
            if (gn < N)     C[(size_t)gm * N + gn]     = v0;
            if (gn + 1 < N) C[(size_t)gm * N + gn + 1] = v1;
        }
    }
}

// =================================================================
// Transpose xp[b][t][g] -> xpt[t][g][b]
// =================================================================
__global__ __launch_bounds__(256) void transpose_xp(
    const float* __restrict__ xp, float* __restrict__ xpt)
{
    __shared__ float tile[NB][33];
    int t  = blockIdx.x;
    int g0 = blockIdx.y * 32;
    int tx = threadIdx.x & 31;
    int ty = threadIdx.x >> 5;

    for (int b = ty; b < NB; b += 8)
        tile[b][tx] = xp[((size_t)b * TT + t) * H3 + g0 + tx];
    __syncthreads();

    for (int gi = ty; gi < 32; gi += 8) {
        size_t base = ((size_t)t * H3 + g0 + gi) * NB;
#pragma unroll
        for (int c = 0; c < 4; c++) {
            int b = c * 32 + tx;
            if (b < NB) xpt[base + b] = tile[b][gi];
        }
    }
}

// =================================================================
// Persistent GRU v6: 128 blocks x 128 threads (4 warps).
// Warp = 2 columns; lane = 4 batches (25 active lanes).
// Weights duplicated f32x2 in smem: [warp][k][6] u64 = 196608 B,
// loaded ONCE. h read directly (LDG.128, MSHR-merged across warps).
// =================================================================
#define WDUP_U64 (4 * 1024 * 6)

__device__ __forceinline__ void gridbar()
{
    __threadfence();
    __syncthreads();
    if (threadIdx.x == 0) {
        volatile unsigned* vg = &g_gen;
        unsigned target = *vg + 1;
        if (atomicAdd(&g_cnt, 1) == gridDim.x - 1) {
            g_cnt = 0;
            __threadfence();
            atomicAdd(&g_gen, 1);
        } else {
            while ((int)(*vg - target) < 0) { }
        }
        __threadfence();
    }
    __syncthreads();
}

__global__ __launch_bounds__(128, 1) void gru_persist(
    const float* __restrict__ xpt, const float* __restrict__ Whh,
    const float* __restrict__ bhh, float* __restrict__ hst)
{
    extern __shared__ u64 wdup[];   // [4 warps][1024 k][6] (g0c0,g0c1,g1c0,g1c1,g2c0,g2c1)
    int tid  = threadIdx.x;
    int w    = tid >> 5;
    int lane = tid & 31;
    int c0   = blockIdx.x * 8 + w * 2;
    int c1   = c0 + 1;
    int b0   = (lane < 25 ? lane : 24) * 4;   // clamp inactive lanes
    bool act = (lane < 25);

    // one-time weight load + duplication
    for (int i = tid; i < WDUP_U64; i += 128) {
        int ww = i / 6144, r = i % 6144, k = r / 6, e = r % 6;
        int g = e >> 1, cc = e & 1;
        float v = Whh[((size_t)g * HD + blockIdx.x * 8 + ww * 2 + cc) * HD + k];
        wdup[i] = bcast2(v);
    }
    float br0 = bhh[c0], bz0 = bhh[HD + c0], bn0 = bhh[2 * HD + c0];
    float br1 = bhh[c1], bz1 = bhh[HD + c1], bn1 = bhh[2 * HD + c1];
    __syncthreads();

    const u64* wbase = wdup + (size_t)w * 6144;

    for (int t = 0; t < TT; t++) {
        // acc[col][gate][bpair]
        u64 a000 = 0, a001 = 0, a010 = 0, a011 = 0, a020 = 0, a021 = 0;
        u64 a100 = 0, a101 = 0, a110 = 0, a111 = 0, a120 = 0, a121 = 0;
        ulonglong2 hold0, hold1;
        hold0.x = hold0.y = hold1.x = hold1.y = 0ull;

        if (t > 0) {
            const float* hp = hst + (size_t)(t - 1) * NDB;
            hold0 = *(const ulonglong2*)(hp + (size_t)c0 * NB + b0);
            hold1 = *(const ulonglong2*)(hp + (size_t)c1 * NB + b0);
            const u64* wk = wbase;
            const float* hk = hp + b0;
            for (int k = 0; k < HD; k += 64) {
                __syncthreads();   // keep warps in lockstep for MSHR merge
#pragma unroll 2
                for (int kk = 0; kk < 64; kk++) {
                    ulonglong2 hq = *(const ulonglong2*)hk;
                    ulonglong2 w01 = *(const ulonglong2*)(wk);
                    ulonglong2 w23 = *(const ulonglong2*)(wk + 2);
                    ulonglong2 w45 = *(const ulonglong2*)(wk + 4);
                    fma2(a000, w01.x, hq.x); fma2(a001, w01.x, hq.y);
                    fma2(a100, w01.y, hq.x); fma2(a101, w01.y, hq.y);
                    fma2(a010, w23.x, hq.x); fma2(a011, w23.x, hq.y);
                    fma2(a110, w23.y, hq.x); fma2(a111, w23.y, hq.y);
                    fma2(a020, w45.x, hq.x); fma2(a021, w45.x, hq.y);
                    fma2(a120, w45.y, hq.x); fma2(a121, w45.y, hq.y);
                    wk += 6;
                    hk += NB;
                }
            }
        }

        // combine gates + write h(t)
        size_t xb = (size_t)t * H3 * (size_t)NB;
        {
            float2 pr0 = unpk(a000), pr1 = unpk(a001);
            float2 pz0 = unpk(a010), pz1 = unpk(a011);
            float2 pn0 = unpk(a020), pn1 = unpk(a021);
            float2 ho0 = unpk(hold0.x), ho1 = unpk(hold0.y);
            float4 xr = *(const float4*)(xpt + xb + (size_t)c0 * NB + b0);
            float4 xz = *(const float4*)(xpt + xb + (size_t)(HD + c0) * NB + b0);
            float4 xn = *(const float4*)(xpt + xb + (size_t)(2 * HD + c0) * NB + b0);
            float arr[4] = { pr0.x, pr0.y, pr1.x, pr1.y };
            float azz[4] = { pz0.x, pz0.y, pz1.x, pz1.y };
            float ann[4] = { pn0.x, pn0.y, pn1.x, pn1.y };
            float hvv[4] = { ho0.x, ho0.y, ho1.x, ho1.y };
            float xrv[4] = { xr.x, xr.y, xr.z, xr.w };
            float xzv[4] = { xz.x, xz.y, xz.z, xz.w };
            float xnv[4] = { xn.x, xn.y, xn.z, xn.w };
            float out[4];
#pragma unroll
            for (int q = 0; q < 4; q++) {
                float r = sigf(xrv[q] + arr[q] + br0);
                float z = sigf(xzv[q] + azz[q] + bz0);
                float n = tanhf(xnv[q] + r * (ann[q] + bn0));
                out[q] = (1.f - z) * n + z * hvv[q];
            }
            if (act)
                *(float4*)(hst + (size_t)t * NDB + (size_t)c0 * NB + b0) =
                    make_float4(out[0], out[1], out[2], out[3]);
        }
        {
            float2 pr0 = unpk(a100), pr1 = unpk(a101);
            float2 pz0 = unpk(a110), pz1 = unpk(a111);
            float2 pn0 = unpk(a120), pn1 = unpk(a121);
            float2 ho0 = unpk(hold1.x), ho1 = unpk(hold1.y);
            float4 xr = *(const float4*)(xpt + xb + (size_t)c1 * NB + b0);
            float4 xz = *(const float4*)(xpt + xb + (size_t)(HD + c1) * NB + b0);
            float4 xn = *(const float4*)(xpt + xb + (size_t)(2 * HD + c1) * NB + b0);
            float arr[4] = { pr0.x, pr0.y, pr1.x, pr1.y };
            float azz[4] = { pz0.x, pz0.y, pz1.x, pz1.y };
            float ann[4] = { pn0.x, pn0.y, pn1.x, pn1.y };
            float hvv[4] = { ho0.x, ho0.y, ho1.x, ho1.y };
            float xrv[4] = { xr.x, xr.y, xr.z, xr.w };
            float xzv[4] = { xz.x, xz.y, xz.z, xz.w };
            float xnv[4] = { xn.x, xn.y, xn.z, xn.w };
            float out[4];
#pragma unroll
            for (int q = 0; q < 4; q++) {
                float r = sigf(xrv[q] + arr[q] + br1);
                float z = sigf(xzv[q] + azz[q] + bz1);
                float n = tanhf(xnv[q] + r * (ann[q] + bn1));
                out[q] = (1.f - z) * n + z * hvv[q];
            }
            if (act)
                *(float4*)(hst + (size_t)t * NDB + (size_t)c1 * NB + b0) =
                    make_float4(out[0], out[1], out[2], out[3]);
        }

        gridbar();
    }
}

// =================================================================
// one-pass online-softmax reduce
// =================================================================
__global__ void att_reduce_flat(const float* __restrict__ S,
                                const float* __restrict__ H,
                                float* __restrict__ vt)
{
    int j = blockIdx.x * 256 + threadIdx.x;
    float mx = -1e30f, se = 0.f, sv = 0.f;
#pragma unroll 4
    for (int u = 0; u < TT; u++) {
        float s = S[(size_t)u * NDB + j];
        float h = H[(size_t)u * NDB + j];
        float m2 = fmaxf(mx, s);
        float cor = expf(mx - m2);
        float e = expf(s - m2);
        se = se * cor + e;
        sv = sv * cor + e * h;
        mx = m2;
    }
    vt[j] = sv / se;
}

// pool attention on vt[d][b] -> catv8[d*8 + c]
__global__ void pool_att_t(const float* __restrict__ vt, const float* __restrict__ pW,
                           const float* __restrict__ pb, float* __restrict__ catv8)
{
    int c = blockIdx.x;
    int d = blockIdx.y * 256 + threadIdx.x;
    if (c >= 5) { catv8[(size_t)d * 8 + c] = 0.f; return; }
    __shared__ float sW[400];
    __shared__ float sb[20];
    for (int i = threadIdx.x; i < 400; i += 256) sW[i] = pW[i];
    if (threadIdx.x < 20) sb[threadIdx.x] = pb[threadIdx.x];
    __syncthreads();

    float xv[20];
#pragma unroll
    for (int s = 0; s < 20; s++) xv[s] = vt[(size_t)d * NB + c * 20 + s];
    float wv[20]; float mx = -1e30f;
#pragma unroll
    for (int u = 0; u < 20; u++) {
        float s = sb[u];
#pragma unroll
        for (int t2 = 0; t2 < 20; t2++) s += xv[t2] * sW[u * 20 + t2];
        wv[u] = s; mx = fmaxf(mx, s);
    }
    float se = 0.f, sv = 0.f;
#pragma unroll
    for (int u = 0; u < 20; u++) {
        float e = expf(wv[u] - mx);
        se += e; sv += e * xv[u];
    }
    catv8[(size_t)d * 8 + c] = sv / se;
}

__global__ void dot2_t(const float* __restrict__ ht, const float* __restrict__ a1,
                       const float* __restrict__ a2, float* __restrict__ o1,
                       float* __restrict__ o2, int stride)
{
    int n = blockIdx.x;
    __shared__ float s1[256], s2[256];
    float p1 = 0.f, p2 = 0.f;
    for (int j = threadIdx.x; j < HD; j += 256) {
        float hv = ht[(size_t)j * stride + n];
        p1 += hv * a1[j]; p2 += hv * a2[j];
    }
    s1[threadIdx.x] = p1; s2[threadIdx.x] = p2;
    __syncthreads();
    for (int s = 128; s > 0; s >>= 1) {
        if (threadIdx.x < s) { s1[threadIdx.x] += s1[threadIdx.x + s]; s2[threadIdx.x] += s2[threadIdx.x + s]; }
        __syncthreads();
    }
    if (threadIdx.x == 0) { o1[n] = s1[0]; o2[n] = s2[0]; }
}

__global__ void gat_agg_t(const float* __restrict__ ht, const float* __restrict__ as,
                          const float* __restrict__ ad, const float* __restrict__ bias,
                          float* __restrict__ outt, int group, int stride, int ostride)
{
    int n = blockIdx.x;
    int base = (n / group) * group;
    __shared__ float alpha[32];
    if (threadIdx.x == 0) {
        float e[32]; float mx = -1e30f;
        for (int s = 0; s < group; s++) {
            float x = as[base + s] + ad[n];
            x = (x > 0.f) ? x : 0.2f * x;
            e[s] = x; mx = fmaxf(mx, x);
        }
        float se = 0.f;
        for (int s = 0; s < group; s++) { e[s] = expf(e[s] - mx); se += e[s]; }
        for (int s = 0; s < group; s++) alpha[s] = e[s] / se;
    }
    __syncthreads();
    for (int j = threadIdx.x; j < HD; j += 256) {
        float acc = 0.f;
        for (int s = 0; s < group; s++)
            acc += alpha[s] * ht[(size_t)j * stride + base + s];
        outt[(size_t)j * ostride + n] = acc + bias[j];
    }
}

__global__ void build_fusion_t(const float* __restrict__ vt, const float* __restrict__ catot,
                               const float* __restrict__ innert, float* __restrict__ fint)
{
    int idx = blockIdx.x * 256 + threadIdx.x;
    if (idx >= H3 * NB) return;
    int k = idx / NB, n = idx - k * NB;
    float val;
    if (k < HD)            val = vt[(size_t)k * NB + n];
    else if (k < 2 * HD)   val = catot[(size_t)(k - HD) * 5 + n / 20];
    else                   val = innert[(size_t)(k - 2 * HD) * NB + n];
    fint[idx] = val;
}

__global__ void heads_t(const float* __restrict__ ft, const float* __restrict__ rw,
                        const float* __restrict__ rb, const float* __restrict__ cw,
                        const float* __restrict__ cb, float* __restrict__ out)
{
    int n = blockIdx.x;
    __shared__ float s1[256], s2[256];
    float p1 = 0.f, p2 = 0.f;
    for (int j = threadIdx.x; j < HD; j += 256) {
        float fv = ft[(size_t)j * NB + n];
        p1 += fv * rw[j]; p2 += fv * cw[j];
    }
    s1[threadIdx.x] = p1; s2[threadIdx.x] = p2;
    __syncthreads();
    for (int s = 128; s > 0; s >>= 1) {
        if (threadIdx.x < s) { s1[threadIdx.x] += s1[threadIdx.x + s]; s2[threadIdx.x] += s2[threadIdx.x + s]; }
        __syncthreads();
    }
    if (threadIdx.x == 0) {
        out[n]      = s1[0] + rb[0];
        out[NB + n] = 1.f / (1.f + expf(-(s2[0] + cb[0])));
    }
}

// =================================================================
extern "C" void kernel_launch(void* const* d_in, const int* in_sizes, int n_in,
                              void* d_out, int out_size)
{
    const float* weekly  = (const float*)d_in[0];
    const float* Wih     = (const float*)d_in[1];
    const float* Whh     = (const float*)d_in[2];
    const float* bih     = (const float*)d_in[3];
    const float* bhh     = (const float*)d_in[4];
    const float* encW    = (const float*)d_in[5];
    const float* encB    = (const float*)d_in[6];
    const float* poolW   = (const float*)d_in[7];
    const float* poolB   = (const float*)d_in[8];
    const float* innerW  = (const float*)d_in[9];
    const float* innerAs = (const float*)d_in[10];
    const float* innerAd = (const float*)d_in[11];
    const float* innerB  = (const float*)d_in[12];
    const float* catW    = (const float*)d_in[13];
    const float* catAs   = (const float*)d_in[14];
    const float* catAd   = (const float*)d_in[15];
    const float* catB    = (const float*)d_in[16];
    const float* fusW    = (const float*)d_in[17];
    const float* fusB    = (const float*)d_in[18];
    const float* regW    = (const float*)d_in[19];
    const float* regB    = (const float*)d_in[20];
    const float* clsW    = (const float*)d_in[21];
    const float* clsB    = (const float*)d_in[22];
    float* out = (float*)d_out;

    float *xp, *xpt, *hst, *vt, *hpt, *innert, *catv8, *hp2t, *catot, *as_, *ad_, *as2, *ad2, *fint, *ftb;
    cudaGetSymbolAddress((void**)&xp,     g_xp);
    cudaGetSymbolAddress((void**)&xpt,    g_xpt);
    cudaGetSymbolAddress((void**)&hst,    g_hst);
    cudaGetSymbolAddress((void**)&vt,     g_vt);
    cudaGetSymbolAddress((void**)&hpt,    g_hpt);
    cudaGetSymbolAddress((void**)&innert, g_innert);
    cudaGetSymbolAddress((void**)&catv8,  g_catv8);
    cudaGetSymbolAddress((void**)&hp2t,   g_hp2t);
    cudaGetSymbolAddress((void**)&catot,  g_catot);
    cudaGetSymbolAddress((void**)&as_,    g_as);
    cudaGetSymbolAddress((void**)&ad_,    g_ad);
    cudaGetSymbolAddress((void**)&as2,    g_as2);
    cudaGetSymbolAddress((void**)&ad2,    g_ad2);
    cudaGetSymbolAddress((void**)&fint,   g_fint);
    cudaGetSymbolAddress((void**)&ftb,    g_ft);

    // 1) xp = weekly(51200,256) @ Wih^T + bih
    gemm_nt<<<dim3(H3 / 128, (NB * TT) / 128), 256>>>(weekly, Wih, bih, xp, NB * TT, H3, IND, 0);

    // 1b) transpose to xpt[t][g][b]
    transpose_xp<<<dim3(TT, H3 / 32), 256>>>(xp, xpt);

    // 2) persistent GRU v6
    int smem = WDUP_U64 * 8;   // 196608
    cudaFuncSetAttribute(gru_persist, cudaFuncAttributeMaxDynamicSharedMemorySize, smem);
    gru_persist<<<128, 128, smem>>>(xpt, Whh, bhh, hst);

    // 3) S(512 x 102400) = encW @ H + encB[u]  (reuse xp buffer)
    gemm_nn<<<dim3(NDB / 128, TT / 128), 256>>>(encW, hst, encB, xp, TT, NDB, TT, 0);

    // 4) vt[j] = softmax-over-u(S) . H
    att_reduce_flat<<<NDB / 256, 256>>>(xp, hst, vt);

    // 5) inner GAT
    gemm_nn<<<dim3(1, HD / 128), 256>>>(innerW, vt, nullptr, hpt, HD, NB, HD, 0);
    dot2_t<<<NB, 256>>>(hpt, innerAs, innerAd, as_, ad_, NB);
    gat_agg_t<<<NB, 256>>>(hpt, as_, ad_, innerB, innert, 20, NB, NB);

    // 6) pool
    pool_att_t<<<dim3(8, HD / 256), 256>>>(vt, poolW, poolB, catv8);

    // 7) category GAT
    gemm_nn<<<dim3(1, HD / 128), 256>>>(catW, catv8, nullptr, hp2t, HD, 8, HD, 0);
    dot2_t<<<5, 256>>>(hp2t, catAs, catAd, as2, ad2, 8);
    gat_agg_t<<<5, 256>>>(hp2t, as2, ad2, catB, catot, 5, 8, 5);

    // 8) fusion
    build_fusion_t<<<(H3 * NB + 255) / 256, 256>>>(vt, catot, innert, fint);
    gemm_nn<<<dim3(1, HD / 128), 256>>>(fusW, fint, fusB, ftb, HD, NB, H3, 1);

    // 9) heads
    heads_t<<<NB, 256>>>(ftb, regW, regB, clsW, clsB, out);
}

// round 7
// speedup vs baseline: 4.1495x; 4.1495x over previous
#include <cuda_runtime.h>
#include <math.h>
#include <stdint.h>
#include <stddef.h>

typedef unsigned long long u64;

#define NB   100
#define TT   512
#define IND  256
#define HD   1024
#define H3   3072
#define NDB  (HD * NB)   // 102400

// ---------------- scratch ----------------
__device__ float g_xp [(size_t)NB * TT * H3];   // xp [b][t][g]; later reused as S [u][(d,b)]
__device__ float g_xpt[(size_t)TT * H3 * NB];   // xp transposed [t][g][b]
__device__ float g_hst[(size_t)TT * HD * NB];   // h states [t][d][b]
__device__ float g_vt  [NDB];
__device__ float g_hpt [NDB];
__device__ float g_innert[NDB];
__device__ float g_catv8[HD * 8];
__device__ float g_hp2t [HD * 8];
__device__ float g_catot[HD * 5];
__device__ float g_as[NB];
__device__ float g_ad[NB];
__device__ float g_as2[8];
__device__ float g_ad2[8];
__device__ float g_fint[H3 * NB];
__device__ float g_ft  [HD * NB];
__device__ unsigned g_cnt;
__device__ unsigned g_gen;

// ---------------- f32x2 helpers ----------------
__device__ __forceinline__ u64 bcast2(float x) {
    u64 r; unsigned u = __float_as_uint(x);
    asm("mov.b64 %0, {%1, %1};" : "=l"(r) : "r"(u));
    return r;
}
__device__ __forceinline__ void fma2(u64& d, u64 a, u64 b) {
    asm("fma.rn.f32x2 %0, %1, %2, %0;" : "+l"(d) : "l"(a), "l"(b));
}
__device__ __forceinline__ float2 unpk(u64 v) {
    unsigned lo, hi;
    asm("mov.b64 {%0, %1}, %2;" : "=r"(lo), "=r"(hi) : "l"(v));
    return make_float2(__uint_as_float(lo), __uint_as_float(hi));
}
__device__ __forceinline__ float sigf(float x) { return 1.f / (1.f + expf(-x)); }

// =================================================================
// SGEMM NT: C[M,N] = A[M,K] @ B[N,K]^T + colbias[N]
// =================================================================
__global__ __launch_bounds__(256) void gemm_nt(
    const float* __restrict__ A, const float* __restrict__ B,
    const float* __restrict__ colbias, float* __restrict__ C,
    int M, int N, int K, int act)
{
    __shared__ float As[16][128];
    __shared__ float Bs[16][128];
    int tid = threadIdx.x;
    int tx = tid & 15, ty = tid >> 4;
    int row0 = blockIdx.y * 128, col0 = blockIdx.x * 128;

    u64 acc[8][4];
#pragma unroll
    for (int i = 0; i < 8; i++)
#pragma unroll
        for (int j = 0; j < 4; j++) acc[i][j] = 0ull;

    int lr = tid >> 2, lc = tid & 3;
    for (int k0 = 0; k0 < K; k0 += 16) {
#pragma unroll
        for (int p = 0; p < 2; p++) {
            int r = lr + p * 64, gr = row0 + r;
            float4 v = make_float4(0.f, 0.f, 0.f, 0.f);
            if (gr < M) v = *(const float4*)(A + (size_t)gr * K + k0 + lc * 4);
            As[lc*4+0][r] = v.x; As[lc*4+1][r] = v.y; As[lc*4+2][r] = v.z; As[lc*4+3][r] = v.w;
        }
#pragma unroll
        for (int p = 0; p < 2; p++) {
            int r = lr + p * 64, gc = col0 + r;
            float4 v = make_float4(0.f, 0.f, 0.f, 0.f);
            if (gc < N) v = *(const float4*)(B + (size_t)gc * K + k0 + lc * 4);
            Bs[lc*4+0][r] = v.x; Bs[lc*4+1][r] = v.y; Bs[lc*4+2][r] = v.z; Bs[lc*4+3][r] = v.w;
        }
        __syncthreads();
#pragma unroll
        for (int kk = 0; kk < 16; kk++) {
            float a[8];
            *(float4*)&a[0] = *(const float4*)&As[kk][ty * 8];
            *(float4*)&a[4] = *(const float4*)&As[kk][ty * 8 + 4];
            u64 b4[4];
#pragma unroll
            for (int j = 0; j < 4; j++) b4[j] = *(const u64*)&Bs[kk][tx * 8 + 2 * j];
#pragma unroll
            for (int i = 0; i < 8; i++) {
                u64 ai = bcast2(a[i]);
#pragma unroll
                for (int j = 0; j < 4; j++) fma2(acc[i][j], ai, b4[j]);
            }
        }
        __syncthreads();
    }
#pragma unroll
    for (int i = 0; i < 8; i++) {
        int gm = row0 + ty * 8 + i;
        if (gm >= M) continue;
#pragma unroll
        for (int j = 0; j < 4; j++) {
            float2 c2 = unpk(acc[i][j]);
            int gn = col0 + tx * 8 + 2 * j;
            float v0 = c2.x, v1 = c2.y;
            if (colbias) { v0 += colbias[gn]; v1 += colbias[gn + 1]; }
            if (act == 1) { v0 = fmaxf(v0, 0.f); v1 = fmaxf(v1, 0.f); }
            if (gn < N)     C[(size_t)gm * N + gn]     = v0;
            if (gn + 1 < N) C[(size_t)gm * N + gn + 1] = v1;
        }
    }
}

// =================================================================
// SGEMM NN: C[M,N] = A[M,K] @ B[K,N] (+ rowbias[M]) (+relu). N%4==0.
// =================================================================
__global__ __launch_bounds__(256) void gemm_nn(
    const float* __restrict__ A, const float* __restrict__ B,
    const float* __restrict__ rowbias, float* __restrict__ C,
    int M, int N, int K, int act)
{
    __shared__ float As[16][128];
    __shared__ float Bs[16][128];
    int tid = threadIdx.x;
    int tx = tid & 15, ty = tid >> 4;
    int row0 = blockIdx.y * 128, col0 = blockIdx.x * 128;

    u64 acc[8][4];
#pragma unroll
    for (int i = 0; i < 8; i++)
#pragma unroll
        for (int j = 0; j < 4; j++) acc[i][j] = 0ull;

    int lr = tid >> 2, lc = tid & 3;
    int br = tid >> 5, bc = tid & 31;
    for (int k0 = 0; k0 < K; k0 += 16) {
#pragma unroll
        for (int p = 0; p < 2; p++) {
            int r = lr + p * 64, gr = row0 + r;
            float4 v = make_float4(0.f, 0.f, 0.f, 0.f);
            if (gr < M) v = *(const float4*)(A + (size_t)gr * K + k0 + lc * 4);
            As[lc*4+0][r] = v.x; As[lc*4+1][r] = v.y; As[lc*4+2][r] = v.z; As[lc*4+3][r] = v.w;
        }
#pragma unroll
        for (int p = 0; p < 2; p++) {
            int k = br + p * 8;
            int gc = col0 + bc * 4;
            float4 v = make_float4(0.f, 0.f, 0.f, 0.f);
            if (gc < N) v = *(const float4*)(B + (size_t)(k0 + k) * N + gc);
            *(float4*)&Bs[k][bc * 4] = v;
        }
        __syncthreads();
#pragma unroll
        for (int kk = 0; kk < 16; kk++) {
            float a[8];
            *(float4*)&a[0] = *(const float4*)&As[kk][ty * 8];
            *(float4*)&a[4] = *(const float4*)&As[kk][ty * 8 + 4];
            u64 b4[4];
#pragma unroll
            for (int j = 0; j < 4; j++) b4[j] = *(const u64*)&Bs[kk][tx * 8 + 2 * j];
#pragma unroll
            for (int i = 0; i < 8; i++) {
                u64 ai = bcast2(a[i]);
#pragma unroll
                for (int j = 0; j < 4; j++) fma2(acc[i][j], ai, b4[j]);
            }
        }
        __syncthreads();
    }
#pragma unroll
    for (int i = 0; i < 8; i++) {
        int gm = row0 + ty * 8 + i;
        if (gm >= M) continue;
        float rb = rowbias ? rowbias[gm] : 0.f;
#pragma unroll
        for (int j = 0; j < 4; j++) {
            float2 c2 = unpk(acc[i][j]);
            int gn = col0 + tx * 8 + 2 * j;
            float v0 = c2.x + rb, v1 = c2.y + rb;
            if (act == 1) { v0 = fmaxf(v0, 0.f); v1 = fmaxf(v1, 0.f); }
            if (gn < N)     C[(size_t)gm * N + gn]     = v0;
            if (gn + 1 < N) C[(size_t)gm * N + gn + 1] = v1;
        }
    }
}

// =================================================================
// Transpose xp[b][t][g] -> xpt[t][g][b]
// =================================================================
__global__ __launch_bounds__(256) void transpose_xp(
    const float* __restrict__ xp, float* __restrict__ xpt)
{
    __shared__ float tile[NB][33];
    int t  = blockIdx.x;
    int g0 = blockIdx.y * 32;
    int tx = threadIdx.x & 31;
    int ty = threadIdx.x >> 5;

    for (int b = ty; b < NB; b += 8)
        tile[b][tx] = xp[((size_t)b * TT + t) * H3 + g0 + tx];
    __syncthreads();

    for (int gi = ty; gi < 32; gi += 8) {
        size_t base = ((size_t)t * H3 + g0 + gi) * NB;
#pragma unroll
        for (int c = 0; c < 4; c++) {
            int b = c * 32 + tx;
            if (b < NB) xpt[base + b] = tile[b][gi];
        }
    }
}

// =================================================================
// Persistent GRU v7: k-split across warps.
// 128 blocks x 256 threads (8 warps). Block owns 8 columns.
// Warp w owns k in [128w, 128w+128); lane = 4 batches (25 active).
// Each block reads h exactly ONCE per step (no redundancy).
// Weights duplicated f32x2 in smem (196608 B) + partial buffer
// (25600 B) for cross-warp gate reduction in 3 gate-rounds.
// =================================================================
#define WDUP_U64 (1024 * 24)          // [k][j=c*3+g] duplicated pairs
#define PBUF_U64 (8 * 8 * 2 * 25)     // [warp][col][pair][lane]

__device__ __forceinline__ void gridbar()
{
    __threadfence();
    __syncthreads();
    if (threadIdx.x == 0) {
        volatile unsigned* vg = &g_gen;
        unsigned target = *vg + 1;
        if (atomicAdd(&g_cnt, 1) == gridDim.x - 1) {
            g_cnt = 0;
            __threadfence();
            atomicAdd(&g_gen, 1);
        } else {
            while ((int)(*vg - target) < 0) { }
        }
        __threadfence();
    }
    __syncthreads();
}

__global__ __launch_bounds__(256, 1) void gru_persist(
    const float* __restrict__ xpt, const float* __restrict__ Whh,
    const float* __restrict__ bhh, float* __restrict__ hst)
{
    extern __shared__ u64 sdyn[];
    u64* wdup = sdyn;                 // WDUP_U64
    u64* pbuf = sdyn + WDUP_U64;      // PBUF_U64

    int tid  = threadIdx.x;
    int w    = tid >> 5;
    int lane = tid & 31;
    bool act = (lane < 25);
    int b0   = (act ? lane : 24) * 4;
    int myc  = blockIdx.x * 8 + w;    // phase-2 column for this warp

    // one-time weight load + duplicate: wdup[k*24 + (c*3+g)] = pair(Whh[g][col c][k])
    for (int i = tid; i < WDUP_U64; i += 256) {
        int k = i / 24, j = i % 24, c = j / 3, g = j % 3;
        float v = Whh[((size_t)g * HD + blockIdx.x * 8 + c) * HD + k];
        wdup[i] = bcast2(v);
    }
    float br = bhh[myc], bz = bhh[HD + myc], bn = bhh[2 * HD + myc];
    __syncthreads();

    const u64* wk0 = wdup + (size_t)(w * 128) * 24;

    for (int t = 0; t < TT; t++) {
        u64 acc[48];                  // [j=c*3+g][pair]
#pragma unroll
        for (int i = 0; i < 48; i++) acc[i] = 0ull;

        if (t > 0) {
            const u64* wk = wk0;
            const float* hk = hst + (size_t)(t - 1) * NDB + (size_t)(w * 128) * NB + b0;
#pragma unroll 4
            for (int kk = 0; kk < 128; kk++) {
                ulonglong2 hq = *(const ulonglong2*)hk;
#pragma unroll
                for (int jj = 0; jj < 12; jj++) {
                    ulonglong2 w2 = *(const ulonglong2*)(wk + jj * 2);
                    fma2(acc[(jj * 2 + 0) * 2 + 0], w2.x, hq.x);
                    fma2(acc[(jj * 2 + 0) * 2 + 1], w2.x, hq.y);
                    fma2(acc[(jj * 2 + 1) * 2 + 0], w2.y, hq.x);
                    fma2(acc[(jj * 2 + 1) * 2 + 1], w2.y, hq.y);
                }
                wk += 24;
                hk += NB;
            }
        }

        // cross-warp reduction, one gate at a time (pbuf = 25.6 KB)
        float2 sg[3][2];
#pragma unroll
        for (int g = 0; g < 3; g++) {
            __syncthreads();
            if (act) {
#pragma unroll
                for (int c = 0; c < 8; c++) {
#pragma unroll
                    for (int p = 0; p < 2; p++)
                        pbuf[(((size_t)w * 8 + c) * 2 + p) * 25 + lane] = acc[(c * 3 + g) * 2 + p];
                }
            }
            __syncthreads();
            if (act) {
#pragma unroll
                for (int p = 0; p < 2; p++) {
                    float sx = 0.f, sy = 0.f;
#pragma unroll
                    for (int ww = 0; ww < 8; ww++) {
                        float2 v = unpk(pbuf[(((size_t)ww * 8 + w) * 2 + p) * 25 + lane]);
                        sx += v.x; sy += v.y;
                    }
                    sg[g][p] = make_float2(sx, sy);
                }
            }
        }

        // gate math + write h(t) for col myc, 4 batches
        if (act) {
            float4 hold = make_float4(0.f, 0.f, 0.f, 0.f);
            if (t > 0)
                hold = *(const float4*)(hst + (size_t)(t - 1) * NDB + (size_t)myc * NB + b0);
            size_t xb = (size_t)t * H3 * (size_t)NB;
            float4 xr = *(const float4*)(xpt + xb + (size_t)myc * NB + b0);
            float4 xz = *(const float4*)(xpt + xb + (size_t)(HD + myc) * NB + b0);
            float4 xn = *(const float4*)(xpt + xb + (size_t)(2 * HD + myc) * NB + b0);

            float arv[4] = { sg[0][0].x, sg[0][0].y, sg[0][1].x, sg[0][1].y };
            float azv[4] = { sg[1][0].x, sg[1][0].y, sg[1][1].x, sg[1][1].y };
            float anv[4] = { sg[2][0].x, sg[2][0].y, sg[2][1].x, sg[2][1].y };
            float hvv[4] = { hold.x, hold.y, hold.z, hold.w };
            float xrv[4] = { xr.x, xr.y, xr.z, xr.w };
            float xzv[4] = { xz.x, xz.y, xz.z, xz.w };
            float xnv[4] = { xn.x, xn.y, xn.z, xn.w };

            float ho[4];
#pragma unroll
            for (int q = 0; q < 4; q++) {
                float r = sigf(xrv[q] + arv[q] + br);
                float z = sigf(xzv[q] + azv[q] + bz);
                float n = tanhf(xnv[q] + r * (anv[q] + bn));
                ho[q] = (1.f - z) * n + z * hvv[q];
            }
            *(float4*)(hst + (size_t)t * NDB + (size_t)myc * NB + b0) =
                make_float4(ho[0], ho[1], ho[2], ho[3]);
        }

        gridbar();
    }
}

// =================================================================
// one-pass online-softmax reduce
// =================================================================
__global__ void att_reduce_flat(const float* __restrict__ S,
                                const float* __restrict__ H,
                                float* __restrict__ vt)
{
    int j = blockIdx.x * 256 + threadIdx.x;
    float mx = -1e30f, se = 0.f, sv = 0.f;
#pragma unroll 4
    for (int u = 0; u < TT; u++) {
        float s = S[(size_t)u * NDB + j];
        float h = H[(size_t)u * NDB + j];
        float m2 = fmaxf(mx, s);
        float cor = expf(mx - m2);
        float e = expf(s - m2);
        se = se * cor + e;
        sv = sv * cor + e * h;
        mx = m2;
    }
    vt[j] = sv / se;
}

// pool attention on vt[d][b] -> catv8[d*8 + c]
__global__ void pool_att_t(const float* __restrict__ vt, const float* __restrict__ pW,
                           const float* __restrict__ pb, float* __restrict__ catv8)
{
    int c = blockIdx.x;
    int d = blockIdx.y * 256 + threadIdx.x;
    if (c >= 5) { catv8[(size_t)d * 8 + c] = 0.f; return; }
    __shared__ float sW[400];
    __shared__ float sb[20];
    for (int i = threadIdx.x; i < 400; i += 256) sW[i] = pW[i];
    if (threadIdx.x < 20) sb[threadIdx.x] = pb[threadIdx.x];
    __syncthreads();

    float xv[20];
#pragma unroll
    for (int s = 0; s < 20; s++) xv[s] = vt[(size_t)d * NB + c * 20 + s];
    float wv[20]; float mx = -1e30f;
#pragma unroll
    for (int u = 0; u < 20; u++) {
        float s = sb[u];
#pragma unroll
        for (int t2 = 0; t2 < 20; t2++) s += xv[t2] * sW[u * 20 + t2];
        wv[u] = s; mx = fmaxf(mx, s);
    }
    float se = 0.f, sv = 0.f;
#pragma unroll
    for (int u = 0; u < 20; u++) {
        float e = expf(wv[u] - mx);
        se += e; sv += e * xv[u];
    }
    catv8[(size_t)d * 8 + c] = sv / se;
}

__global__ void dot2_t(const float* __restrict__ ht, const float* __restrict__ a1,
                       const float* __restrict__ a2, float* __restrict__ o1,
                       float* __restrict__ o2, int stride)
{
    int n = blockIdx.x;
    __shared__ float s1[256], s2[256];
    float p1 = 0.f, p2 = 0.f;
    for (int j = threadIdx.x; j < HD; j += 256) {
        float hv = ht[(size_t)j * stride + n];
        p1 += hv * a1[j]; p2 += hv * a2[j];
    }
    s1[threadIdx.x] = p1; s2[threadIdx.x] = p2;
    __syncthreads();
    for (int s = 128; s > 0; s >>= 1) {
        if (threadIdx.x < s) { s1[threadIdx.x] += s1[threadIdx.x + s]; s2[threadIdx.x] += s2[threadIdx.x + s]; }
        __syncthreads();
    }
    if (threadIdx.x == 0) { o1[n] = s1[0]; o2[n] = s2[0]; }
}

__global__ void gat_agg_t(const float* __restrict__ ht, const float* __restrict__ as,
                          const float* __restrict__ ad, const float* __restrict__ bias,
                          float* __restrict__ outt, int group, int stride, int ostride)
{
    int n = blockIdx.x;
    int base = (n / group) * group;
    __shared__ float alpha[32];
    if (threadIdx.x == 0) {
        float e[32]; float mx = -1e30f;
        for (int s = 0; s < group; s++) {
            float x = as[base + s] + ad[n];
            x = (x > 0.f) ? x : 0.2f * x;
            e[s] = x; mx = fmaxf(mx, x);
        }
        float se = 0.f;
        for (int s = 0; s < group; s++) { e[s] = expf(e[s] - mx); se += e[s]; }
        for (int s = 0; s < group; s++) alpha[s] = e[s] / se;
    }
    __syncthreads();
    for (int j = threadIdx.x; j < HD; j += 256) {
        float acc = 0.f;
        for (int s = 0; s < group; s++)
            acc += alpha[s] * ht[(size_t)j * stride + base + s];
        outt[(size_t)j * ostride + n] = acc + bias[j];
    }
}

__global__ void build_fusion_t(const float* __restrict__ vt, const float* __restrict__ catot,
                               const float* __restrict__ innert, float* __restrict__ fint)
{
    int idx = blockIdx.x * 256 + threadIdx.x;
    if (idx >= H3 * NB) return;
    int k = idx / NB, n = idx - k * NB;
    float val;
    if (k < HD)            val = vt[(size_t)k * NB + n];
    else if (k < 2 * HD)   val = catot[(size_t)(k - HD) * 5 + n / 20];
    else                   val = innert[(size_t)(k - 2 * HD) * NB + n];
    fint[idx] = val;
}

__global__ void heads_t(const float* __restrict__ ft, const float* __restrict__ rw,
                        const float* __restrict__ rb, const float* __restrict__ cw,
                        const float* __restrict__ cb, float* __restrict__ out)
{
    int n = blockIdx.x;
    __shared__ float s1[256], s2[256];
    float p1 = 0.f, p2 = 0.f;
    for (int j = threadIdx.x; j < HD; j += 256) {
        float fv = ft[(size_t)j * NB + n];
        p1 += fv * rw[j]; p2 += fv * cw[j];
    }
    s1[threadIdx.x] = p1; s2[threadIdx.x] = p2;
    __syncthreads();
    for (int s = 128; s > 0; s >>= 1) {
        if (threadIdx.x < s) { s1[threadIdx.x] += s1[threadIdx.x + s]; s2[threadIdx.x] += s2[threadIdx.x + s]; }
        __syncthreads();
    }
    if (threadIdx.x == 0) {
        out[n]      = s1[0] + rb[0];
        out[NB + n] = 1.f / (1.f + expf(-(s2[0] + cb[0])));
    }
}

// =================================================================
extern "C" void kernel_launch(void* const* d_in, const int* in_sizes, int n_in,
                              void* d_out, int out_size)
{
    const float* weekly  = (const float*)d_in[0];
    const float* Wih     = (const float*)d_in[1];
    const float* Whh     = (const float*)d_in[2];
    const float* bih     = (const float*)d_in[3];
    const float* bhh     = (const float*)d_in[4];
    const float* encW    = (const float*)d_in[5];
    const float* encB    = (const float*)d_in[6];
    const float* poolW   = (const float*)d_in[7];
    const float* poolB   = (const float*)d_in[8];
    const float* innerW  = (const float*)d_in[9];
    const float* innerAs = (const float*)d_in[10];
    const float* innerAd = (const float*)d_in[11];
    const float* innerB  = (const float*)d_in[12];
    const float* catW    = (const float*)d_in[13];
    const float* catAs   = (const float*)d_in[14];
    const float* catAd   = (const float*)d_in[15];
    const float* catB    = (const float*)d_in[16];
    const float* fusW    = (const float*)d_in[17];
    const float* fusB    = (const float*)d_in[18];
    const float* regW    = (const float*)d_in[19];
    const float* regB    = (const float*)d_in[20];
    const float* clsW    = (const float*)d_in[21];
    const float* clsB    = (const float*)d_in[22];
    float* out = (float*)d_out;

    float *xp, *xpt, *hst, *vt, *hpt, *innert, *catv8, *hp2t, *catot, *as_, *ad_, *as2, *ad2, *fint, *ftb;
    cudaGetSymbolAddress((void**)&xp,     g_xp);
    cudaGetSymbolAddress((void**)&xpt,    g_xpt);
    cudaGetSymbolAddress((void**)&hst,    g_hst);
    cudaGetSymbolAddress((void**)&vt,     g_vt);
    cudaGetSymbolAddress((void**)&hpt,    g_hpt);
    cudaGetSymbolAddress((void**)&innert, g_innert);
    cudaGetSymbolAddress((void**)&catv8,  g_catv8);
    cudaGetSymbolAddress((void**)&hp2t,   g_hp2t);
    cudaGetSymbolAddress((void**)&catot,  g_catot);
    cudaGetSymbolAddress((void**)&as_,    g_as);
    cudaGetSymbolAddress((void**)&ad_,    g_ad);
    cudaGetSymbolAddress((void**)&as2,    g_as2);
    cudaGetSymbolAddress((void**)&ad2,    g_ad2);
    cudaGetSymbolAddress((void**)&fint,   g_fint);
    cudaGetSymbolAddress((void**)&ftb,    g_ft);

    // 1) xp = weekly(51200,256) @ Wih^T + bih
    gemm_nt<<<dim3(H3 / 128, (NB * TT) / 128), 256>>>(weekly, Wih, bih, xp, NB * TT, H3, IND, 0);

    // 1b) transpose to xpt[t][g][b]
    transpose_xp<<<dim3(TT, H3 / 32), 256>>>(xp, xpt);

    // 2) persistent GRU v7 (k-split warps)
    int smem = (WDUP_U64 + PBUF_U64) * 8;   // 196608 + 25600 = 222208
    cudaFuncSetAttribute(gru_persist, cudaFuncAttributeMaxDynamicSharedMemorySize, smem);
    gru_persist<<<128, 256, smem>>>(xpt, Whh, bhh, hst);

    // 3) S(512 x 102400) = encW @ H + encB[u]  (reuse xp buffer)
    gemm_nn<<<dim3(NDB / 128, TT / 128), 256>>>(encW, hst, encB, xp, TT, NDB, TT, 0);

    // 4) vt[j] = softmax-over-u(S) . H
    att_reduce_flat<<<NDB / 256, 256>>>(xp, hst, vt);

    // 5) inner GAT
    gemm_nn<<<dim3(1, HD / 128), 256>>>(innerW, vt, nullptr, hpt, HD, NB, HD, 0);
    dot2_t<<<NB, 256>>>(hpt, innerAs, innerAd, as_, ad_, NB);
    gat_agg_t<<<NB, 256>>>(hpt, as_, ad_, innerB, innert, 20, NB, NB);

    // 6) pool
    pool_att_t<<<dim3(8, HD / 256), 256>>>(vt, poolW, poolB, catv8);

    // 7) category GAT
    gemm_nn<<<dim3(1, HD / 128), 256>>>(catW, catv8, nullptr, hp2t, HD, 8, HD, 0);
    dot2_t<<<5, 256>>>(hp2t, catAs, catAd, as2, ad2, 8);
    gat_agg_t<<<5, 256>>>(hp2t, as2, ad2, catB, catot, 5, 8, 5);

    // 8) fusion
    build_fusion_t<<<(H3 * NB + 255) / 256, 256>>>(vt, catot, innert, fint);
    gemm_nn<<<dim3(1, HD / 128), 256>>>(fusW, fint, fusB, ftb, HD, NB, H3, 1);

    // 9) heads
    heads_t<<<NB, 256>>>(ftb, regW, regB, clsW, clsB, out);
}

// round 9
// speedup vs baseline: 4.7734x; 1.1504x over previous
#include <cuda_runtime.h>
#include <math.h>
#include <stdint.h>
#include <stddef.h>

typedef unsigned long long u64;

#define NB   100
#define TT   512
#define IND  256
#define HD   1024
#define H3   3072
#define NDB  (HD * NB)          // 102400
#define HBT_STRIDE (128 * 1024) // padded per-t stride (128 batch rows x 1024)

// ---------------- scratch ----------------
__device__ float g_xp [(size_t)NB * TT * H3];     // xp [b][t][g]; later reused as S [u][j]
__device__ float g_hbt[(size_t)TT * HBT_STRIDE];  // h states [t][b(pad128)][k]
__device__ float g_v  [NB * HD];
__device__ float g_hp [NB * HD];
__device__ float g_inner[NB * HD];
__device__ float g_catv[5 * HD];
__device__ float g_hp2 [5 * HD];
__device__ float g_cat [5 * HD];
__device__ float g_as[NB];
__device__ float g_ad[NB];
__device__ float g_as2[8];
__device__ float g_ad2[8];
__device__ float g_fin[NB * H3];
__device__ float g_f  [NB * HD];
__device__ unsigned g_cnt;
__device__ unsigned g_gen;

// ---------------- f32x2 helpers (SIMT GEMMs) ----------------
__device__ __forceinline__ u64 bcast2(float x) {
    u64 r; unsigned u = __float_as_uint(x);
    asm("mov.b64 %0, {%1, %1};" : "=l"(r) : "r"(u));
    return r;
}
__device__ __forceinline__ void fma2(u64& d, u64 a, u64 b) {
    asm("fma.rn.f32x2 %0, %1, %2, %0;" : "+l"(d) : "l"(a), "l"(b));
}
__device__ __forceinline__ float2 unpk(u64 v) {
    unsigned lo, hi;
    asm("mov.b64 {%0, %1}, %2;" : "=r"(lo), "=r"(hi) : "l"(v));
    return make_float2(__uint_as_float(lo), __uint_as_float(hi));
}
__device__ __forceinline__ float sigf(float x) { return 1.f / (1.f + expf(-x)); }
__device__ __forceinline__ uint32_t f2tf32(float x) {
    uint32_t u;
    asm("cvt.rna.tf32.f32 %0, %1;" : "=r"(u) : "f"(x));
    return u;
}

// tf32 warp MMA: D(16x8) += A(16x8) * B(8x8)   [sm_80 baseline, compute_103-legal]
__device__ __forceinline__ void mma_tf32(
    float& c0, float& c1, float& c2, float& c3,
    uint32_t a0, uint32_t a1, uint32_t a2, uint32_t a3,
    uint32_t b0, uint32_t b1)
{
    asm volatile(
        "mma.sync.aligned.m16n8k8.row.col.f32.tf32.tf32.f32 "
        "{%0,%1,%2,%3}, {%4,%5,%6,%7}, {%8,%9}, {%0,%1,%2,%3};"
        : "+f"(c0), "+f"(c1), "+f"(c2), "+f"(c3)
        : "r"(a0), "r"(a1), "r"(a2), "r"(a3), "r"(b0), "r"(b1));
}

// =================================================================
// SGEMM NT: C[M,N] = A[M,K] @ B[N,K]^T + colbias[N] (+relu)
// =================================================================
__global__ __launch_bounds__(256) void gemm_nt(
    const float* __restrict__ A, const float* __restrict__ B,
    const float* __restrict__ colbias, float* __restrict__ C,
    int M, int N, int K, int act)
{
    __shared__ float As[16][128];
    __shared__ float Bs[16][128];
    int tid = threadIdx.x;
    int tx = tid & 15, ty = tid >> 4;
    int row0 = blockIdx.y * 128, col0 = blockIdx.x * 128;

    u64 acc[8][4];
#pragma unroll
    for (int i = 0; i < 8; i++)
#pragma unroll
        for (int j = 0; j < 4; j++) acc[i][j] = 0ull;

    int lr = tid >> 2, lc = tid & 3;
    for (int k0 = 0; k0 < K; k0 += 16) {
#pragma unroll
        for (int p = 0; p < 2; p++) {
            int r = lr + p * 64, gr = row0 + r;
            float4 v = make_float4(0.f, 0.f, 0.f, 0.f);
            if (gr < M) v = *(const float4*)(A + (size_t)gr * K + k0 + lc * 4);
            As[lc*4+0][r] = v.x; As[lc*4+1][r] = v.y; As[lc*4+2][r] = v.z; As[lc*4+3][r] = v.w;
        }
#pragma unroll
        for (int p = 0; p < 2; p++) {
            int r = lr + p * 64, gc = col0 + r;
            float4 v = make_float4(0.f, 0.f, 0.f, 0.f);
            if (gc < N) v = *(const float4*)(B + (size_t)gc * K + k0 + lc * 4);
            Bs[lc*4+0][r] = v.x; Bs[lc*4+1][r] = v.y; Bs[lc*4+2][r] = v.z; Bs[lc*4+3][r] = v.w;
        }
        __syncthreads();
#pragma unroll
        for (int kk = 0; kk < 16; kk++) {
            float a[8];
            *(float4*)&a[0] = *(const float4*)&As[kk][ty * 8];
            *(float4*)&a[4] = *(const float4*)&As[kk][ty * 8 + 4];
            u64 b4[4];
#pragma unroll
            for (int j = 0; j < 4; j++) b4[j] = *(const u64*)&Bs[kk][tx * 8 + 2 * j];
#pragma unroll
            for (int i = 0; i < 8; i++) {
                u64 ai = bcast2(a[i]);
#pragma unroll
                for (int j = 0; j < 4; j++) fma2(acc[i][j], ai, b4[j]);
            }
        }
        __syncthreads();
    }
#pragma unroll
    for (int i = 0; i < 8; i++) {
        int gm = row0 + ty * 8 + i;
        if (gm >= M) continue;
#pragma unroll
        for (int j = 0; j < 4; j++) {
            float2 c2 = unpk(acc[i][j]);
            int gn = col0 + tx * 8 + 2 * j;
            float v0 = c2.x, v1 = c2.y;
            if (colbias) { v0 += colbias[gn]; v1 += colbias[gn + 1]; }
            if (act == 1) { v0 = fmaxf(v0, 0.f); v1 = fmaxf(v1, 0.f); }
            if (gn < N)     C[(size_t)gm * N + gn]     = v0;
            if (gn + 1 < N) C[(size_t)gm * N + gn + 1] = v1;
        }
    }
}

// =================================================================
// SGEMM NN with B row stride: C[M,N] = A[M,K] @ B[K(ldB),N] + rowbias[M]
// M,N multiples of 128 used here; N%4==0.
// =================================================================
__global__ __launch_bounds__(256) void gemm_nn(
    const float* __restrict__ A, const float* __restrict__ B,
    const float* __restrict__ rowbias, float* __restrict__ C,
    int M, int N, int K, size_t ldB)
{
    __shared__ float As[16][128];
    __shared__ float Bs[16][128];
    int tid = threadIdx.x;
    int tx = tid & 15, ty = tid >> 4;
    int row0 = blockIdx.y * 128, col0 = blockIdx.x * 128;

    u64 acc[8][4];
#pragma unroll
    for (int i = 0; i < 8; i++)
#pragma unroll
        for (int j = 0; j < 4; j++) acc[i][j] = 0ull;

    int lr = tid >> 2, lc = tid & 3;
    int br = tid >> 5, bc = tid & 31;
    for (int k0 = 0; k0 < K; k0 += 16) {
#pragma unroll
        for (int p = 0; p < 2; p++) {
            int r = lr + p * 64, gr = row0 + r;
            float4 v = make_float4(0.f, 0.f, 0.f, 0.f);
            if (gr < M) v = *(const float4*)(A + (size_t)gr * K + k0 + lc * 4);
            As[lc*4+0][r] = v.x; As[lc*4+1][r] = v.y; As[lc*4+2][r] = v.z; As[lc*4+3][r] = v.w;
        }
#pragma unroll
        for (int p = 0; p < 2; p++) {
            int k = br + p * 8;
            float4 v = *(const float4*)(B + (size_t)(k0 + k) * ldB + col0 + bc * 4);
            *(float4*)&Bs[k][bc * 4] = v;
        }
        __syncthreads();
#pragma unroll
        for (int kk = 0; kk < 16; kk++) {
            float a[8];
            *(float4*)&a[0] = *(const float4*)&As[kk][ty * 8];
            *(float4*)&a[4] = *(const float4*)&As[kk][ty * 8 + 4];
            u64 b4[4];
#pragma unroll
            for (int j = 0; j < 4; j++) b4[j] = *(const u64*)&Bs[kk][tx * 8 + 2 * j];
#pragma unroll
            for (int i = 0; i < 8; i++) {
                u64 ai = bcast2(a[i]);
#pragma unroll
                for (int j = 0; j < 4; j++) fma2(acc[i][j], ai, b4[j]);
            }
        }
        __syncthreads();
    }
#pragma unroll
    for (int i = 0; i < 8; i++) {
        int gm = row0 + ty * 8 + i;
        if (gm >= M) continue;
        float rb = rowbias ? rowbias[gm] : 0.f;
#pragma unroll
        for (int j = 0; j < 4; j++) {
            float2 c2 = unpk(acc[i][j]);
            int gn = col0 + tx * 8 + 2 * j;
            C[(size_t)gm * N + gn]     = c2.x + rb;
            C[(size_t)gm * N + gn + 1] = c2.y + rb;
        }
    }
}

// =================================================================
// Persistent GRU v9: warp-level tf32 mma.sync.
// 128 blocks x 256 threads (8 warps). Block owns 8 hidden cols
// (24 gate rows). Warp w owns k-slice [128w, 128w+128); its Whh
// fragments (96 regs) stay register-resident for all 512 steps.
// Per step: D[112,24] partials via HMMA, cross-warp reduce in smem,
// fused gate epilogue, grid barrier.
// =================================================================
#define PBS 9   // partials stride (8 warps + 1 pad)

__device__ __forceinline__ void gridbar()
{
    __threadfence();
    __syncthreads();
    if (threadIdx.x == 0) {
        volatile unsigned* vg = &g_gen;
        unsigned target = *vg + 1;
        if (atomicAdd(&g_cnt, 1) == gridDim.x - 1) {
            g_cnt = 0;
            __threadfence();
            atomicAdd(&g_gen, 1);
        } else {
            while ((int)(*vg - target) < 0) { }
        }
        __threadfence();
    }
    __syncthreads();
}

__global__ __launch_bounds__(256, 1) void gru_mma(
    const float* __restrict__ xp, const float* __restrict__ Whh,
    const float* __restrict__ bhh, float* __restrict__ hbt)
{
    extern __shared__ float pbuf[];   // [112 rows][24 n][PBS]
    int tid  = threadIdx.x;
    int w    = tid >> 5;
    int lane = tid & 31;
    int gidq = lane >> 2;   // groupID 0..7
    int tig  = lane & 3;    // thread-in-group 0..3
    int col0 = blockIdx.x * 8;
    int k0   = w * 128;

    // ---- load Whh fragments (register-resident, once) ----
    // B tile (k8 x n8) col-major: b0=(k=tig, n=gidq), b1=(k=tig+4, n=gidq)
    uint32_t bf[16][3][2];
#pragma unroll
    for (int kt = 0; kt < 16; kt++) {
#pragma unroll
        for (int j = 0; j < 3; j++) {
            int n = j * 8 + gidq;
            int c = n / 3, g = n % 3;
            const float* wrow = Whh + ((size_t)g * HD + col0 + c) * HD;
            int kk = k0 + kt * 8 + tig;
            bf[kt][j][0] = f2tf32(wrow[kk]);
            bf[kt][j][1] = f2tf32(wrow[kk + 4]);
        }
    }

    for (int t = 0; t < TT; t++) {
        if (t > 0) {
            const float* hprev = hbt + (size_t)(t - 1) * HBT_STRIDE;
#pragma unroll 1
            for (int mt = 0; mt < 7; mt++) {
                float c0[3], c1[3], c2[3], c3[3];
#pragma unroll
                for (int j = 0; j < 3; j++) { c0[j] = 0.f; c1[j] = 0.f; c2[j] = 0.f; c3[j] = 0.f; }

                const float* ab = hprev + (size_t)(mt * 16 + gidq) * HD + k0 + tig;
#pragma unroll
                for (int kt = 0; kt < 16; kt++) {
                    const float* p = ab + kt * 8;
                    uint32_t a0 = __float_as_uint(p[0]);
                    uint32_t a1 = __float_as_uint(p[8 * HD]);
                    uint32_t a2 = __float_as_uint(p[4]);
                    uint32_t a3 = __float_as_uint(p[8 * HD + 4]);
#pragma unroll
                    for (int j = 0; j < 3; j++)
                        mma_tf32(c0[j], c1[j], c2[j], c3[j],
                                 a0, a1, a2, a3, bf[kt][j][0], bf[kt][j][1]);
                }
                // write partials: C row = groupID (+8), col n = tig*2 (+1)
                int r0 = mt * 16 + gidq;
#pragma unroll
                for (int j = 0; j < 3; j++) {
                    int n0 = j * 8 + tig * 2;
                    pbuf[((size_t)r0 * 24 + n0) * PBS + w]           = c0[j];
                    pbuf[((size_t)r0 * 24 + n0 + 1) * PBS + w]       = c1[j];
                    pbuf[((size_t)(r0 + 8) * 24 + n0) * PBS + w]     = c2[j];
                    pbuf[((size_t)(r0 + 8) * 24 + n0 + 1) * PBS + w] = c3[j];
                }
            }
        }
        __syncthreads();

        // fused reduction + gate epilogue: 800 (b, col) pairs
        for (int idx = tid; idx < NB * 8; idx += 256) {
            int b = idx >> 3, c = idx & 7;
            int col = col0 + c;
            float ar = 0.f, az = 0.f, an = 0.f;
            if (t > 0) {
                const float* pr = pbuf + ((size_t)b * 24 + c * 3) * PBS;
#pragma unroll
                for (int ww = 0; ww < 8; ww++) {
                    ar += pr[ww];
                    az += pr[PBS + ww];
                    an += pr[2 * PBS + ww];
                }
            }
            size_t xbase = ((size_t)b * TT + t) * H3;
            float xr = xp[xbase + col];
            float xz = xp[xbase + HD + col];
            float xn = xp[xbase + 2 * HD + col];
            float hold = (t > 0) ? hbt[(size_t)(t - 1) * HBT_STRIDE + (size_t)b * HD + col] : 0.f;
            float r = sigf(xr + ar + bhh[col]);
            float z = sigf(xz + az + bhh[HD + col]);
            float n = tanhf(xn + r * (an + bhh[2 * HD + col]));
            hbt[(size_t)t * HBT_STRIDE + (size_t)b * HD + col] = (1.f - z) * n + z * hold;
        }

        gridbar();
    }
}

// =================================================================
// one-pass online-softmax reduce: v[j] = sum_u softmax_u(S[u,j]) H[u,j]
// =================================================================
__global__ void att_reduce_flat(const float* __restrict__ S,
                                const float* __restrict__ H,
                                float* __restrict__ v)
{
    int j = blockIdx.x * 256 + threadIdx.x;
    float mx = -1e30f, se = 0.f, sv = 0.f;
#pragma unroll 4
    for (int u = 0; u < TT; u++) {
        float s = S[(size_t)u * NDB + j];
        float h = H[(size_t)u * HBT_STRIDE + j];
        float m2 = fmaxf(mx, s);
        float cor = expf(mx - m2);
        float e = expf(s - m2);
        se = se * cor + e;
        sv = sv * cor + e * h;
        mx = m2;
    }
    v[j] = sv / se;
}

// pool attention, row-major v -> catv[c][d]
__global__ void pool_att(const float* __restrict__ v, const float* __restrict__ pW,
                         const float* __restrict__ pb, float* __restrict__ catv)
{
    int c = blockIdx.x;
    int d = blockIdx.y * 256 + threadIdx.x;
    __shared__ float sW[400];
    __shared__ float sb[20];
    for (int i = threadIdx.x; i < 400; i += 256) sW[i] = pW[i];
    if (threadIdx.x < 20) sb[threadIdx.x] = pb[threadIdx.x];
    __syncthreads();

    float xv[20];
#pragma unroll
    for (int s = 0; s < 20; s++) xv[s] = v[(size_t)(c * 20 + s) * HD + d];
    float wv[20]; float mx = -1e30f;
#pragma unroll
    for (int u = 0; u < 20; u++) {
        float s = sb[u];
#pragma unroll
        for (int t2 = 0; t2 < 20; t2++) s += xv[t2] * sW[u * 20 + t2];
        wv[u] = s; mx = fmaxf(mx, s);
    }
    float se = 0.f, sv = 0.f;
#pragma unroll
    for (int u = 0; u < 20; u++) {
        float e = expf(wv[u] - mx);
        se += e; sv += e * xv[u];
    }
    catv[(size_t)c * HD + d] = sv / se;
}

// two dots per node (row-major)
__global__ void dot2(const float* __restrict__ h, const float* __restrict__ a1,
                     const float* __restrict__ a2, float* __restrict__ o1,
                     float* __restrict__ o2)
{
    int n = blockIdx.x;
    __shared__ float s1[256], s2[256];
    float p1 = 0.f, p2 = 0.f;
    for (int k = threadIdx.x; k < HD; k += 256) {
        float hv = h[(size_t)n * HD + k];
        p1 += hv * a1[k]; p2 += hv * a2[k];
    }
    s1[threadIdx.x] = p1; s2[threadIdx.x] = p2;
    __syncthreads();
    for (int s = 128; s > 0; s >>= 1) {
        if (threadIdx.x < s) { s1[threadIdx.x] += s1[threadIdx.x + s]; s2[threadIdx.x] += s2[threadIdx.x + s]; }
        __syncthreads();
    }
    if (threadIdx.x == 0) { o1[n] = s1[0]; o2[n] = s2[0]; }
}

// GAT aggregation (complete cliques + self loops), row-major
__global__ void gat_agg(const float* __restrict__ h, const float* __restrict__ as,
                        const float* __restrict__ ad, const float* __restrict__ bias,
                        float* __restrict__ out, int group)
{
    int n = blockIdx.x;
    int base = (n / group) * group;
    __shared__ float alpha[32];
    if (threadIdx.x == 0) {
        float e[32]; float mx = -1e30f;
        for (int s = 0; s < group; s++) {
            float x = as[base + s] + ad[n];
            x = (x > 0.f) ? x : 0.2f * x;
            e[s] = x; mx = fmaxf(mx, x);
        }
        float se = 0.f;
        for (int s = 0; s < group; s++) { e[s] = expf(e[s] - mx); se += e[s]; }
        for (int s = 0; s < group; s++) alpha[s] = e[s] / se;
    }
    __syncthreads();
    for (int dd = threadIdx.x; dd < HD; dd += 256) {
        float acc = 0.f;
        for (int s = 0; s < group; s++)
            acc += alpha[s] * h[(size_t)(base + s) * HD + dd];
        out[(size_t)n * HD + dd] = acc + bias[dd];
    }
}

// fusion concat (row-major)
__global__ void build_fusion(const float* __restrict__ v, const float* __restrict__ catv,
                             const float* __restrict__ inner, float* __restrict__ fin)
{
    int idx = blockIdx.x * 256 + threadIdx.x;
    if (idx >= NB * H3) return;
    int n = idx / H3, k = idx - n * H3;
    float val;
    if (k < HD)            val = v[(size_t)n * HD + k];
    else if (k < 2 * HD)   val = catv[(size_t)(n / 20) * HD + (k - HD)];
    else                   val = inner[(size_t)n * HD + (k - 2 * HD)];
    fin[idx] = val;
}

// heads (row-major)
__global__ void heads(const float* __restrict__ f, const float* __restrict__ rw,
                      const float* __restrict__ rb, const float* __restrict__ cw,
                      const float* __restrict__ cb, float* __restrict__ out)
{
    int n = blockIdx.x;
    __shared__ float s1[256], s2[256];
    float p1 = 0.f, p2 = 0.f;
    for (int k = threadIdx.x; k < HD; k += 256) {
        float fv = f[(size_t)n * HD + k];
        p1 += fv * rw[k]; p2 += fv * cw[k];
    }
    s1[threadIdx.x] = p1; s2[threadIdx.x] = p2;
    __syncthreads();
    for (int s = 128; s > 0; s >>= 1) {
        if (threadIdx.x < s) { s1[threadIdx.x] += s1[threadIdx.x + s]; s2[threadIdx.x] += s2[threadIdx.x + s]; }
        __syncthreads();
    }
    if (threadIdx.x == 0) {
        out[n]      = s1[0] + rb[0];
        out[NB + n] = 1.f / (1.f + expf(-(s2[0] + cb[0])));
    }
}

// =================================================================
extern "C" void kernel_launch(void* const* d_in, const int* in_sizes, int n_in,
                              void* d_out, int out_size)
{
    const float* weekly  = (const float*)d_in[0];
    const float* Wih     = (const float*)d_in[1];
    const float* Whh     = (const float*)d_in[2];
    const float* bih     = (const float*)d_in[3];
    const float* bhh     = (const float*)d_in[4];
    const float* encW    = (const float*)d_in[5];
    const float* encB    = (const float*)d_in[6];
    const float* poolW   = (const float*)d_in[7];
    const float* poolB   = (const float*)d_in[8];
    const float* innerW  = (const float*)d_in[9];
    const float* innerAs = (const float*)d_in[10];
    const float* innerAd = (const float*)d_in[11];
    const float* innerB  = (const float*)d_in[12];
    const float* catW    = (const float*)d_in[13];
    const float* catAs   = (const float*)d_in[14];
    const float* catAd   = (const float*)d_in[15];
    const float* catB    = (const float*)d_in[16];
    const float* fusW    = (const float*)d_in[17];
    const float* fusB    = (const float*)d_in[18];
    const float* regW    = (const float*)d_in[19];
    const float* regB    = (const float*)d_in[20];
    const float* clsW    = (const float*)d_in[21];
    const float* clsB    = (const float*)d_in[22];
    float* out = (float*)d_out;

    float *xp, *hbt, *v, *hp, *inner, *catv, *hp2, *catg, *as_, *ad_, *as2, *ad2, *fin, *f;
    cudaGetSymbolAddress((void**)&xp,    g_xp);
    cudaGetSymbolAddress((void**)&hbt,   g_hbt);
    cudaGetSymbolAddress((void**)&v,     g_v);
    cudaGetSymbolAddress((void**)&hp,    g_hp);
    cudaGetSymbolAddress((void**)&inner, g_inner);
    cudaGetSymbolAddress((void**)&catv,  g_catv);
    cudaGetSymbolAddress((void**)&hp2,   g_hp2);
    cudaGetSymbolAddress((void**)&catg,  g_cat);
    cudaGetSymbolAddress((void**)&as_,   g_as);
    cudaGetSymbolAddress((void**)&ad_,   g_ad);
    cudaGetSymbolAddress((void**)&as2,   g_as2);
    cudaGetSymbolAddress((void**)&ad2,   g_ad2);
    cudaGetSymbolAddress((void**)&fin,   g_fin);
    cudaGetSymbolAddress((void**)&f,     g_f);

    // 1) xp = weekly(51200,256) @ Wih^T + bih   [b][t][g]
    gemm_nt<<<dim3(H3 / 128, (NB * TT) / 128), 256>>>(weekly, Wih, bih, xp, NB * TT, H3, IND, 0);

    // 2) persistent tf32 mma GRU -> hbt [t][b][k] (b padded to 128)
    int smem = 112 * 24 * PBS * 4;   // 96768 B
    cudaFuncSetAttribute(gru_mma, cudaFuncAttributeMaxDynamicSharedMemorySize, smem);
    gru_mma<<<128, 256, smem>>>(xp, Whh, bhh, hbt);

    // 3) S(512 x 102400) = encW @ Hflat + encB[u]  (reuse xp; H row stride 131072)
    gemm_nn<<<dim3(NDB / 128, TT / 128), 256>>>(encW, hbt, encB, xp, TT, NDB, TT, (size_t)HBT_STRIDE);

    // 4) v[j] = softmax-over-u(S) . H   (v is [100][1024] row-major)
    att_reduce_flat<<<NDB / 256, 256>>>(xp, hbt, v);

    // 5) inner GAT: hp = v @ innerW^T
    gemm_nt<<<dim3(HD / 128, 1), 256>>>(v, innerW, nullptr, hp, NB, HD, HD, 0);
    dot2<<<NB, 256>>>(hp, innerAs, innerAd, as_, ad_);
    gat_agg<<<NB, 256>>>(hp, as_, ad_, innerB, inner, 20);

    // 6) pool 20 stocks -> category vectors
    pool_att<<<dim3(5, HD / 256), 256>>>(v, poolW, poolB, catv);

    // 7) category GAT
    gemm_nt<<<dim3(HD / 128, 1), 256>>>(catv, catW, nullptr, hp2, 5, HD, HD, 0);
    dot2<<<5, 256>>>(hp2, catAs, catAd, as2, ad2);
    gat_agg<<<5, 256>>>(hp2, as2, ad2, catB, catg, 5);

    // 8) fusion
    build_fusion<<<(NB * H3 + 255) / 256, 256>>>(v, catg, inner, fin);
    gemm_nt<<<dim3(HD / 128, 1), 256>>>(fin, fusW, fusB, f, NB, HD, H3, 1);

    // 9) heads
    heads<<<NB, 256>>>(f, regW, regB, clsW, clsB, out);
}

// round 10
// speedup vs baseline: 6.4558x; 1.3525x over previous
#include <cuda_runtime.h>
#include <math.h>
#include <stdint.h>
#include <stddef.h>

typedef unsigned long long u64;

#define NB   100
#define TT   512
#define IND  256
#define HD   1024
#define H3   3072
#define NDB  (HD * NB)          // 102400
#define HBT_STRIDE (128 * 1024) // padded per-t stride (128 batch rows x 1024)

// ---------------- scratch ----------------
__device__ float g_xp [(size_t)NB * TT * H3];     // xp [b][t][g]; later reused as S [u][j]
__device__ float g_hbt[(size_t)TT * HBT_STRIDE];  // h states [t][b(pad128)][k]
__device__ float g_v  [NB * HD];
__device__ float g_hp [NB * HD];
__device__ float g_inner[NB * HD];
__device__ float g_catv[5 * HD];
__device__ float g_hp2 [5 * HD];
__device__ float g_cat [5 * HD];
__device__ float g_as[NB];
__device__ float g_ad[NB];
__device__ float g_as2[8];
__device__ float g_ad2[8];
__device__ float g_fin[NB * H3];
__device__ float g_f  [NB * HD];
__device__ unsigned g_cnt;
__device__ unsigned g_gen;

// ---------------- f32x2 helpers (SIMT GEMMs) ----------------
__device__ __forceinline__ u64 bcast2(float x) {
    u64 r; unsigned u = __float_as_uint(x);
    asm("mov.b64 %0, {%1, %1};" : "=l"(r) : "r"(u));
    return r;
}
__device__ __forceinline__ void fma2(u64& d, u64 a, u64 b) {
    asm("fma.rn.f32x2 %0, %1, %2, %0;" : "+l"(d) : "l"(a), "l"(b));
}
__device__ __forceinline__ float2 unpk(u64 v) {
    unsigned lo, hi;
    asm("mov.b64 {%0, %1}, %2;" : "=r"(lo), "=r"(hi) : "l"(v));
    return make_float2(__uint_as_float(lo), __uint_as_float(hi));
}
__device__ __forceinline__ float sigf(float x) { return 1.f / (1.f + expf(-x)); }
__device__ __forceinline__ uint32_t f2tf32(float x) {
    uint32_t u;
    asm("cvt.rna.tf32.f32 %0, %1;" : "=r"(u) : "f"(x));
    return u;
}

// tf32 warp MMA: D(16x8) += A(16x8) * B(8x8)
__device__ __forceinline__ void mma_tf32(
    float& c0, float& c1, float& c2, float& c3,
    uint32_t a0, uint32_t a1, uint32_t a2, uint32_t a3,
    uint32_t b0, uint32_t b1)
{
    asm volatile(
        "mma.sync.aligned.m16n8k8.row.col.f32.tf32.tf32.f32 "
        "{%0,%1,%2,%3}, {%4,%5,%6,%7}, {%8,%9}, {%0,%1,%2,%3};"
        : "+f"(c0), "+f"(c1), "+f"(c2), "+f"(c3)
        : "r"(a0), "r"(a1), "r"(a2), "r"(a3), "r"(b0), "r"(b1));
}

// =================================================================
// SGEMM NT: C[M,N] = A[M,K] @ B[N,K]^T + colbias[N] (+relu)
// =================================================================
__global__ __launch_bounds__(256) void gemm_nt(
    const float* __restrict__ A, const float* __restrict__ B,
    const float* __restrict__ colbias, float* __restrict__ C,
    int M, int N, int K, int act)
{
    __shared__ float As[16][128];
    __shared__ float Bs[16][128];
    int tid = threadIdx.x;
    int tx = tid & 15, ty = tid >> 4;
    int row0 = blockIdx.y * 128, col0 = blockIdx.x * 128;

    u64 acc[8][4];
#pragma unroll
    for (int i = 0; i < 8; i++)
#pragma unroll
        for (int j = 0; j < 4; j++) acc[i][j] = 0ull;

    int lr = tid >> 2, lc = tid & 3;
    for (int k0 = 0; k0 < K; k0 += 16) {
#pragma unroll
        for (int p = 0; p < 2; p++) {
            int r = lr + p * 64, gr = row0 + r;
            float4 v = make_float4(0.f, 0.f, 0.f, 0.f);
            if (gr < M) v = *(const float4*)(A + (size_t)gr * K + k0 + lc * 4);
            As[lc*4+0][r] = v.x; As[lc*4+1][r] = v.y; As[lc*4+2][r] = v.z; As[lc*4+3][r] = v.w;
        }
#pragma unroll
        for (int p = 0; p < 2; p++) {
            int r = lr + p * 64, gc = col0 + r;
            float4 v = make_float4(0.f, 0.f, 0.f, 0.f);
            if (gc < N) v = *(const float4*)(B + (size_t)gc * K + k0 + lc * 4);
            Bs[lc*4+0][r] = v.x; Bs[lc*4+1][r] = v.y; Bs[lc*4+2][r] = v.z; Bs[lc*4+3][r] = v.w;
        }
        __syncthreads();
#pragma unroll
        for (int kk = 0; kk < 16; kk++) {
            float a[8];
            *(float4*)&a[0] = *(const float4*)&As[kk][ty * 8];
            *(float4*)&a[4] = *(const float4*)&As[kk][ty * 8 + 4];
            u64 b4[4];
#pragma unroll
            for (int j = 0; j < 4; j++) b4[j] = *(const u64*)&Bs[kk][tx * 8 + 2 * j];
#pragma unroll
            for (int i = 0; i < 8; i++) {
                u64 ai = bcast2(a[i]);
#pragma unroll
                for (int j = 0; j < 4; j++) fma2(acc[i][j], ai, b4[j]);
            }
        }
        __syncthreads();
    }
#pragma unroll
    for (int i = 0; i < 8; i++) {
        int gm = row0 + ty * 8 + i;
        if (gm >= M) continue;
#pragma unroll
        for (int j = 0; j < 4; j++) {
            float2 c2 = unpk(acc[i][j]);
            int gn = col0 + tx * 8 + 2 * j;
            float v0 = c2.x, v1 = c2.y;
            if (colbias) { v0 += colbias[gn]; v1 += colbias[gn + 1]; }
            if (act == 1) { v0 = fmaxf(v0, 0.f); v1 = fmaxf(v1, 0.f); }
            if (gn < N)     C[(size_t)gm * N + gn]     = v0;
            if (gn + 1 < N) C[(size_t)gm * N + gn + 1] = v1;
        }
    }
}

// =================================================================
// SGEMM NN with B row stride: C[M,N] = A[M,K] @ B[K(ldB),N] + rowbias[M]
// =================================================================
__global__ __launch_bounds__(256) void gemm_nn(
    const float* __restrict__ A, const float* __restrict__ B,
    const float* __restrict__ rowbias, float* __restrict__ C,
    int M, int N, int K, size_t ldB)
{
    __shared__ float As[16][128];
    __shared__ float Bs[16][128];
    int tid = threadIdx.x;
    int tx = tid & 15, ty = tid >> 4;
    int row0 = blockIdx.y * 128, col0 = blockIdx.x * 128;

    u64 acc[8][4];
#pragma unroll
    for (int i = 0; i < 8; i++)
#pragma unroll
        for (int j = 0; j < 4; j++) acc[i][j] = 0ull;

    int lr = tid >> 2, lc = tid & 3;
    int br = tid >> 5, bc = tid & 31;
    for (int k0 = 0; k0 < K; k0 += 16) {
#pragma unroll
        for (int p = 0; p < 2; p++) {
            int r = lr + p * 64, gr = row0 + r;
            float4 v = make_float4(0.f, 0.f, 0.f, 0.f);
            if (gr < M) v = *(const float4*)(A + (size_t)gr * K + k0 + lc * 4);
            As[lc*4+0][r] = v.x; As[lc*4+1][r] = v.y; As[lc*4+2][r] = v.z; As[lc*4+3][r] = v.w;
        }
#pragma unroll
        for (int p = 0; p < 2; p++) {
            int k = br + p * 8;
            float4 v = *(const float4*)(B + (size_t)(k0 + k) * ldB + col0 + bc * 4);
            *(float4*)&Bs[k][bc * 4] = v;
        }
        __syncthreads();
#pragma unroll
        for (int kk = 0; kk < 16; kk++) {
            float a[8];
            *(float4*)&a[0] = *(const float4*)&As[kk][ty * 8];
            *(float4*)&a[4] = *(const float4*)&As[kk][ty * 8 + 4];
            u64 b4[4];
#pragma unroll
            for (int j = 0; j < 4; j++) b4[j] = *(const u64*)&Bs[kk][tx * 8 + 2 * j];
#pragma unroll
            for (int i = 0; i < 8; i++) {
                u64 ai = bcast2(a[i]);
#pragma unroll
                for (int j = 0; j < 4; j++) fma2(acc[i][j], ai, b4[j]);
            }
        }
        __syncthreads();
    }
#pragma unroll
    for (int i = 0; i < 8; i++) {
        int gm = row0 + ty * 8 + i;
        if (gm >= M) continue;
        float rb = rowbias ? rowbias[gm] : 0.f;
#pragma unroll
        for (int j = 0; j < 4; j++) {
            float2 c2 = unpk(acc[i][j]);
            int gn = col0 + tx * 8 + 2 * j;
            C[(size_t)gm * N + gn]     = c2.x + rb;
            C[(size_t)gm * N + gn + 1] = c2.y + rb;
        }
    }
}

// =================================================================
// Persistent GRU v10: tf32 mma.sync + padded-smem fragment staging.
// 128 blocks x 256 threads (8 warps). Block owns 8 hidden cols.
// Warp w owns k-slice [128w,128w+128); Whh fragments register-resident.
// Per mt: stage 16x128 h-chunk into private smem (row stride 132 ->
// conflict-free fragment LDS), mma, write partials; reduce + epilogue.
// =================================================================
#define PBS 9                         // partials stride (8 warps + 1 pad)
#define ASTRIDE 132                   // padded row stride (floats)
#define PBUF_F (112 * 24 * PBS)       // 24192 floats
#define ABUF_F (16 * ASTRIDE)         // per-warp floats (2112)
#define GRU_SMEM ((PBUF_F + 8 * ABUF_F) * 4)   // 96768 + 67584 = 164352 B

__device__ __forceinline__ void gridbar()
{
    __threadfence();
    __syncthreads();
    if (threadIdx.x == 0) {
        volatile unsigned* vg = &g_gen;
        unsigned target = *vg + 1;
        if (atomicAdd(&g_cnt, 1) == gridDim.x - 1) {
            g_cnt = 0;
            __threadfence();
            atomicAdd(&g_gen, 1);
        } else {
            while ((int)(*vg - target) < 0) { }
        }
        __threadfence();
    }
    __syncthreads();
}

__global__ __launch_bounds__(256, 1) void gru_mma(
    const float* __restrict__ xp, const float* __restrict__ Whh,
    const float* __restrict__ bhh, float* __restrict__ hbt)
{
    extern __shared__ float smf[];
    float* pbuf = smf;                          // [112][24][PBS]
    int tid  = threadIdx.x;
    int w    = tid >> 5;
    int lane = tid & 31;
    float* abuf = smf + PBUF_F + w * ABUF_F;    // per-warp staging
    int gidq = lane >> 2;   // groupID 0..7
    int tig  = lane & 3;    // thread-in-group 0..3
    int col0 = blockIdx.x * 8;
    int k0   = w * 128;

    // ---- load Whh fragments (register-resident, once) ----
    uint32_t bf[16][3][2];
#pragma unroll
    for (int kt = 0; kt < 16; kt++) {
#pragma unroll
        for (int j = 0; j < 3; j++) {
            int n = j * 8 + gidq;
            int c = n / 3, g = n % 3;
            const float* wrow = Whh + ((size_t)g * HD + col0 + c) * HD;
            int kk = k0 + kt * 8 + tig;
            bf[kt][j][0] = f2tf32(wrow[kk]);
            bf[kt][j][1] = f2tf32(wrow[kk + 4]);
        }
    }

    // staging index: f4 = lane + j*32 -> row = f4>>5, c4 = f4&31
    for (int t = 0; t < TT; t++) {
        if (t > 0) {
            const float* hprev = hbt + (size_t)(t - 1) * HBT_STRIDE;
#pragma unroll 1
            for (int mt = 0; mt < 7; mt++) {
                // stage warp's A chunk: rows [mt*16, mt*16+16) x k [k0, k0+128)
                const float* src = hprev + (size_t)(mt * 16) * HD + k0;
#pragma unroll
                for (int j = 0; j < 16; j++) {
                    int f4 = lane + j * 32;
                    int row = f4 >> 5, c4 = f4 & 31;
                    float4 v = *(const float4*)(src + (size_t)row * HD + c4 * 4);
                    *(float4*)(abuf + row * ASTRIDE + c4 * 4) = v;
                }
                __syncwarp();

                float c0[3], c1[3], c2[3], c3[3];
#pragma unroll
                for (int j = 0; j < 3; j++) { c0[j] = 0.f; c1[j] = 0.f; c2[j] = 0.f; c3[j] = 0.f; }

                const float* fb = abuf + gidq * ASTRIDE + tig;
#pragma unroll
                for (int kt = 0; kt < 16; kt++) {
                    const float* p = fb + kt * 8;
                    uint32_t a0 = __float_as_uint(p[0]);
                    uint32_t a1 = __float_as_uint(p[8 * ASTRIDE]);
                    uint32_t a2 = __float_as_uint(p[4]);
                    uint32_t a3 = __float_as_uint(p[8 * ASTRIDE + 4]);
#pragma unroll
                    for (int j = 0; j < 3; j++)
                        mma_tf32(c0[j], c1[j], c2[j], c3[j],
                                 a0, a1, a2, a3, bf[kt][j][0], bf[kt][j][1]);
                }
                __syncwarp();   // all lanes done reading before next overwrite

                int r0 = mt * 16 + gidq;
#pragma unroll
                for (int j = 0; j < 3; j++) {
                    int n0 = j * 8 + tig * 2;
                    pbuf[((size_t)r0 * 24 + n0) * PBS + w]           = c0[j];
                    pbuf[((size_t)r0 * 24 + n0 + 1) * PBS + w]       = c1[j];
                    pbuf[((size_t)(r0 + 8) * 24 + n0) * PBS + w]     = c2[j];
                    pbuf[((size_t)(r0 + 8) * 24 + n0 + 1) * PBS + w] = c3[j];
                }
            }
        }
        __syncthreads();

        // fused reduction + gate epilogue: 800 (b, col) pairs
        for (int idx = tid; idx < NB * 8; idx += 256) {
            int b = idx >> 3, c = idx & 7;
            int col = col0 + c;
            float ar = 0.f, az = 0.f, an = 0.f;
            if (t > 0) {
                const float* pr = pbuf + ((size_t)b * 24 + c * 3) * PBS;
#pragma unroll
                for (int ww = 0; ww < 8; ww++) {
                    ar += pr[ww];
                    az += pr[PBS + ww];
                    an += pr[2 * PBS + ww];
                }
            }
            size_t xbase = ((size_t)b * TT + t) * H3;
            float xr = xp[xbase + col];
            float xz = xp[xbase + HD + col];
            float xn = xp[xbase + 2 * HD + col];
            float hold = (t > 0) ? hbt[(size_t)(t - 1) * HBT_STRIDE + (size_t)b * HD + col] : 0.f;
            float r = sigf(xr + ar + bhh[col]);
            float z = sigf(xz + az + bhh[HD + col]);
            float n = tanhf(xn + r * (an + bhh[2 * HD + col]));
            hbt[(size_t)t * HBT_STRIDE + (size_t)b * HD + col] = (1.f - z) * n + z * hold;
        }

        gridbar();
    }
}

// =================================================================
// one-pass online-softmax reduce: v[j] = sum_u softmax_u(S[u,j]) H[u,j]
// =================================================================
__global__ void att_reduce_flat(const float* __restrict__ S,
                                const float* __restrict__ H,
                                float* __restrict__ v)
{
    int j = blockIdx.x * 256 + threadIdx.x;
    float mx = -1e30f, se = 0.f, sv = 0.f;
#pragma unroll 4
    for (int u = 0; u < TT; u++) {
        float s = S[(size_t)u * NDB + j];
        float h = H[(size_t)u * HBT_STRIDE + j];
        float m2 = fmaxf(mx, s);
        float cor = expf(mx - m2);
        float e = expf(s - m2);
        se = se * cor + e;
        sv = sv * cor + e * h;
        mx = m2;
    }
    v[j] = sv / se;
}

// pool attention, row-major v -> catv[c][d]
__global__ void pool_att(const float* __restrict__ v, const float* __restrict__ pW,
                         const float* __restrict__ pb, float* __restrict__ catv)
{
    int c = blockIdx.x;
    int d = blockIdx.y * 256 + threadIdx.x;
    __shared__ float sW[400];
    __shared__ float sb[20];
    for (int i = threadIdx.x; i < 400; i += 256) sW[i] = pW[i];
    if (threadIdx.x < 20) sb[threadIdx.x] = pb[threadIdx.x];
    __syncthreads();

    float xv[20];
#pragma unroll
    for (int s = 0; s < 20; s++) xv[s] = v[(size_t)(c * 20 + s) * HD + d];
    float wv[20]; float mx = -1e30f;
#pragma unroll
    for (int u = 0; u < 20; u++) {
        float s = sb[u];
#pragma unroll
        for (int t2 = 0; t2 < 20; t2++) s += xv[t2] * sW[u * 20 + t2];
        wv[u] = s; mx = fmaxf(mx, s);
    }
    float se = 0.f, sv = 0.f;
#pragma unroll
    for (int u = 0; u < 20; u++) {
        float e = expf(wv[u] - mx);
        se += e; sv += e * xv[u];
    }
    catv[(size_t)c * HD + d] = sv / se;
}

// two dots per node (row-major)
__global__ void dot2(const float* __restrict__ h, const float* __restrict__ a1,
                     const float* __restrict__ a2, float* __restrict__ o1,
                     float* __restrict__ o2)
{
    int n = blockIdx.x;
    __shared__ float s1[256], s2[256];
    float p1 = 0.f, p2 = 0.f;
    for (int k = threadIdx.x; k < HD; k += 256) {
        float hv = h[(size_t)n * HD + k];
        p1 += hv * a1[k]; p2 += hv * a2[k];
    }
    s1[threadIdx.x] = p1; s2[threadIdx.x] = p2;
    __syncthreads();
    for (int s = 128; s > 0; s >>= 1) {
        if (threadIdx.x < s) { s1[threadIdx.x] += s1[threadIdx.x + s]; s2[threadIdx.x] += s2[threadIdx.x + s]; }
        __syncthreads();
    }
    if (threadIdx.x == 0) { o1[n] = s1[0]; o2[n] = s2[0]; }
}

// GAT aggregation (complete cliques + self loops), row-major
__global__ void gat_agg(const float* __restrict__ h, const float* __restrict__ as,
                        const float* __restrict__ ad, const float* __restrict__ bias,
                        float* __restrict__ out, int group)
{
    int n = blockIdx.x;
    int base = (n / group) * group;
    __shared__ float alpha[32];
    if (threadIdx.x == 0) {
        float e[32]; float mx = -1e30f;
        for (int s = 0; s < group; s++) {
            float x = as[base + s] + ad[n];
            x = (x > 0.f) ? x : 0.2f * x;
            e[s] = x; mx = fmaxf(mx, x);
        }
        float se = 0.f;
        for (int s = 0; s < group; s++) { e[s] = expf(e[s] - mx); se += e[s]; }
        for (int s = 0; s < group; s++) alpha[s] = e[s] / se;
    }
    __syncthreads();
    for (int dd = threadIdx.x; dd < HD; dd += 256) {
        float acc = 0.f;
        for (int s = 0; s < group; s++)
            acc += alpha[s] * h[(size_t)(base + s) * HD + dd];
        out[(size_t)n * HD + dd] = acc + bias[dd];
    }
}

// fusion concat (row-major)
__global__ void build_fusion(const float* __restrict__ v, const float* __restrict__ catv,
                             const float* __restrict__ inner, float* __restrict__ fin)
{
    int idx = blockIdx.x * 256 + threadIdx.x;
    if (idx >= NB * H3) return;
    int n = idx / H3, k = idx - n * H3;
    float val;
    if (k < HD)            val = v[(size_t)n * HD + k];
    else if (k < 2 * HD)   val = catv[(size_t)(n / 20) * HD + (k - HD)];
    else                   val = inner[(size_t)n * HD + (k - 2 * HD)];
    fin[idx] = val;
}

// heads (row-major)
__global__ void heads(const float* __restrict__ f, const float* __restrict__ rw,
                      const float* __restrict__ rb, const float* __restrict__ cw,
                      const float* __restrict__ cb, float* __restrict__ out)
{
    int n = blockIdx.x;
    __shared__ float s1[256], s2[256];
    float p1 = 0.f, p2 = 0.f;
    for (int k = threadIdx.x; k < HD; k += 256) {
        float fv = f[(size_t)n * HD + k];
        p1 += fv * rw[k]; p2 += fv * cw[k];
    }
    s1[threadIdx.x] = p1; s2[threadIdx.x] = p2;
    __syncthreads();
    for (int s = 128; s > 0; s >>= 1) {
        if (threadIdx.x < s) { s1[threadIdx.x] += s1[threadIdx.x + s]; s2[threadIdx.x] += s2[threadIdx.x + s]; }
        __syncthreads();
    }
    if (threadIdx.x == 0) {
        out[n]      = s1[0] + rb[0];
        out[NB + n] = 1.f / (1.f + expf(-(s2[0] + cb[0])));
    }
}

// =================================================================
extern "C" void kernel_launch(void* const* d_in, const int* in_sizes, int n_in,
                              void* d_out, int out_size)
{
    const float* weekly  = (const float*)d_in[0];
    const float* Wih     = (const float*)d_in[1];
    const float* Whh     = (const float*)d_in[2];
    const float* bih     = (const float*)d_in[3];
    const float* bhh     = (const float*)d_in[4];
    const float* encW    = (const float*)d_in[5];
    const float* encB    = (const float*)d_in[6];
    const float* poolW   = (const float*)d_in[7];
    const float* poolB   = (const float*)d_in[8];
    const float* innerW  = (const float*)d_in[9];
    const float* innerAs = (const float*)d_in[10];
    const float* innerAd = (const float*)d_in[11];
    const float* innerB  = (const float*)d_in[12];
    const float* catW    = (const float*)d_in[13];
    const float* catAs   = (const float*)d_in[14];
    const float* catAd   = (const float*)d_in[15];
    const float* catB    = (const float*)d_in[16];
    const float* fusW    = (const float*)d_in[17];
    const float* fusB    = (const float*)d_in[18];
    const float* regW    = (const float*)d_in[19];
    const float* regB    = (const float*)d_in[20];
    const float* clsW    = (const float*)d_in[21];
    const float* clsB    = (const float*)d_in[22];
    float* out = (float*)d_out;

    float *xp, *hbt, *v, *hp, *inner, *catv, *hp2, *catg, *as_, *ad_, *as2, *ad2, *fin, *f;
    cudaGetSymbolAddress((void**)&xp,    g_xp);
    cudaGetSymbolAddress((void**)&hbt,   g_hbt);
    cudaGetSymbolAddress((void**)&v,     g_v);
    cudaGetSymbolAddress((void**)&hp,    g_hp);
    cudaGetSymbolAddress((void**)&inner, g_inner);
    cudaGetSymbolAddress((void**)&catv,  g_catv);
    cudaGetSymbolAddress((void**)&hp2,   g_hp2);
    cudaGetSymbolAddress((void**)&catg,  g_cat);
    cudaGetSymbolAddress((void**)&as_,   g_as);
    cudaGetSymbolAddress((void**)&ad_,   g_ad);
    cudaGetSymbolAddress((void**)&as2,   g_as2);
    cudaGetSymbolAddress((void**)&ad2,   g_ad2);
    cudaGetSymbolAddress((void**)&fin,   g_fin);
    cudaGetSymbolAddress((void**)&f,     g_f);

    // 1) xp = weekly(51200,256) @ Wih^T + bih   [b][t][g]
    gemm_nt<<<dim3(H3 / 128, (NB * TT) / 128), 256>>>(weekly, Wih, bih, xp, NB * TT, H3, IND, 0);

    // 2) persistent tf32 mma GRU -> hbt [t][b][k] (b padded to 128)
    cudaFuncSetAttribute(gru_mma, cudaFuncAttributeMaxDynamicSharedMemorySize, GRU_SMEM);
    gru_mma<<<128, 256, GRU_SMEM>>>(xp, Whh, bhh, hbt);

    // 3) S(512 x 102400) = encW @ Hflat + encB[u]  (reuse xp; H row stride 131072)
    gemm_nn<<<dim3(NDB / 128, TT / 128), 256>>>(encW, hbt, encB, xp, TT, NDB, TT, (size_t)HBT_STRIDE);

    // 4) v[j] = softmax-over-u(S) . H   (v is [100][1024] row-major)
    att_reduce_flat<<<NDB / 256, 256>>>(xp, hbt, v);

    // 5) inner GAT: hp = v @ innerW^T
    gemm_nt<<<dim3(HD / 128, 1), 256>>>(v, innerW, nullptr, hp, NB, HD, HD, 0);
    dot2<<<NB, 256>>>(hp, innerAs, innerAd, as_, ad_);
    gat_agg<<<NB, 256>>>(hp, as_, ad_, innerB, inner, 20);

    // 6) pool 20 stocks -> category vectors
    pool_att<<<dim3(5, HD / 256), 256>>>(v, poolW, poolB, catv);

    // 7) category GAT
    gemm_nt<<<dim3(HD / 128, 1), 256>>>(catv, catW, nullptr, hp2, 5, HD, HD, 0);
    dot2<<<5, 256>>>(hp2, catAs, catAd, as2, ad2);
    gat_agg<<<5, 256>>>(hp2, as2, ad2, catB, catg, 5);

    // 8) fusion
    build_fusion<<<(NB * H3 + 255) / 256, 256>>>(v, catg, inner, fin);
    gemm_nt<<<dim3(HD / 128, 1), 256>>>(fin, fusW, fusB, f, NB, HD, H3, 1);

    // 9) heads
    heads<<<NB, 256>>>(f, regW, regB, clsW, clsB, out);
}

// round 11
// speedup vs baseline: 7.9413x; 1.2301x over previous
#include <cuda_runtime.h>
#include <math.h>
#include <stdint.h>
#include <stddef.h>

typedef unsigned long long u64;

#define NB   100
#define TT   512
#define IND  256
#define HD   1024
#define H3   3072
#define NDB  (HD * NB)          // 102400
#define HBT_STRIDE (128 * 1024) // padded per-t stride (128 batch rows x 1024)

// ---------------- scratch ----------------
__device__ float g_xp [(size_t)NB * TT * H3];     // xp [b][t][g]; later reused as S [u][j]
__device__ float g_hbt[(size_t)TT * HBT_STRIDE];  // h states [t][b(pad128)][k]
__device__ float g_v  [NB * HD];
__device__ float g_hp [NB * HD];
__device__ float g_inner[NB * HD];
__device__ float g_catv[5 * HD];
__device__ float g_hp2 [5 * HD];
__device__ float g_cat [5 * HD];
__device__ float g_as[NB];
__device__ float g_ad[NB];
__device__ float g_as2[8];
__device__ float g_ad2[8];
__device__ float g_fin[NB * H3];
__device__ float g_f  [NB * HD];
__device__ unsigned g_cnt;
__device__ unsigned g_gen;

// ---------------- f32x2 helpers (SIMT small GEMMs) ----------------
__device__ __forceinline__ u64 bcast2(float x) {
    u64 r; unsigned u = __float_as_uint(x);
    asm("mov.b64 %0, {%1, %1};" : "=l"(r) : "r"(u));
    return r;
}
__device__ __forceinline__ void fma2(u64& d, u64 a, u64 b) {
    asm("fma.rn.f32x2 %0, %1, %2, %0;" : "+l"(d) : "l"(a), "l"(b));
}
__device__ __forceinline__ float2 unpk(u64 v) {
    unsigned lo, hi;
    asm("mov.b64 {%0, %1}, %2;" : "=r"(lo), "=r"(hi) : "l"(v));
    return make_float2(__uint_as_float(lo), __uint_as_float(hi));
}
__device__ __forceinline__ float sigf(float x) { return 1.f / (1.f + expf(-x)); }
__device__ __forceinline__ uint32_t f2tf32(float x) {
    uint32_t u;
    asm("cvt.rna.tf32.f32 %0, %1;" : "=r"(u) : "f"(x));
    return u;
}

// tf32 warp MMA: D(16x8) += A(16x8) * B(8x8)
__device__ __forceinline__ void mma_tf32(
    float& c0, float& c1, float& c2, float& c3,
    uint32_t a0, uint32_t a1, uint32_t a2, uint32_t a3,
    uint32_t b0, uint32_t b1)
{
    asm volatile(
        "mma.sync.aligned.m16n8k8.row.col.f32.tf32.tf32.f32 "
        "{%0,%1,%2,%3}, {%4,%5,%6,%7}, {%8,%9}, {%0,%1,%2,%3};"
        : "+f"(c0), "+f"(c1), "+f"(c2), "+f"(c3)
        : "r"(a0), "r"(a1), "r"(a2), "r"(a3), "r"(b0), "r"(b1));
}

// =================================================================
// tf32 tensor-core GEMM NT: C[M,N] = A[M,K] @ B[N,K]^T + colbias (+relu)
// M,N multiples of 128; K multiple of 32. 256 thr, warp tile 64x32.
// =================================================================
#define AST 36
__global__ __launch_bounds__(256) void gemm_nt_tc(
    const float* __restrict__ A, const float* __restrict__ B,
    const float* __restrict__ colbias, float* __restrict__ C,
    int M, int N, int K, int act)
{
    __shared__ uint32_t As[128 * AST];
    __shared__ uint32_t Bs[128 * AST];
    int tid = threadIdx.x, w = tid >> 5, lane = tid & 31;
    int gid = lane >> 2, tig = lane & 3;
    int wm = w >> 2, wn = w & 3;
    int row0 = blockIdx.y * 128, col0 = blockIdx.x * 128;

    float acc[4][4][4];
#pragma unroll
    for (int i = 0; i < 4; i++)
#pragma unroll
        for (int j = 0; j < 4; j++)
#pragma unroll
            for (int q = 0; q < 4; q++) acc[i][j][q] = 0.f;

    for (int k0 = 0; k0 < K; k0 += 32) {
#pragma unroll
        for (int q = 0; q < 4; q++) {
            int idx = tid + q * 256;
            int row = idx >> 3, k4 = (idx & 7) * 4;
            float4 v = *(const float4*)(A + (size_t)(row0 + row) * K + k0 + k4);
            uint32_t* d = &As[row * AST + k4];
            d[0] = f2tf32(v.x); d[1] = f2tf32(v.y); d[2] = f2tf32(v.z); d[3] = f2tf32(v.w);
        }
#pragma unroll
        for (int q = 0; q < 4; q++) {
            int idx = tid + q * 256;
            int row = idx >> 3, k4 = (idx & 7) * 4;
            float4 v = *(const float4*)(B + (size_t)(col0 + row) * K + k0 + k4);
            uint32_t* d = &Bs[row * AST + k4];
            d[0] = f2tf32(v.x); d[1] = f2tf32(v.y); d[2] = f2tf32(v.z); d[3] = f2tf32(v.w);
        }
        __syncthreads();
#pragma unroll
        for (int kq = 0; kq < 4; kq++) {
            int kb = kq * 8;
            uint32_t af[4][4];
#pragma unroll
            for (int i = 0; i < 4; i++) {
                int base = (wm * 64 + i * 16 + gid) * AST + kb + tig;
                af[i][0] = As[base];
                af[i][1] = As[base + 8 * AST];
                af[i][2] = As[base + 4];
                af[i][3] = As[base + 8 * AST + 4];
            }
#pragma unroll
            for (int j = 0; j < 4; j++) {
                int bbase = (wn * 32 + j * 8 + gid) * AST + kb + tig;
                uint32_t b0 = Bs[bbase], b1 = Bs[bbase + 4];
#pragma unroll
                for (int i = 0; i < 4; i++)
                    mma_tf32(acc[i][j][0], acc[i][j][1], acc[i][j][2], acc[i][j][3],
                             af[i][0], af[i][1], af[i][2], af[i][3], b0, b1);
            }
        }
        __syncthreads();
    }
#pragma unroll
    for (int i = 0; i < 4; i++) {
#pragma unroll
        for (int j = 0; j < 4; j++) {
            int r = row0 + wm * 64 + i * 16 + gid;
            int cix = col0 + wn * 32 + j * 8 + tig * 2;
            float v0 = acc[i][j][0], v1 = acc[i][j][1];
            float v2 = acc[i][j][2], v3 = acc[i][j][3];
            if (colbias) {
                float bb0 = colbias[cix], bb1 = colbias[cix + 1];
                v0 += bb0; v1 += bb1; v2 += bb0; v3 += bb1;
            }
            if (act == 1) {
                v0 = fmaxf(v0, 0.f); v1 = fmaxf(v1, 0.f);
                v2 = fmaxf(v2, 0.f); v3 = fmaxf(v3, 0.f);
            }
            C[(size_t)r * N + cix]           = v0;
            C[(size_t)r * N + cix + 1]       = v1;
            C[(size_t)(r + 8) * N + cix]     = v2;
            C[(size_t)(r + 8) * N + cix + 1] = v3;
        }
    }
}

// =================================================================
// tf32 tensor-core GEMM NN: C[M,N] = A[M,K] @ B[K(ldB),N] + rowbias[M]
// M,N multiples of 128; K multiple of 32.
// =================================================================
#define BSTN 132
__global__ __launch_bounds__(256) void gemm_nn_tc(
    const float* __restrict__ A, const float* __restrict__ B,
    const float* __restrict__ rowbias, float* __restrict__ C,
    int M, int N, int K, size_t ldB)
{
    __shared__ uint32_t As[128 * AST];
    __shared__ uint32_t Bs[32 * BSTN];
    int tid = threadIdx.x, w = tid >> 5, lane = tid & 31;
    int gid = lane >> 2, tig = lane & 3;
    int wm = w >> 2, wn = w & 3;
    int row0 = blockIdx.y * 128, col0 = blockIdx.x * 128;

    float acc[4][4][4];
#pragma unroll
    for (int i = 0; i < 4; i++)
#pragma unroll
        for (int j = 0; j < 4; j++)
#pragma unroll
            for (int q = 0; q < 4; q++) acc[i][j][q] = 0.f;

    for (int k0 = 0; k0 < K; k0 += 32) {
#pragma unroll
        for (int q = 0; q < 4; q++) {
            int idx = tid + q * 256;
            int row = idx >> 3, k4 = (idx & 7) * 4;
            float4 v = *(const float4*)(A + (size_t)(row0 + row) * K + k0 + k4);
            uint32_t* d = &As[row * AST + k4];
            d[0] = f2tf32(v.x); d[1] = f2tf32(v.y); d[2] = f2tf32(v.z); d[3] = f2tf32(v.w);
        }
#pragma unroll
        for (int q = 0; q < 4; q++) {
            int idx = tid + q * 256;
            int k = idx >> 5, n4 = (idx & 31) * 4;
            float4 v = *(const float4*)(B + (size_t)(k0 + k) * ldB + col0 + n4);
            uint32_t* d = &Bs[k * BSTN + n4];
            d[0] = f2tf32(v.x); d[1] = f2tf32(v.y); d[2] = f2tf32(v.z); d[3] = f2tf32(v.w);
        }
        __syncthreads();
#pragma unroll
        for (int kq = 0; kq < 4; kq++) {
            int kb = kq * 8;
            uint32_t af[4][4];
#pragma unroll
            for (int i = 0; i < 4; i++) {
                int base = (wm * 64 + i * 16 + gid) * AST + kb + tig;
                af[i][0] = As[base];
                af[i][1] = As[base + 8 * AST];
                af[i][2] = As[base + 4];
                af[i][3] = As[base + 8 * AST + 4];
            }
#pragma unroll
            for (int j = 0; j < 4; j++) {
                int ncol = wn * 32 + j * 8 + gid;
                uint32_t b0 = Bs[(kb + tig) * BSTN + ncol];
                uint32_t b1 = Bs[(kb + tig + 4) * BSTN + ncol];
#pragma unroll
                for (int i = 0; i < 4; i++)
                    mma_tf32(acc[i][j][0], acc[i][j][1], acc[i][j][2], acc[i][j][3],
                             af[i][0], af[i][1], af[i][2], af[i][3], b0, b1);
            }
        }
        __syncthreads();
    }
#pragma unroll
    for (int i = 0; i < 4; i++) {
#pragma unroll
        for (int j = 0; j < 4; j++) {
            int r = row0 + wm * 64 + i * 16 + gid;
            int cix = col0 + wn * 32 + j * 8 + tig * 2;
            float rb0 = rowbias ? rowbias[r] : 0.f;
            float rb8 = rowbias ? rowbias[r + 8] : 0.f;
            C[(size_t)r * N + cix]           = acc[i][j][0] + rb0;
            C[(size_t)r * N + cix + 1]       = acc[i][j][1] + rb0;
            C[(size_t)(r + 8) * N + cix]     = acc[i][j][2] + rb8;
            C[(size_t)(r + 8) * N + cix + 1] = acc[i][j][3] + rb8;
        }
    }
}

// =================================================================
// SIMT SGEMM NT (small GEMMs): C = A @ B^T + colbias (+relu)
// =================================================================
__global__ __launch_bounds__(256) void gemm_nt(
    const float* __restrict__ A, const float* __restrict__ B,
    const float* __restrict__ colbias, float* __restrict__ C,
    int M, int N, int K, int act)
{
    __shared__ float As[16][128];
    __shared__ float Bs[16][128];
    int tid = threadIdx.x;
    int tx = tid & 15, ty = tid >> 4;
    int row0 = blockIdx.y * 128, col0 = blockIdx.x * 128;

    u64 acc[8][4];
#pragma unroll
    for (int i = 0; i < 8; i++)
#pragma unroll
        for (int j = 0; j < 4; j++) acc[i][j] = 0ull;

    int lr = tid >> 2, lc = tid & 3;
    for (int k0 = 0; k0 < K; k0 += 16) {
#pragma unroll
        for (int p = 0; p < 2; p++) {
            int r = lr + p * 64, gr = row0 + r;
            float4 v = make_float4(0.f, 0.f, 0.f, 0.f);
            if (gr < M) v = *(const float4*)(A + (size_t)gr * K + k0 + lc * 4);
            As[lc*4+0][r] = v.x; As[lc*4+1][r] = v.y; As[lc*4+2][r] = v.z; As[lc*4+3][r] = v.w;
        }
#pragma unroll
        for (int p = 0; p < 2; p++) {
            int r = lr + p * 64, gc = col0 + r;
            float4 v = make_float4(0.f, 0.f, 0.f, 0.f);
            if (gc < N) v = *(const float4*)(B + (size_t)gc * K + k0 + lc * 4);
            Bs[lc*4+0][r] = v.x; Bs[lc*4+1][r] = v.y; Bs[lc*4+2][r] = v.z; Bs[lc*4+3][r] = v.w;
        }
        __syncthreads();
#pragma unroll
        for (int kk = 0; kk < 16; kk++) {
            float a[8];
            *(float4*)&a[0] = *(const float4*)&As[kk][ty * 8];
            *(float4*)&a[4] = *(const float4*)&As[kk][ty * 8 + 4];
            u64 b4[4];
#pragma unroll
            for (int j = 0; j < 4; j++) b4[j] = *(const u64*)&Bs[kk][tx * 8 + 2 * j];
#pragma unroll
            for (int i = 0; i < 8; i++) {
                u64 ai = bcast2(a[i]);
#pragma unroll
                for (int j = 0; j < 4; j++) fma2(acc[i][j], ai, b4[j]);
            }
        }
        __syncthreads();
    }
#pragma unroll
    for (int i = 0; i < 8; i++) {
        int gm = row0 + ty * 8 + i;
        if (gm >= M) continue;
#pragma unroll
        for (int j = 0; j < 4; j++) {
            float2 c2 = unpk(acc[i][j]);
            int gn = col0 + tx * 8 + 2 * j;
            float v0 = c2.x, v1 = c2.y;
            if (colbias) { v0 += colbias[gn]; v1 += colbias[gn + 1]; }
            if (act == 1) { v0 = fmaxf(v0, 0.f); v1 = fmaxf(v1, 0.f); }
            if (gn < N)     C[(size_t)gm * N + gn]     = v0;
            if (gn + 1 < N) C[(size_t)gm * N + gn + 1] = v1;
        }
    }
}

// =================================================================
// Persistent GRU v10 (unchanged from R10 passing version)
// =================================================================
#define PBS 9
#define ASTRIDE 132
#define PBUF_F (112 * 24 * PBS)
#define ABUF_F (16 * ASTRIDE)
#define GRU_SMEM ((PBUF_F + 8 * ABUF_F) * 4)

__device__ __forceinline__ void gridbar()
{
    __threadfence();
    __syncthreads();
    if (threadIdx.x == 0) {
        volatile unsigned* vg = &g_gen;
        unsigned target = *vg + 1;
        if (atomicAdd(&g_cnt, 1) == gridDim.x - 1) {
            g_cnt = 0;
            __threadfence();
            atomicAdd(&g_gen, 1);
        } else {
            while ((int)(*vg - target) < 0) { }
        }
        __threadfence();
    }
    __syncthreads();
}

__global__ __launch_bounds__(256, 1) void gru_mma(
    const float* __restrict__ xp, const float* __restrict__ Whh,
    const float* __restrict__ bhh, float* __restrict__ hbt)
{
    extern __shared__ float smf[];
    float* pbuf = smf;
    int tid  = threadIdx.x;
    int w    = tid >> 5;
    int lane = tid & 31;
    float* abuf = smf + PBUF_F + w * ABUF_F;
    int gidq = lane >> 2;
    int tig  = lane & 3;
    int col0 = blockIdx.x * 8;
    int k0   = w * 128;

    uint32_t bf[16][3][2];
#pragma unroll
    for (int kt = 0; kt < 16; kt++) {
#pragma unroll
        for (int j = 0; j < 3; j++) {
            int n = j * 8 + gidq;
            int c = n / 3, g = n % 3;
            const float* wrow = Whh + ((size_t)g * HD + col0 + c) * HD;
            int kk = k0 + kt * 8 + tig;
            bf[kt][j][0] = f2tf32(wrow[kk]);
            bf[kt][j][1] = f2tf32(wrow[kk + 4]);
        }
    }

    for (int t = 0; t < TT; t++) {
        if (t > 0) {
            const float* hprev = hbt + (size_t)(t - 1) * HBT_STRIDE;
#pragma unroll 1
            for (int mt = 0; mt < 7; mt++) {
                const float* src = hprev + (size_t)(mt * 16) * HD + k0;
#pragma unroll
                for (int j = 0; j < 16; j++) {
                    int f4 = lane + j * 32;
                    int row = f4 >> 5, c4 = f4 & 31;
                    float4 v = *(const float4*)(src + (size_t)row * HD + c4 * 4);
                    *(float4*)(abuf + row * ASTRIDE + c4 * 4) = v;
                }
                __syncwarp();

                float c0[3], c1[3], c2[3], c3[3];
#pragma unroll
                for (int j = 0; j < 3; j++) { c0[j] = 0.f; c1[j] = 0.f; c2[j] = 0.f; c3[j] = 0.f; }

                const float* fb = abuf + gidq * ASTRIDE + tig;
#pragma unroll
                for (int kt = 0; kt < 16; kt++) {
                    const float* p = fb + kt * 8;
                    uint32_t a0 = __float_as_uint(p[0]);
                    uint32_t a1 = __float_as_uint(p[8 * ASTRIDE]);
                    uint32_t a2 = __float_as_uint(p[4]);
                    uint32_t a3 = __float_as_uint(p[8 * ASTRIDE + 4]);
#pragma unroll
                    for (int j = 0; j < 3; j++)
                        mma_tf32(c0[j], c1[j], c2[j], c3[j],
                                 a0, a1, a2, a3, bf[kt][j][0], bf[kt][j][1]);
                }
                __syncwarp();

                int r0 = mt * 16 + gidq;
#pragma unroll
                for (int j = 0; j < 3; j++) {
                    int n0 = j * 8 + tig * 2;
                    pbuf[((size_t)r0 * 24 + n0) * PBS + w]           = c0[j];
                    pbuf[((size_t)r0 * 24 + n0 + 1) * PBS + w]       = c1[j];
                    pbuf[((size_t)(r0 + 8) * 24 + n0) * PBS + w]     = c2[j];
                    pbuf[((size_t)(r0 + 8) * 24 + n0 + 1) * PBS + w] = c3[j];
                }
            }
        }
        __syncthreads();

        for (int idx = tid; idx < NB * 8; idx += 256) {
            int b = idx >> 3, c = idx & 7;
            int col = col0 + c;
            float ar = 0.f, az = 0.f, an = 0.f;
            if (t > 0) {
                const float* pr = pbuf + ((size_t)b * 24 + c * 3) * PBS;
#pragma unroll
                for (int ww = 0; ww < 8; ww++) {
                    ar += pr[ww];
                    az += pr[PBS + ww];
                    an += pr[2 * PBS + ww];
                }
            }
            size_t xbase = ((size_t)b * TT + t) * H3;
            float xr = xp[xbase + col];
            float xz = xp[xbase + HD + col];
            float xn = xp[xbase + 2 * HD + col];
            float hold = (t > 0) ? hbt[(size_t)(t - 1) * HBT_STRIDE + (size_t)b * HD + col] : 0.f;
            float r = sigf(xr + ar + bhh[col]);
            float z = sigf(xz + az + bhh[HD + col]);
            float n = tanhf(xn + r * (an + bhh[2 * HD + col]));
            hbt[(size_t)t * HBT_STRIDE + (size_t)b * HD + col] = (1.f - z) * n + z * hold;
        }

        gridbar();
    }
}

// =================================================================
// one-pass online-softmax reduce
// =================================================================
__global__ void att_reduce_flat(const float* __restrict__ S,
                                const float* __restrict__ H,
                                float* __restrict__ v)
{
    int j = blockIdx.x * 256 + threadIdx.x;
    float mx = -1e30f, se = 0.f, sv = 0.f;
#pragma unroll 4
    for (int u = 0; u < TT; u++) {
        float s = S[(size_t)u * NDB + j];
        float h = H[(size_t)u * HBT_STRIDE + j];
        float m2 = fmaxf(mx, s);
        float cor = expf(mx - m2);
        float e = expf(s - m2);
        se = se * cor + e;
        sv = sv * cor + e * h;
        mx = m2;
    }
    v[j] = sv / se;
}

// pool attention, row-major v -> catv[c][d]
__global__ void pool_att(const float* __restrict__ v, const float* __restrict__ pW,
                         const float* __restrict__ pb, float* __restrict__ catv)
{
    int c = blockIdx.x;
    int d = blockIdx.y * 256 + threadIdx.x;
    __shared__ float sW[400];
    __shared__ float sb[20];
    for (int i = threadIdx.x; i < 400; i += 256) sW[i] = pW[i];
    if (threadIdx.x < 20) sb[threadIdx.x] = pb[threadIdx.x];
    __syncthreads();

    float xv[20];
#pragma unroll
    for (int s = 0; s < 20; s++) xv[s] = v[(size_t)(c * 20 + s) * HD + d];
    float wv[20]; float mx = -1e30f;
#pragma unroll
    for (int u = 0; u < 20; u++) {
        float s = sb[u];
#pragma unroll
        for (int t2 = 0; t2 < 20; t2++) s += xv[t2] * sW[u * 20 + t2];
        wv[u] = s; mx = fmaxf(mx, s);
    }
    float se = 0.f, sv = 0.f;
#pragma unroll
    for (int u = 0; u < 20; u++) {
        float e = expf(wv[u] - mx);
        se += e; sv += e * xv[u];
    }
    catv[(size_t)c * HD + d] = sv / se;
}

// two dots per node (row-major)
__global__ void dot2(const float* __restrict__ h, const float* __restrict__ a1,
                     const float* __restrict__ a2, float* __restrict__ o1,
                     float* __restrict__ o2)
{
    int n = blockIdx.x;
    __shared__ float s1[256], s2[256];
    float p1 = 0.f, p2 = 0.f;
    for (int k = threadIdx.x; k < HD; k += 256) {
        float hv = h[(size_t)n * HD + k];
        p1 += hv * a1[k]; p2 += hv * a2[k];
    }
    s1[threadIdx.x] = p1; s2[threadIdx.x] = p2;
    __syncthreads();
    for (int s = 128; s > 0; s >>= 1) {
        if (threadIdx.x < s) { s1[threadIdx.x] += s1[threadIdx.x + s]; s2[threadIdx.x] += s2[threadIdx.x + s]; }
        __syncthreads();
    }
    if (threadIdx.x == 0) { o1[n] = s1[0]; o2[n] = s2[0]; }
}

// GAT aggregation (complete cliques + self loops), row-major
__global__ void gat_agg(const float* __restrict__ h, const float* __restrict__ as,
                        const float* __restrict__ ad, const float* __restrict__ bias,
                        float* __restrict__ out, int group)
{
    int n = blockIdx.x;
    int base = (n / group) * group;
    __shared__ float alpha[32];
    if (threadIdx.x == 0) {
        float e[32]; float mx = -1e30f;
        for (int s = 0; s < group; s++) {
            float x = as[base + s] + ad[n];
            x = (x > 0.f) ? x : 0.2f * x;
            e[s] = x; mx = fmaxf(mx, x);
        }
        float se = 0.f;
        for (int s = 0; s < group; s++) { e[s] = expf(e[s] - mx); se += e[s]; }
        for (int s = 0; s < group; s++) alpha[s] = e[s] / se;
    }
    __syncthreads();
    for (int dd = threadIdx.x; dd < HD; dd += 256) {
        float acc = 0.f;
        for (int s = 0; s < group; s++)
            acc += alpha[s] * h[(size_t)(base + s) * HD + dd];
        out[(size_t)n * HD + dd] = acc + bias[dd];
    }
}

// fusion concat (row-major)
__global__ void build_fusion(const float* __restrict__ v, const float* __restrict__ catv,
                             const float* __restrict__ inner, float* __restrict__ fin)
{
    int idx = blockIdx.x * 256 + threadIdx.x;
    if (idx >= NB * H3) return;
    int n = idx / H3, k = idx - n * H3;
    float val;
    if (k < HD)            val = v[(size_t)n * HD + k];
    else if (k < 2 * HD)   val = catv[(size_t)(n / 20) * HD + (k - HD)];
    else                   val = inner[(size_t)n * HD + (k - 2 * HD)];
    fin[idx] = val;
}

// heads (row-major)
__global__ void heads(const float* __restrict__ f, const float* __restrict__ rw,
                      const float* __restrict__ rb, const float* __restrict__ cw,
                      const float* __restrict__ cb, float* __restrict__ out)
{
    int n = blockIdx.x;
    __shared__ float s1[256], s2[256];
    float p1 = 0.f, p2 = 0.f;
    for (int k = threadIdx.x; k < HD; k += 256) {
        float fv = f[(size_t)n * HD + k];
        p1 += fv * rw[k]; p2 += fv * cw[k];
    }
    s1[threadIdx.x] = p1; s2[threadIdx.x] = p2;
    __syncthreads();
    for (int s = 128; s > 0; s >>= 1) {
        if (threadIdx.x < s) { s1[threadIdx.x] += s1[threadIdx.x + s]; s2[threadIdx.x] += s2[threadIdx.x + s]; }
        __syncthreads();
    }
    if (threadIdx.x == 0) {
        out[n]      = s1[0] + rb[0];
        out[NB + n] = 1.f / (1.f + expf(-(s2[0] + cb[0])));
    }
}

// =================================================================
extern "C" void kernel_launch(void* const* d_in, const int* in_sizes, int n_in,
                              void* d_out, int out_size)
{
    const float* weekly  = (const float*)d_in[0];
    const float* Wih     = (const float*)d_in[1];
    const float* Whh     = (const float*)d_in[2];
    const float* bih     = (const float*)d_in[3];
    const float* bhh     = (const float*)d_in[4];
    const float* encW    = (const float*)d_in[5];
    const float* encB    = (const float*)d_in[6];
    const float* poolW   = (const float*)d_in[7];
    const float* poolB   = (const float*)d_in[8];
    const float* innerW  = (const float*)d_in[9];
    const float* innerAs = (const float*)d_in[10];
    const float* innerAd = (const float*)d_in[11];
    const float* innerB  = (const float*)d_in[12];
    const float* catW    = (const float*)d_in[13];
    const float* catAs   = (const float*)d_in[14];
    const float* catAd   = (const float*)d_in[15];
    const float* catB    = (const float*)d_in[16];
    const float* fusW    = (const float*)d_in[17];
    const float* fusB    = (const float*)d_in[18];
    const float* regW    = (const float*)d_in[19];
    const float* regB    = (const float*)d_in[20];
    const float* clsW    = (const float*)d_in[21];
    const float* clsB    = (const float*)d_in[22];
    float* out = (float*)d_out;

    float *xp, *hbt, *v, *hp, *inner, *catv, *hp2, *catg, *as_, *ad_, *as2, *ad2, *fin, *f;
    cudaGetSymbolAddress((void**)&xp,    g_xp);
    cudaGetSymbolAddress((void**)&hbt,   g_hbt);
    cudaGetSymbolAddress((void**)&v,     g_v);
    cudaGetSymbolAddress((void**)&hp,    g_hp);
    cudaGetSymbolAddress((void**)&inner, g_inner);
    cudaGetSymbolAddress((void**)&catv,  g_catv);
    cudaGetSymbolAddress((void**)&hp2,   g_hp2);
    cudaGetSymbolAddress((void**)&catg,  g_cat);
    cudaGetSymbolAddress((void**)&as_,   g_as);
    cudaGetSymbolAddress((void**)&ad_,   g_ad);
    cudaGetSymbolAddress((void**)&as2,   g_as2);
    cudaGetSymbolAddress((void**)&ad2,   g_ad2);
    cudaGetSymbolAddress((void**)&fin,   g_fin);
    cudaGetSymbolAddress((void**)&f,     g_f);

    // 1) xp = weekly(51200,256) @ Wih^T + bih   [b][t][g]   (tf32 tensor cores)
    gemm_nt_tc<<<dim3(H3 / 128, (NB * TT) / 128), 256>>>(weekly, Wih, bih, xp, NB * TT, H3, IND, 0);

    // 2) persistent tf32 mma GRU -> hbt [t][b][k] (b padded to 128)
    cudaFuncSetAttribute(gru_mma, cudaFuncAttributeMaxDynamicSharedMemorySize, GRU_SMEM);
    gru_mma<<<128, 256, GRU_SMEM>>>(xp, Whh, bhh, hbt);

    // 3) S(512 x 102400) = encW @ Hflat + encB[u]  (tf32; H row stride 131072)
    gemm_nn_tc<<<dim3(NDB / 128, TT / 128), 256>>>(encW, hbt, encB, xp, TT, NDB, TT, (size_t)HBT_STRIDE);

    // 4) v[j] = softmax-over-u(S) . H   (v is [100][1024] row-major)
    att_reduce_flat<<<NDB / 256, 256>>>(xp, hbt, v);

    // 5) inner GAT: hp = v @ innerW^T
    gemm_nt<<<dim3(HD / 128, 1), 256>>>(v, innerW, nullptr, hp, NB, HD, HD, 0);
    dot2<<<NB, 256>>>(hp, innerAs, innerAd, as_, ad_);
    gat_agg<<<NB, 256>>>(hp, as_, ad_, innerB, inner, 20);

    // 6) pool 20 stocks -> category vectors
    pool_att<<<dim3(5, HD / 256), 256>>>(v, poolW, poolB, catv);

    // 7) category GAT
    gemm_nt<<<dim3(HD / 128, 1), 256>>>(catv, catW, nullptr, hp2, 5, HD, HD, 0);
    dot2<<<5, 256>>>(hp2, catAs, catAd, as2, ad2);
    gat_agg<<<5, 256>>>(hp2, as2, ad2, catB, catg, 5);

    // 8) fusion
    build_fusion<<<(NB * H3 + 255) / 256, 256>>>(v, catg, inner, fin);
    gemm_nt<<<dim3(HD / 128, 1), 256>>>(fin, fusW, fusB, f, NB, HD, H3, 1);

    // 9) heads
    heads<<<NB, 256>>>(f, regW, regB, clsW, clsB, out);
}

// round 12
// speedup vs baseline: 8.5624x; 1.0782x over previous
#include <cuda_runtime.h>
#include <math.h>
#include <stdint.h>
#include <stddef.h>

typedef unsigned long long u64;

#define NB   100
#define TT   512
#define IND  256
#define HD   1024
#define H3   3072
#define NDB  (HD * NB)          // 102400
#define HBT_STRIDE (128 * 1024) // padded per-t stride (128 batch rows x 1024)

// ---------------- scratch ----------------
__device__ float g_xp [(size_t)TT * NB * H3];     // xp [t][b][g]; later reused as S [u][j]
__device__ float g_hbt[(size_t)TT * HBT_STRIDE];  // h states [t][b(pad128)][k]
__device__ float g_v  [NB * HD];
__device__ float g_hp [NB * HD];
__device__ float g_inner[NB * HD];
__device__ float g_catv[5 * HD];
__device__ float g_hp2 [5 * HD];
__device__ float g_cat [5 * HD];
__device__ float g_as[NB];
__device__ float g_ad[NB];
__device__ float g_as2[8];
__device__ float g_ad2[8];
__device__ float g_fin[NB * H3];
__device__ float g_f  [NB * HD];
__device__ unsigned g_cnt;
__device__ unsigned g_gen;

// ---------------- helpers ----------------
__device__ __forceinline__ u64 bcast2(float x) {
    u64 r; unsigned u = __float_as_uint(x);
    asm("mov.b64 %0, {%1, %1};" : "=l"(r) : "r"(u));
    return r;
}
__device__ __forceinline__ void fma2(u64& d, u64 a, u64 b) {
    asm("fma.rn.f32x2 %0, %1, %2, %0;" : "+l"(d) : "l"(a), "l"(b));
}
__device__ __forceinline__ float2 unpk(u64 v) {
    unsigned lo, hi;
    asm("mov.b64 {%0, %1}, %2;" : "=r"(lo), "=r"(hi) : "l"(v));
    return make_float2(__uint_as_float(lo), __uint_as_float(hi));
}
__device__ __forceinline__ uint32_t f2tf32(float x) {
    uint32_t u;
    asm("cvt.rna.tf32.f32 %0, %1;" : "=r"(u) : "f"(x));
    return u;
}
// fast sigmoid / tanh via hardware EX2 (safe at extremes: exp->inf => 0)
__device__ __forceinline__ float fsig(float x) {
    return __fdividef(1.f, 1.f + __expf(-x));
}
__device__ __forceinline__ float ftanh(float x) {
    float ax = fabsf(x);
    float e = __expf(2.f * ax);
    float t = 1.f - __fdividef(2.f, e + 1.f);
    return copysignf(t, x);
}
__device__ __forceinline__ uint32_t smem_u32(const void* p) {
    uint32_t a;
    asm("{ .reg .u64 t; cvta.to.shared.u64 t, %1; cvt.u32.u64 %0, t; }" : "=r"(a) : "l"(p));
    return a;
}
#define CP_ASYNC16(dst, src) \
    asm volatile("cp.async.ca.shared.global [%0], [%1], 16;" :: "r"(dst), "l"(src))
#define CP_COMMIT()  asm volatile("cp.async.commit_group;" ::: "memory")
#define CP_WAIT0()   asm volatile("cp.async.wait_group 0;" ::: "memory")

// tf32 warp MMA: D(16x8) += A(16x8) * B(8x8)
__device__ __forceinline__ void mma_tf32(
    float& c0, float& c1, float& c2, float& c3,
    uint32_t a0, uint32_t a1, uint32_t a2, uint32_t a3,
    uint32_t b0, uint32_t b1)
{
    asm volatile(
        "mma.sync.aligned.m16n8k8.row.col.f32.tf32.tf32.f32 "
        "{%0,%1,%2,%3}, {%4,%5,%6,%7}, {%8,%9}, {%0,%1,%2,%3};"
        : "+f"(c0), "+f"(c1), "+f"(c2), "+f"(c3)
        : "r"(a0), "r"(a1), "r"(a2), "r"(a3), "r"(b0), "r"(b1));
}

// =================================================================
// tf32 tensor-core GEMM NT: C[M,N] = A[M,K] @ B[N,K]^T + colbias (+relu)
// M,N multiples of 128; K multiple of 32. remap!=0: output row gm
// (= b*TT+t) is stored at row (t*NB + b) instead (xp -> [t][b][g]).
// =================================================================
#define AST 36
__global__ __launch_bounds__(256) void gemm_nt_tc(
    const float* __restrict__ A, const float* __restrict__ B,
    const float* __restrict__ colbias, float* __restrict__ C,
    int M, int N, int K, int act, int remap)
{
    __shared__ uint32_t As[128 * AST];
    __shared__ uint32_t Bs[128 * AST];
    int tid = threadIdx.x, w = tid >> 5, lane = tid & 31;
    int gid = lane >> 2, tig = lane & 3;
    int wm = w >> 2, wn = w & 3;
    int row0 = blockIdx.y * 128, col0 = blockIdx.x * 128;

    float acc[4][4][4];
#pragma unroll
    for (int i = 0; i < 4; i++)
#pragma unroll
        for (int j = 0; j < 4; j++)
#pragma unroll
            for (int q = 0; q < 4; q++) acc[i][j][q] = 0.f;

    for (int k0 = 0; k0 < K; k0 += 32) {
#pragma unroll
        for (int q = 0; q < 4; q++) {
            int idx = tid + q * 256;
            int row = idx >> 3, k4 = (idx & 7) * 4;
            float4 v = *(const float4*)(A + (size_t)(row0 + row) * K + k0 + k4);
            uint32_t* d = &As[row * AST + k4];
            d[0] = f2tf32(v.x); d[1] = f2tf32(v.y); d[2] = f2tf32(v.z); d[3] = f2tf32(v.w);
        }
#pragma unroll
        for (int q = 0; q < 4; q++) {
            int idx = tid + q * 256;
            int row = idx >> 3, k4 = (idx & 7) * 4;
            float4 v = *(const float4*)(B + (size_t)(col0 + row) * K + k0 + k4);
            uint32_t* d = &Bs[row * AST + k4];
            d[0] = f2tf32(v.x); d[1] = f2tf32(v.y); d[2] = f2tf32(v.z); d[3] = f2tf32(v.w);
        }
        __syncthreads();
#pragma unroll
        for (int kq = 0; kq < 4; kq++) {
            int kb = kq * 8;
            uint32_t af[4][4];
#pragma unroll
            for (int i = 0; i < 4; i++) {
                int base = (wm * 64 + i * 16 + gid) * AST + kb + tig;
                af[i][0] = As[base];
                af[i][1] = As[base + 8 * AST];
                af[i][2] = As[base + 4];
                af[i][3] = As[base + 8 * AST + 4];
            }
#pragma unroll
            for (int j = 0; j < 4; j++) {
                int bbase = (wn * 32 + j * 8 + gid) * AST + kb + tig;
                uint32_t b0 = Bs[bbase], b1 = Bs[bbase + 4];
#pragma unroll
                for (int i = 0; i < 4; i++)
                    mma_tf32(acc[i][j][0], acc[i][j][1], acc[i][j][2], acc[i][j][3],
                             af[i][0], af[i][1], af[i][2], af[i][3], b0, b1);
            }
        }
        __syncthreads();
    }
#pragma unroll
    for (int i = 0; i < 4; i++) {
#pragma unroll
        for (int j = 0; j < 4; j++) {
            int r = row0 + wm * 64 + i * 16 + gid;
            int r2 = r + 8;
            int cix = col0 + wn * 32 + j * 8 + tig * 2;
            float v0 = acc[i][j][0], v1 = acc[i][j][1];
            float v2 = acc[i][j][2], v3 = acc[i][j][3];
            if (colbias) {
                float bb0 = colbias[cix], bb1 = colbias[cix + 1];
                v0 += bb0; v1 += bb1; v2 += bb0; v3 += bb1;
            }
            if (act == 1) {
                v0 = fmaxf(v0, 0.f); v1 = fmaxf(v1, 0.f);
                v2 = fmaxf(v2, 0.f); v3 = fmaxf(v3, 0.f);
            }
            size_t ro = (size_t)r, ro2 = (size_t)r2;
            if (remap) {
                ro  = (size_t)(r  % TT) * NB + (r  / TT);
                ro2 = (size_t)(r2 % TT) * NB + (r2 / TT);
            }
            C[ro  * N + cix]     = v0;
            C[ro  * N + cix + 1] = v1;
            C[ro2 * N + cix]     = v2;
            C[ro2 * N + cix + 1] = v3;
        }
    }
}

// =================================================================
// tf32 tensor-core GEMM NN: C[M,N] = A[M,K] @ B[K(ldB),N] + rowbias[M]
// =================================================================
#define BSTN 132
__global__ __launch_bounds__(256) void gemm_nn_tc(
    const float* __restrict__ A, const float* __restrict__ B,
    const float* __restrict__ rowbias, float* __restrict__ C,
    int M, int N, int K, size_t ldB)
{
    __shared__ uint32_t As[128 * AST];
    __shared__ uint32_t Bs[32 * BSTN];
    int tid = threadIdx.x, w = tid >> 5, lane = tid & 31;
    int gid = lane >> 2, tig = lane & 3;
    int wm = w >> 2, wn = w & 3;
    int row0 = blockIdx.y * 128, col0 = blockIdx.x * 128;

    float acc[4][4][4];
#pragma unroll
    for (int i = 0; i < 4; i++)
#pragma unroll
        for (int j = 0; j < 4; j++)
#pragma unroll
            for (int q = 0; q < 4; q++) acc[i][j][q] = 0.f;

    for (int k0 = 0; k0 < K; k0 += 32) {
#pragma unroll
        for (int q = 0; q < 4; q++) {
            int idx = tid + q * 256;
            int row = idx >> 3, k4 = (idx & 7) * 4;
            float4 v = *(const float4*)(A + (size_t)(row0 + row) * K + k0 + k4);
            uint32_t* d = &As[row * AST + k4];
            d[0] = f2tf32(v.x); d[1] = f2tf32(v.y); d[2] = f2tf32(v.z); d[3] = f2tf32(v.w);
        }
#pragma unroll
        for (int q = 0; q < 4; q++) {
            int idx = tid + q * 256;
            int k = idx >> 5, n4 = (idx & 31) * 4;
            float4 v = *(const float4*)(B + (size_t)(k0 + k) * ldB + col0 + n4);
            uint32_t* d = &Bs[k * BSTN + n4];
            d[0] = f2tf32(v.x); d[1] = f2tf32(v.y); d[2] = f2tf32(v.z); d[3] = f2tf32(v.w);
        }
        __syncthreads();
#pragma unroll
        for (int kq = 0; kq < 4; kq++) {
            int kb = kq * 8;
            uint32_t af[4][4];
#pragma unroll
            for (int i = 0; i < 4; i++) {
                int base = (wm * 64 + i * 16 + gid) * AST + kb + tig;
                af[i][0] = As[base];
                af[i][1] = As[base + 8 * AST];
                af[i][2] = As[base + 4];
                af[i][3] = As[base + 8 * AST + 4];
            }
#pragma unroll
            for (int j = 0; j < 4; j++) {
                int ncol = wn * 32 + j * 8 + gid;
                uint32_t b0 = Bs[(kb + tig) * BSTN + ncol];
                uint32_t b1 = Bs[(kb + tig + 4) * BSTN + ncol];
#pragma unroll
                for (int i = 0; i < 4; i++)
                    mma_tf32(acc[i][j][0], acc[i][j][1], acc[i][j][2], acc[i][j][3],
                             af[i][0], af[i][1], af[i][2], af[i][3], b0, b1);
            }
        }
        __syncthreads();
    }
#pragma unroll
    for (int i = 0; i < 4; i++) {
#pragma unroll
        for (int j = 0; j < 4; j++) {
            int r = row0 + wm * 64 + i * 16 + gid;
            int cix = col0 + wn * 32 + j * 8 + tig * 2;
            float rb0 = rowbias ? rowbias[r] : 0.f;
            float rb8 = rowbias ? rowbias[r + 8] : 0.f;
            C[(size_t)r * N + cix]           = acc[i][j][0] + rb0;
            C[(size_t)r * N + cix + 1]       = acc[i][j][1] + rb0;
            C[(size_t)(r + 8) * N + cix]     = acc[i][j][2] + rb8;
            C[(size_t)(r + 8) * N + cix + 1] = acc[i][j][3] + rb8;
        }
    }
}

// =================================================================
// SIMT SGEMM NT (small GEMMs): C = A @ B^T + colbias (+relu)
// =================================================================
__global__ __launch_bounds__(256) void gemm_nt(
    const float* __restrict__ A, const float* __restrict__ B,
    const float* __restrict__ colbias, float* __restrict__ C,
    int M, int N, int K, int act)
{
    __shared__ float As[16][128];
    __shared__ float Bs[16][128];
    int tid = threadIdx.x;
    int tx = tid & 15, ty = tid >> 4;
    int row0 = blockIdx.y * 128, col0 = blockIdx.x * 128;

    u64 acc[8][4];
#pragma unroll
    for (int i = 0; i < 8; i++)
#pragma unroll
        for (int j = 0; j < 4; j++) acc[i][j] = 0ull;

    int lr = tid >> 2, lc = tid & 3;
    for (int k0 = 0; k0 < K; k0 += 16) {
#pragma unroll
        for (int p = 0; p < 2; p++) {
            int r = lr + p * 64, gr = row0 + r;
            float4 v = make_float4(0.f, 0.f, 0.f, 0.f);
            if (gr < M) v = *(const float4*)(A + (size_t)gr * K + k0 + lc * 4);
            As[lc*4+0][r] = v.x; As[lc*4+1][r] = v.y; As[lc*4+2][r] = v.z; As[lc*4+3][r] = v.w;
        }
#pragma unroll
        for (int p = 0; p < 2; p++) {
            int r = lr + p * 64, gc = col0 + r;
            float4 v = make_float4(0.f, 0.f, 0.f, 0.f);
            if (gc < N) v = *(const float4*)(B + (size_t)gc * K + k0 + lc * 4);
            Bs[lc*4+0][r] = v.x; Bs[lc*4+1][r] = v.y; Bs[lc*4+2][r] = v.z; Bs[lc*4+3][r] = v.w;
        }
        __syncthreads();
#pragma unroll
        for (int kk = 0; kk < 16; kk++) {
            float a[8];
            *(float4*)&a[0] = *(const float4*)&As[kk][ty * 8];
            *(float4*)&a[4] = *(const float4*)&As[kk][ty * 8 + 4];
            u64 b4[4];
#pragma unroll
            for (int j = 0; j < 4; j++) b4[j] = *(const u64*)&Bs[kk][tx * 8 + 2 * j];
#pragma unroll
            for (int i = 0; i < 8; i++) {
                u64 ai = bcast2(a[i]);
#pragma unroll
                for (int j = 0; j < 4; j++) fma2(acc[i][j], ai, b4[j]);
            }
        }
        __syncthreads();
    }
#pragma unroll
    for (int i = 0; i < 8; i++) {
        int gm = row0 + ty * 8 + i;
        if (gm >= M) continue;
#pragma unroll
        for (int j = 0; j < 4; j++) {
            float2 c2 = unpk(acc[i][j]);
            int gn = col0 + tx * 8 + 2 * j;
            float v0 = c2.x, v1 = c2.y;
            if (colbias) { v0 += colbias[gn]; v1 += colbias[gn + 1]; }
            if (act == 1) { v0 = fmaxf(v0, 0.f); v1 = fmaxf(v1, 0.f); }
            if (gn < N)     C[(size_t)gm * N + gn]     = v0;
            if (gn + 1 < N) C[(size_t)gm * N + gn + 1] = v1;
        }
    }
}

// =================================================================
// Persistent GRU v11: tf32 mma + cp.async staging + coalesced xp.
// 128 blocks x 256 threads (8 warps). Block owns 8 hidden cols.
// =================================================================
#define PBS 9
#define ASTRIDE 132
#define PBUF_F (112 * 24 * PBS)
#define ABUF_F (16 * ASTRIDE)
#define GRU_SMEM ((PBUF_F + 8 * ABUF_F) * 4)

__device__ __forceinline__ void gridbar()
{
    __threadfence();
    __syncthreads();
    if (threadIdx.x == 0) {
        volatile unsigned* vg = &g_gen;
        unsigned target = *vg + 1;
        if (atomicAdd(&g_cnt, 1) == gridDim.x - 1) {
            g_cnt = 0;
            __threadfence();
            atomicAdd(&g_gen, 1);
        } else {
            while ((int)(*vg - target) < 0) { }
        }
        __threadfence();
    }
    __syncthreads();
}

__global__ __launch_bounds__(256, 1) void gru_mma(
    const float* __restrict__ xpt, const float* __restrict__ Whh,
    const float* __restrict__ bhh, float* __restrict__ hbt)
{
    extern __shared__ float smf[];
    float* pbuf = smf;
    int tid  = threadIdx.x;
    int w    = tid >> 5;
    int lane = tid & 31;
    float* abuf = smf + PBUF_F + w * ABUF_F;
    uint32_t abuf_u32 = smem_u32(abuf);
    int gidq = lane >> 2;
    int tig  = lane & 3;
    int col0 = blockIdx.x * 8;
    int k0   = w * 128;

    // staging slot for this lane (fixed across mt)
    int srow[16], scol[16];
#pragma unroll
    for (int j = 0; j < 16; j++) {
        int f4 = lane + j * 32;
        srow[j] = f4 >> 5; scol[j] = (f4 & 31) * 4;
    }

    uint32_t bf[16][3][2];
#pragma unroll
    for (int kt = 0; kt < 16; kt++) {
#pragma unroll
        for (int j = 0; j < 3; j++) {
            int n = j * 8 + gidq;
            int c = n / 3, g = n % 3;
            const float* wrow = Whh + ((size_t)g * HD + col0 + c) * HD;
            int kk = k0 + kt * 8 + tig;
            bf[kt][j][0] = f2tf32(wrow[kk]);
            bf[kt][j][1] = f2tf32(wrow[kk + 4]);
        }
    }

    for (int t = 0; t < TT; t++) {
        if (t > 0) {
            const float* hprev = hbt + (size_t)(t - 1) * HBT_STRIDE;
#pragma unroll 1
            for (int mt = 0; mt < 7; mt++) {
                const float* src = hprev + (size_t)(mt * 16) * HD + k0;
#pragma unroll
                for (int j = 0; j < 16; j++)
                    CP_ASYNC16(abuf_u32 + (uint32_t)(srow[j] * ASTRIDE + scol[j]) * 4,
                               src + (size_t)srow[j] * HD + scol[j]);
                CP_COMMIT();
                CP_WAIT0();
                __syncwarp();

                float c0[3], c1[3], c2[3], c3[3];
#pragma unroll
                for (int j = 0; j < 3; j++) { c0[j] = 0.f; c1[j] = 0.f; c2[j] = 0.f; c3[j] = 0.f; }

                const float* fb = abuf + gidq * ASTRIDE + tig;
#pragma unroll
                for (int kt = 0; kt < 16; kt++) {
                    const float* p = fb + kt * 8;
                    uint32_t a0 = __float_as_uint(p[0]);
                    uint32_t a1 = __float_as_uint(p[8 * ASTRIDE]);
                    uint32_t a2 = __float_as_uint(p[4]);
                    uint32_t a3 = __float_as_uint(p[8 * ASTRIDE + 4]);
#pragma unroll
                    for (int j = 0; j < 3; j++)
                        mma_tf32(c0[j], c1[j], c2[j], c3[j],
                                 a0, a1, a2, a3, bf[kt][j][0], bf[kt][j][1]);
                }
                __syncwarp();

                int r0 = mt * 16 + gidq;
#pragma unroll
                for (int j = 0; j < 3; j++) {
                    int n0 = j * 8 + tig * 2;
                    pbuf[((size_t)r0 * 24 + n0) * PBS + w]           = c0[j];
                    pbuf[((size_t)r0 * 24 + n0 + 1) * PBS + w]       = c1[j];
                    pbuf[((size_t)(r0 + 8) * 24 + n0) * PBS + w]     = c2[j];
                    pbuf[((size_t)(r0 + 8) * 24 + n0 + 1) * PBS + w] = c3[j];
                }
            }
        }
        __syncthreads();

        // fused reduction + gate epilogue (xpt is [t][b][g]: coalesced)
        for (int idx = tid; idx < NB * 8; idx += 256) {
            int b = idx >> 3, c = idx & 7;
            int col = col0 + c;
            float ar = 0.f, az = 0.f, an = 0.f;
            if (t > 0) {
                const float* pr = pbuf + ((size_t)b * 24 + c * 3) * PBS;
#pragma unroll
                for (int ww = 0; ww < 8; ww++) {
                    ar += pr[ww];
                    az += pr[PBS + ww];
                    an += pr[2 * PBS + ww];
                }
            }
            size_t xbase = ((size_t)t * NB + b) * H3;
            float xr = xpt[xbase + col];
            float xz = xpt[xbase + HD + col];
            float xn = xpt[xbase + 2 * HD + col];
            float hold = (t > 0) ? hbt[(size_t)(t - 1) * HBT_STRIDE + (size_t)b * HD + col] : 0.f;
            float r = fsig(xr + ar + bhh[col]);
            float z = fsig(xz + az + bhh[HD + col]);
            float n = ftanh(xn + r * (an + bhh[2 * HD + col]));
            hbt[(size_t)t * HBT_STRIDE + (size_t)b * HD + col] = (1.f - z) * n + z * hold;
        }

        gridbar();
    }
}

// =================================================================
// one-pass online-softmax reduce
// =================================================================
__global__ void att_reduce_flat(const float* __restrict__ S,
                                const float* __restrict__ H,
                                float* __restrict__ v)
{
    int j = blockIdx.x * 256 + threadIdx.x;
    float mx = -1e30f, se = 0.f, sv = 0.f;
#pragma unroll 4
    for (int u = 0; u < TT; u++) {
        float s = S[(size_t)u * NDB + j];
        float h = H[(size_t)u * HBT_STRIDE + j];
        float m2 = fmaxf(mx, s);
        float cor = __expf(mx - m2);
        float e = __expf(s - m2);
        se = se * cor + e;
        sv = sv * cor + e * h;
        mx = m2;
    }
    v[j] = __fdividef(sv, se);
}

// pool attention, row-major v -> catv[c][d]
__global__ void pool_att(const float* __restrict__ v, const float* __restrict__ pW,
                         const float* __restrict__ pb, float* __restrict__ catv)
{
    int c = blockIdx.x;
    int d = blockIdx.y * 256 + threadIdx.x;
    __shared__ float sW[400];
    __shared__ float sb[20];
    for (int i = threadIdx.x; i < 400; i += 256) sW[i] = pW[i];
    if (threadIdx.x < 20) sb[threadIdx.x] = pb[threadIdx.x];
    __syncthreads();

    float xv[20];
#pragma unroll
    for (int s = 0; s < 20; s++) xv[s] = v[(size_t)(c * 20 + s) * HD + d];
    float wv[20]; float mx = -1e30f;
#pragma unroll
    for (int u = 0; u < 20; u++) {
        float s = sb[u];
#pragma unroll
        for (int t2 = 0; t2 < 20; t2++) s += xv[t2] * sW[u * 20 + t2];
        wv[u] = s; mx = fmaxf(mx, s);
    }
    float se = 0.f, sv = 0.f;
#pragma unroll
    for (int u = 0; u < 20; u++) {
        float e = __expf(wv[u] - mx);
        se += e; sv += e * xv[u];
    }
    catv[(size_t)c * HD + d] = __fdividef(sv, se);
}

// two dots per node (row-major)
__global__ void dot2(const float* __restrict__ h, const float* __restrict__ a1,
                     const float* __restrict__ a2, float* __restrict__ o1,
                     float* __restrict__ o2)
{
    int n = blockIdx.x;
    __shared__ float s1[256], s2[256];
    float p1 = 0.f, p2 = 0.f;
    for (int k = threadIdx.x; k < HD; k += 256) {
        float hv = h[(size_t)n * HD + k];
        p1 += hv * a1[k]; p2 += hv * a2[k];
    }
    s1[threadIdx.x] = p1; s2[threadIdx.x] = p2;
    __syncthreads();
    for (int s = 128; s > 0; s >>= 1) {
        if (threadIdx.x < s) { s1[threadIdx.x] += s1[threadIdx.x + s]; s2[threadIdx.x] += s2[threadIdx.x + s]; }
        __syncthreads();
    }
    if (threadIdx.x == 0) { o1[n] = s1[0]; o2[n] = s2[0]; }
}

// GAT aggregation (complete cliques + self loops), row-major
__global__ void gat_agg(const float* __restrict__ h, const float* __restrict__ as,
                        const float* __restrict__ ad, const float* __restrict__ bias,
                        float* __restrict__ out, int group)
{
    int n = blockIdx.x;
    int base = (n / group) * group;
    __shared__ float alpha[32];
    if (threadIdx.x == 0) {
        float e[32]; float mx = -1e30f;
        for (int s = 0; s < group; s++) {
            float x = as[base + s] + ad[n];
            x = (x > 0.f) ? x : 0.2f * x;
            e[s] = x; mx = fmaxf(mx, x);
        }
        float se = 0.f;
        for (int s = 0; s < group; s++) { e[s] = __expf(e[s] - mx); se += e[s]; }
        for (int s = 0; s < group; s++) alpha[s] = __fdividef(e[s], se);
    }
    __syncthreads();
    for (int dd = threadIdx.x; dd < HD; dd += 256) {
        float acc = 0.f;
        for (int s = 0; s < group; s++)
            acc += alpha[s] * h[(size_t)(base + s) * HD + dd];
        out[(size_t)n * HD + dd] = acc + bias[dd];
    }
}

// fusion concat (row-major)
__global__ void build_fusion(const float* __restrict__ v, const float* __restrict__ catv,
                             const float* __restrict__ inner, float* __restrict__ fin)
{
    int idx = blockIdx.x * 256 + threadIdx.x;
    if (idx >= NB * H3) return;
    int n = idx / H3, k = idx - n * H3;
    float val;
    if (k < HD)            val = v[(size_t)n * HD + k];
    else if (k < 2 * HD)   val = catv[(size_t)(n / 20) * HD + (k - HD)];
    else                   val = inner[(size_t)n * HD + (k - 2 * HD)];
    fin[idx] = val;
}

// heads (row-major)
__global__ void heads(const float* __restrict__ f, const float* __restrict__ rw,
                      const float* __restrict__ rb, const float* __restrict__ cw,
                      const float* __restrict__ cb, float* __restrict__ out)
{
    int n = blockIdx.x;
    __shared__ float s1[256], s2[256];
    float p1 = 0.f, p2 = 0.f;
    for (int k = threadIdx.x; k < HD; k += 256) {
        float fv = f[(size_t)n * HD + k];
        p1 += fv * rw[k]; p2 += fv * cw[k];
    }
    s1[threadIdx.x] = p1; s2[threadIdx.x] = p2;
    __syncthreads();
    for (int s = 128; s > 0; s >>= 1) {
        if (threadIdx.x < s) { s1[threadIdx.x] += s1[threadIdx.x + s]; s2[threadIdx.x] += s2[threadIdx.x + s]; }
        __syncthreads();
    }
    if (threadIdx.x == 0) {
        out[n]      = s1[0] + rb[0];
        out[NB + n] = fsig(s2[0] + cb[0]);
    }
}

// =================================================================
extern "C" void kernel_launch(void* const* d_in, const int* in_sizes, int n_in,
                              void* d_out, int out_size)
{
    const float* weekly  = (const float*)d_in[0];
    const float* Wih     = (const float*)d_in[1];
    const float* Whh     = (const float*)d_in[2];
    const float* bih     = (const float*)d_in[3];
    const float* bhh     = (const float*)d_in[4];
    const float* encW    = (const float*)d_in[5];
    const float* encB    = (const float*)d_in[6];
    const float* poolW   = (const float*)d_in[7];
    const float* poolB   = (const float*)d_in[8];
    const float* innerW  = (const float*)d_in[9];
    const float* innerAs = (const float*)d_in[10];
    const float* innerAd = (const float*)d_in[11];
    const float* innerB  = (const float*)d_in[12];
    const float* catW    = (const float*)d_in[13];
    const float* catAs   = (const float*)d_in[14];
    const float* catAd   = (const float*)d_in[15];
    const float* catB    = (const float*)d_in[16];
    const float* fusW    = (const float*)d_in[17];
    const float* fusB    = (const float*)d_in[18];
    const float* regW    = (const float*)d_in[19];
    const float* regB    = (const float*)d_in[20];
    const float* clsW    = (const float*)d_in[21];
    const float* clsB    = (const float*)d_in[22];
    float* out = (float*)d_out;

    float *xp, *hbt, *v, *hp, *inner, *catv, *hp2, *catg, *as_, *ad_, *as2, *ad2, *fin, *f;
    cudaGetSymbolAddress((void**)&xp,    g_xp);
    cudaGetSymbolAddress((void**)&hbt,   g_hbt);
    cudaGetSymbolAddress((void**)&v,     g_v);
    cudaGetSymbolAddress((void**)&hp,    g_hp);
    cudaGetSymbolAddress((void**)&inner, g_inner);
    cudaGetSymbolAddress((void**)&catv,  g_catv);
    cudaGetSymbolAddress((void**)&hp2,   g_hp2);
    cudaGetSymbolAddress((void**)&catg,  g_cat);
    cudaGetSymbolAddress((void**)&as_,   g_as);
    cudaGetSymbolAddress((void**)&ad_,   g_ad);
    cudaGetSymbolAddress((void**)&as2,   g_as2);
    cudaGetSymbolAddress((void**)&ad2,   g_ad2);
    cudaGetSymbolAddress((void**)&fin,   g_fin);
    cudaGetSymbolAddress((void**)&f,     g_f);

    // 1) xp = weekly @ Wih^T + bih, written as [t][b][g] (remap=1)
    gemm_nt_tc<<<dim3(H3 / 128, (NB * TT) / 128), 256>>>(weekly, Wih, bih, xp, NB * TT, H3, IND, 0, 1);

    // 2) persistent tf32 mma GRU -> hbt [t][b][k] (b padded to 128)
    cudaFuncSetAttribute(gru_mma, cudaFuncAttributeMaxDynamicSharedMemorySize, GRU_SMEM);
    gru_mma<<<128, 256, GRU_SMEM>>>(xp, Whh, bhh, hbt);

    // 3) S(512 x 102400) = encW @ Hflat + encB[u]  (tf32; H row stride 131072)
    gemm_nn_tc<<<dim3(NDB / 128, TT / 128), 256>>>(encW, hbt, encB, xp, TT, NDB, TT, (size_t)HBT_STRIDE);

    // 4) v[j] = softmax-over-u(S) . H
    att_reduce_flat<<<NDB / 256, 256>>>(xp, hbt, v);

    // 5) inner GAT: hp = v @ innerW^T
    gemm_nt<<<dim3(HD / 128, 1), 256>>>(v, innerW, nullptr, hp, NB, HD, HD, 0);
    dot2<<<NB, 256>>>(hp, innerAs, innerAd, as_, ad_);
    gat_agg<<<NB, 256>>>(hp, as_, ad_, innerB, inner, 20);

    // 6) pool 20 stocks -> category vectors
    pool_att<<<dim3(5, HD / 256), 256>>>(v, poolW, poolB, catv);

    // 7) category GAT
    gemm_nt<<<dim3(HD / 128, 1), 256>>>(catv, catW, nullptr, hp2, 5, HD, HD, 0);
    dot2<<<5, 256>>>(hp2, catAs, catAd, as2, ad2);
    gat_agg<<<5, 256>>>(hp2, as2, ad2, catB, catg, 5);

    // 8) fusion
    build_fusion<<<(NB * H3 + 255) / 256, 256>>>(v, catg, inner, fin);
    gemm_nt<<<dim3(HD / 128, 1), 256>>>(fin, fusW, fusB, f, NB, HD, H3, 1);

    // 9) heads
    heads<<<NB, 256>>>(f, regW, regB, clsW, clsB, out);
}

// round 13
// speedup vs baseline: 9.5365x; 1.1138x over previous
#include <cuda_runtime.h>
#include <math.h>
#include <stdint.h>
#include <stddef.h>

typedef unsigned long long u64;

#define NB   100
#define TT   512
#define IND  256
#define HD   1024
#define H3   3072
#define NDB  (HD * NB)          // 102400
#define HBT_STRIDE (128 * 1024) // padded per-t stride (128 batch rows x 1024)
#define HFRAG_T 114688          // floats per t in fragment layout (8*7*16*32*4)

// ---------------- scratch ----------------
__device__ float g_xp [(size_t)TT * NB * H3];     // xp [t][b][g]; later reused as S [u][j]
__device__ float g_hbt[(size_t)TT * HBT_STRIDE];  // h states [t][b(pad128)][k] (normal layout)
__device__ float g_hfrag[(size_t)TT * HFRAG_T];   // h states in mma A-fragment layout
__device__ float g_v  [NB * HD];
__device__ float g_hp [NB * HD];
__device__ float g_inner[NB * HD];
__device__ float g_catv[5 * HD];
__device__ float g_hp2 [5 * HD];
__device__ float g_cat [5 * HD];
__device__ float g_as[NB];
__device__ float g_ad[NB];
__device__ float g_as2[8];
__device__ float g_ad2[8];
__device__ float g_fin[NB * H3];
__device__ float g_f  [NB * HD];
__device__ unsigned g_cnt;
__device__ unsigned g_gen;

// ---------------- helpers ----------------
__device__ __forceinline__ u64 bcast2(float x) {
    u64 r; unsigned u = __float_as_uint(x);
    asm("mov.b64 %0, {%1, %1};" : "=l"(r) : "r"(u));
    return r;
}
__device__ __forceinline__ void fma2(u64& d, u64 a, u64 b) {
    asm("fma.rn.f32x2 %0, %1, %2, %0;" : "+l"(d) : "l"(a), "l"(b));
}
__device__ __forceinline__ float2 unpk(u64 v) {
    unsigned lo, hi;
    asm("mov.b64 {%0, %1}, %2;" : "=r"(lo), "=r"(hi) : "l"(v));
    return make_float2(__uint_as_float(lo), __uint_as_float(hi));
}
__device__ __forceinline__ uint32_t f2tf32(float x) {
    uint32_t u;
    asm("cvt.rna.tf32.f32 %0, %1;" : "=r"(u) : "f"(x));
    return u;
}
__device__ __forceinline__ float fsig(float x) {
    return __fdividef(1.f, 1.f + __expf(-x));
}
__device__ __forceinline__ float ftanh(float x) {
    float ax = fabsf(x);
    float e = __expf(2.f * ax);
    float t = 1.f - __fdividef(2.f, e + 1.f);
    return copysignf(t, x);
}

// tf32 warp MMA: D(16x8) += A(16x8) * B(8x8)
__device__ __forceinline__ void mma_tf32(
    float& c0, float& c1, float& c2, float& c3,
    uint32_t a0, uint32_t a1, uint32_t a2, uint32_t a3,
    uint32_t b0, uint32_t b1)
{
    asm volatile(
        "mma.sync.aligned.m16n8k8.row.col.f32.tf32.tf32.f32 "
        "{%0,%1,%2,%3}, {%4,%5,%6,%7}, {%8,%9}, {%0,%1,%2,%3};"
        : "+f"(c0), "+f"(c1), "+f"(c2), "+f"(c3)
        : "r"(a0), "r"(a1), "r"(a2), "r"(a3), "r"(b0), "r"(b1));
}

// =================================================================
// tf32 tensor-core GEMM NT (remap: xp stored as [t][b][g])
// =================================================================
#define AST 36
__global__ __launch_bounds__(256) void gemm_nt_tc(
    const float* __restrict__ A, const float* __restrict__ B,
    const float* __restrict__ colbias, float* __restrict__ C,
    int M, int N, int K, int act, int remap)
{
    __shared__ uint32_t As[128 * AST];
    __shared__ uint32_t Bs[128 * AST];
    int tid = threadIdx.x, w = tid >> 5, lane = tid & 31;
    int gid = lane >> 2, tig = lane & 3;
    int wm = w >> 2, wn = w & 3;
    int row0 = blockIdx.y * 128, col0 = blockIdx.x * 128;

    float acc[4][4][4];
#pragma unroll
    for (int i = 0; i < 4; i++)
#pragma unroll
        for (int j = 0; j < 4; j++)
#pragma unroll
            for (int q = 0; q < 4; q++) acc[i][j][q] = 0.f;

    for (int k0 = 0; k0 < K; k0 += 32) {
#pragma unroll
        for (int q = 0; q < 4; q++) {
            int idx = tid + q * 256;
            int row = idx >> 3, k4 = (idx & 7) * 4;
            float4 v = *(const float4*)(A + (size_t)(row0 + row) * K + k0 + k4);
            uint32_t* d = &As[row * AST + k4];
            d[0] = f2tf32(v.x); d[1] = f2tf32(v.y); d[2] = f2tf32(v.z); d[3] = f2tf32(v.w);
        }
#pragma unroll
        for (int q = 0; q < 4; q++) {
            int idx = tid + q * 256;
            int row = idx >> 3, k4 = (idx & 7) * 4;
            float4 v = *(const float4*)(B + (size_t)(col0 + row) * K + k0 + k4);
            uint32_t* d = &Bs[row * AST + k4];
            d[0] = f2tf32(v.x); d[1] = f2tf32(v.y); d[2] = f2tf32(v.z); d[3] = f2tf32(v.w);
        }
        __syncthreads();
#pragma unroll
        for (int kq = 0; kq < 4; kq++) {
            int kb = kq * 8;
            uint32_t af[4][4];
#pragma unroll
            for (int i = 0; i < 4; i++) {
                int base = (wm * 64 + i * 16 + gid) * AST + kb + tig;
                af[i][0] = As[base];
                af[i][1] = As[base + 8 * AST];
                af[i][2] = As[base + 4];
                af[i][3] = As[base + 8 * AST + 4];
            }
#pragma unroll
            for (int j = 0; j < 4; j++) {
                int bbase = (wn * 32 + j * 8 + gid) * AST + kb + tig;
                uint32_t b0 = Bs[bbase], b1 = Bs[bbase + 4];
#pragma unroll
                for (int i = 0; i < 4; i++)
                    mma_tf32(acc[i][j][0], acc[i][j][1], acc[i][j][2], acc[i][j][3],
                             af[i][0], af[i][1], af[i][2], af[i][3], b0, b1);
            }
        }
        __syncthreads();
    }
#pragma unroll
    for (int i = 0; i < 4; i++) {
#pragma unroll
        for (int j = 0; j < 4; j++) {
            int r = row0 + wm * 64 + i * 16 + gid;
            int r2 = r + 8;
            int cix = col0 + wn * 32 + j * 8 + tig * 2;
            float v0 = acc[i][j][0], v1 = acc[i][j][1];
            float v2 = acc[i][j][2], v3 = acc[i][j][3];
            if (colbias) {
                float bb0 = colbias[cix], bb1 = colbias[cix + 1];
                v0 += bb0; v1 += bb1; v2 += bb0; v3 += bb1;
            }
            if (act == 1) {
                v0 = fmaxf(v0, 0.f); v1 = fmaxf(v1, 0.f);
                v2 = fmaxf(v2, 0.f); v3 = fmaxf(v3, 0.f);
            }
            size_t ro = (size_t)r, ro2 = (size_t)r2;
            if (remap) {
                ro  = (size_t)(r  % TT) * NB + (r  / TT);
                ro2 = (size_t)(r2 % TT) * NB + (r2 / TT);
            }
            C[ro  * N + cix]     = v0;
            C[ro  * N + cix + 1] = v1;
            C[ro2 * N + cix]     = v2;
            C[ro2 * N + cix + 1] = v3;
        }
    }
}

// =================================================================
// tf32 tensor-core GEMM NN: C[M,N] = A[M,K] @ B[K(ldB),N] + rowbias[M]
// =================================================================
#define BSTN 132
__global__ __launch_bounds__(256) void gemm_nn_tc(
    const float* __restrict__ A, const float* __restrict__ B,
    const float* __restrict__ rowbias, float* __restrict__ C,
    int M, int N, int K, size_t ldB)
{
    __shared__ uint32_t As[128 * AST];
    __shared__ uint32_t Bs[32 * BSTN];
    int tid = threadIdx.x, w = tid >> 5, lane = tid & 31;
    int gid = lane >> 2, tig = lane & 3;
    int wm = w >> 2, wn = w & 3;
    int row0 = blockIdx.y * 128, col0 = blockIdx.x * 128;

    float acc[4][4][4];
#pragma unroll
    for (int i = 0; i < 4; i++)
#pragma unroll
        for (int j = 0; j < 4; j++)
#pragma unroll
            for (int q = 0; q < 4; q++) acc[i][j][q] = 0.f;

    for (int k0 = 0; k0 < K; k0 += 32) {
#pragma unroll
        for (int q = 0; q < 4; q++) {
            int idx = tid + q * 256;
            int row = idx >> 3, k4 = (idx & 7) * 4;
            float4 v = *(const float4*)(A + (size_t)(row0 + row) * K + k0 + k4);
            uint32_t* d = &As[row * AST + k4];
            d[0] = f2tf32(v.x); d[1] = f2tf32(v.y); d[2] = f2tf32(v.z); d[3] = f2tf32(v.w);
        }
#pragma unroll
        for (int q = 0; q < 4; q++) {
            int idx = tid + q * 256;
            int k = idx >> 5, n4 = (idx & 31) * 4;
            float4 v = *(const float4*)(B + (size_t)(k0 + k) * ldB + col0 + n4);
            uint32_t* d = &Bs[k * BSTN + n4];
            d[0] = f2tf32(v.x); d[1] = f2tf32(v.y); d[2] = f2tf32(v.z); d[3] = f2tf32(v.w);
        }
        __syncthreads();
#pragma unroll
        for (int kq = 0; kq < 4; kq++) {
            int kb = kq * 8;
            uint32_t af[4][4];
#pragma unroll
            for (int i = 0; i < 4; i++) {
                int base = (wm * 64 + i * 16 + gid) * AST + kb + tig;
                af[i][0] = As[base];
                af[i][1] = As[base + 8 * AST];
                af[i][2] = As[base + 4];
                af[i][3] = As[base + 8 * AST + 4];
            }
#pragma unroll
            for (int j = 0; j < 4; j++) {
                int ncol = wn * 32 + j * 8 + gid;
                uint32_t b0 = Bs[(kb + tig) * BSTN + ncol];
                uint32_t b1 = Bs[(kb + tig + 4) * BSTN + ncol];
#pragma unroll
                for (int i = 0; i < 4; i++)
                    mma_tf32(acc[i][j][0], acc[i][j][1], acc[i][j][2], acc[i][j][3],
                             af[i][0], af[i][1], af[i][2], af[i][3], b0, b1);
            }
        }
        __syncthreads();
    }
#pragma unroll
    for (int i = 0; i < 4; i++) {
#pragma unroll
        for (int j = 0; j < 4; j++) {
            int r = row0 + wm * 64 + i * 16 + gid;
            int cix = col0 + wn * 32 + j * 8 + tig * 2;
            float rb0 = rowbias ? rowbias[r] : 0.f;
            float rb8 = rowbias ? rowbias[r + 8] : 0.f;
            C[(size_t)r * N + cix]           = acc[i][j][0] + rb0;
            C[(size_t)r * N + cix + 1]       = acc[i][j][1] + rb0;
            C[(size_t)(r + 8) * N + cix]     = acc[i][j][2] + rb8;
            C[(size_t)(r + 8) * N + cix + 1] = acc[i][j][3] + rb8;
        }
    }
}

// =================================================================
// SIMT SGEMM NT (small GEMMs)
// =================================================================
__global__ __launch_bounds__(256) void gemm_nt(
    const float* __restrict__ A, const float* __restrict__ B,
    const float* __restrict__ colbias, float* __restrict__ C,
    int M, int N, int K, int act)
{
    __shared__ float As[16][128];
    __shared__ float Bs[16][128];
    int tid = threadIdx.x;
    int tx = tid & 15, ty = tid >> 4;
    int row0 = blockIdx.y * 128, col0 = blockIdx.x * 128;

    u64 acc[8][4];
#pragma unroll
    for (int i = 0; i < 8; i++)
#pragma unroll
        for (int j = 0; j < 4; j++) acc[i][j] = 0ull;

    int lr = tid >> 2, lc = tid & 3;
    for (int k0 = 0; k0 < K; k0 += 16) {
#pragma unroll
        for (int p = 0; p < 2; p++) {
            int r = lr + p * 64, gr = row0 + r;
            float4 v = make_float4(0.f, 0.f, 0.f, 0.f);
            if (gr < M) v = *(const float4*)(A + (size_t)gr * K + k0 + lc * 4);
            As[lc*4+0][r] = v.x; As[lc*4+1][r] = v.y; As[lc*4+2][r] = v.z; As[lc*4+3][r] = v.w;
        }
#pragma unroll
        for (int p = 0; p < 2; p++) {
            int r = lr + p * 64, gc = col0 + r;
            float4 v = make_float4(0.f, 0.f, 0.f, 0.f);
            if (gc < N) v = *(const float4*)(B + (size_t)gc * K + k0 + lc * 4);
            Bs[lc*4+0][r] = v.x; Bs[lc*4+1][r] = v.y; Bs[lc*4+2][r] = v.z; Bs[lc*4+3][r] = v.w;
        }
        __syncthreads();
#pragma unroll
        for (int kk = 0; kk < 16; kk++) {
            float a[8];
            *(float4*)&a[0] = *(const float4*)&As[kk][ty * 8];
            *(float4*)&a[4] = *(const float4*)&As[kk][ty * 8 + 4];
            u64 b4[4];
#pragma unroll
            for (int j = 0; j < 4; j++) b4[j] = *(const u64*)&Bs[kk][tx * 8 + 2 * j];
#pragma unroll
            for (int i = 0; i < 8; i++) {
                u64 ai = bcast2(a[i]);
#pragma unroll
                for (int j = 0; j < 4; j++) fma2(acc[i][j], ai, b4[j]);
            }
        }
        __syncthreads();
    }
#pragma unroll
    for (int i = 0; i < 8; i++) {
        int gm = row0 + ty * 8 + i;
        if (gm >= M) continue;
#pragma unroll
        for (int j = 0; j < 4; j++) {
            float2 c2 = unpk(acc[i][j]);
            int gn = col0 + tx * 8 + 2 * j;
            float v0 = c2.x, v1 = c2.y;
            if (colbias) { v0 += colbias[gn]; v1 += colbias[gn + 1]; }
            if (act == 1) { v0 = fmaxf(v0, 0.f); v1 = fmaxf(v1, 0.f); }
            if (gn < N)     C[(size_t)gm * N + gn]     = v0;
            if (gn + 1 < N) C[(size_t)gm * N + gn + 1] = v1;
        }
    }
}

// =================================================================
// Persistent GRU v13: tf32 mma, A operands read DIRECTLY from
// fragment-layout hfrag (written by previous step's epilogue).
// 128 blocks x 256 threads (8 warps). Block owns 8 hidden cols.
// hfrag slot (per t): (((w*7+mt)*16+kt)*32 + lane) float4, components
// (a0,a1,a2,a3) = rows (gidq, gidq+8) x k (base, base+4).
// =================================================================
#define PBS 9
#define PBUF_F (112 * 24 * PBS)
#define GRU_SMEM (PBUF_F * 4)

__device__ __forceinline__ void gridbar()
{
    __threadfence();
    __syncthreads();
    if (threadIdx.x == 0) {
        volatile unsigned* vg = &g_gen;
        unsigned target = *vg + 1;
        if (atomicAdd(&g_cnt, 1) == gridDim.x - 1) {
            g_cnt = 0;
            __threadfence();
            atomicAdd(&g_gen, 1);
        } else {
            while ((int)(*vg - target) < 0) { }
        }
        __threadfence();
    }
    __syncthreads();
}

__global__ __launch_bounds__(256, 1) void gru_mma(
    const float* __restrict__ xpt, const float* __restrict__ Whh,
    const float* __restrict__ bhh, float* __restrict__ hbt,
    float* __restrict__ hfrag)
{
    extern __shared__ float pbuf[];
    int tid  = threadIdx.x;
    int w    = tid >> 5;
    int lane = tid & 31;
    int gidq = lane >> 2;
    int tig  = lane & 3;
    int col0 = blockIdx.x * 8;
    int k0   = w * 128;

    // register-resident Whh fragments
    uint32_t bf[16][3][2];
#pragma unroll
    for (int kt = 0; kt < 16; kt++) {
#pragma unroll
        for (int j = 0; j < 3; j++) {
            int n = j * 8 + gidq;
            int c = n / 3, g = n % 3;
            const float* wrow = Whh + ((size_t)g * HD + col0 + c) * HD;
            int kk = k0 + kt * 8 + tig;
            bf[kt][j][0] = f2tf32(wrow[kk]);
            bf[kt][j][1] = f2tf32(wrow[kk + 4]);
        }
    }

    for (int t = 0; t < TT; t++) {
        if (t > 0) {
            // A fragments straight from hfrag[t-1]
            const float4* fb = (const float4*)(hfrag + (size_t)(t - 1) * HFRAG_T)
                               + (size_t)w * 112 * 32 + lane;
#pragma unroll 1
            for (int mt = 0; mt < 7; mt++) {
                float c0[3], c1[3], c2[3], c3[3];
#pragma unroll
                for (int j = 0; j < 3; j++) { c0[j] = 0.f; c1[j] = 0.f; c2[j] = 0.f; c3[j] = 0.f; }

                const float4* fm = fb + (size_t)(mt * 16) * 32;
#pragma unroll
                for (int kt = 0; kt < 16; kt++) {
                    float4 a = fm[(size_t)kt * 32];
                    uint32_t a0 = __float_as_uint(a.x);
                    uint32_t a1 = __float_as_uint(a.y);
                    uint32_t a2 = __float_as_uint(a.z);
                    uint32_t a3 = __float_as_uint(a.w);
#pragma unroll
                    for (int j = 0; j < 3; j++)
                        mma_tf32(c0[j], c1[j], c2[j], c3[j],
                                 a0, a1, a2, a3, bf[kt][j][0], bf[kt][j][1]);
                }

                int r0 = mt * 16 + gidq;
#pragma unroll
                for (int j = 0; j < 3; j++) {
                    int n0 = j * 8 + tig * 2;
                    pbuf[((size_t)r0 * 24 + n0) * PBS + w]           = c0[j];
                    pbuf[((size_t)r0 * 24 + n0 + 1) * PBS + w]       = c1[j];
                    pbuf[((size_t)(r0 + 8) * 24 + n0) * PBS + w]     = c2[j];
                    pbuf[((size_t)(r0 + 8) * 24 + n0 + 1) * PBS + w] = c3[j];
                }
            }
        }
        __syncthreads();

        // fused reduction + gate epilogue
        float* hfrag_t = hfrag + (size_t)t * HFRAG_T;
        for (int idx = tid; idx < NB * 8; idx += 256) {
            int b = idx >> 3, c = idx & 7;
            int col = col0 + c;
            float ar = 0.f, az = 0.f, an = 0.f;
            if (t > 0) {
                const float* pr = pbuf + ((size_t)b * 24 + c * 3) * PBS;
#pragma unroll
                for (int ww = 0; ww < 8; ww++) {
                    ar += pr[ww];
                    az += pr[PBS + ww];
                    an += pr[2 * PBS + ww];
                }
            }
            size_t xbase = ((size_t)t * NB + b) * H3;
            float xr = xpt[xbase + col];
            float xz = xpt[xbase + HD + col];
            float xn = xpt[xbase + 2 * HD + col];
            float hold = (t > 0) ? hbt[(size_t)(t - 1) * HBT_STRIDE + (size_t)b * HD + col] : 0.f;
            float r = fsig(xr + ar + bhh[col]);
            float z = fsig(xz + az + bhh[HD + col]);
            float n = ftanh(xn + r * (an + bhh[2 * HD + col]));
            float hnew = (1.f - z) * n + z * hold;

            hbt[(size_t)t * HBT_STRIDE + (size_t)b * HD + col] = hnew;

            // fragment-layout write
            int fw   = col >> 7;
            int fmt  = b >> 4;
            int fkt  = (col >> 3) & 15;
            int ftig = col & 3;
            int fah  = (col >> 2) & 1;
            int fgid = b & 7;
            int frh  = (b >> 3) & 1;
            size_t slot = (((size_t)fw * 7 + fmt) * 16 + fkt) * 32 + fgid * 4 + ftig;
            hfrag_t[slot * 4 + frh + 2 * fah] = hnew;
        }

        gridbar();
    }
}

// =================================================================
// one-pass online-softmax reduce
// =================================================================
__global__ void att_reduce_flat(const float* __restrict__ S,
                                const float* __restrict__ H,
                                float* __restrict__ v)
{
    int j = blockIdx.x * 256 + threadIdx.x;
    float mx = -1e30f, se = 0.f, sv = 0.f;
#pragma unroll 4
    for (int u = 0; u < TT; u++) {
        float s = S[(size_t)u * NDB + j];
        float h = H[(size_t)u * HBT_STRIDE + j];
        float m2 = fmaxf(mx, s);
        float cor = __expf(mx - m2);
        float e = __expf(s - m2);
        se = se * cor + e;
        sv = sv * cor + e * h;
        mx = m2;
    }
    v[j] = __fdividef(sv, se);
}

// pool attention, row-major v -> catv[c][d]
__global__ void pool_att(const float* __restrict__ v, const float* __restrict__ pW,
                         const float* __restrict__ pb, float* __restrict__ catv)
{
    int c = blockIdx.x;
    int d = blockIdx.y * 256 + threadIdx.x;
    __shared__ float sW[400];
    __shared__ float sb[20];
    for (int i = threadIdx.x; i < 400; i += 256) sW[i] = pW[i];
    if (threadIdx.x < 20) sb[threadIdx.x] = pb[threadIdx.x];
    __syncthreads();

    float xv[20];
#pragma unroll
    for (int s = 0; s < 20; s++) xv[s] = v[(size_t)(c * 20 + s) * HD + d];
    float wv[20]; float mx = -1e30f;
#pragma unroll
    for (int u = 0; u < 20; u++) {
        float s = sb[u];
#pragma unroll
        for (int t2 = 0; t2 < 20; t2++) s += xv[t2] * sW[u * 20 + t2];
        wv[u] = s; mx = fmaxf(mx, s);
    }
    float se = 0.f, sv = 0.f;
#pragma unroll
    for (int u = 0; u < 20; u++) {
        float e = __expf(wv[u] - mx);
        se += e; sv += e * xv[u];
    }
    catv[(size_t)c * HD + d] = __fdividef(sv, se);
}

// two dots per node (row-major)
__global__ void dot2(const float* __restrict__ h, const float* __restrict__ a1,
                     const float* __restrict__ a2, float* __restrict__ o1,
                     float* __restrict__ o2)
{
    int n = blockIdx.x;
    __shared__ float s1[256], s2[256];
    float p1 = 0.f, p2 = 0.f;
    for (int k = threadIdx.x; k < HD; k += 256) {
        float hv = h[(size_t)n * HD + k];
        p1 += hv * a1[k]; p2 += hv * a2[k];
    }
    s1[threadIdx.x] = p1; s2[threadIdx.x] = p2;
    __syncthreads();
    for (int s = 128; s > 0; s >>= 1) {
        if (threadIdx.x < s) { s1[threadIdx.x] += s1[threadIdx.x + s]; s2[threadIdx.x] += s2[threadIdx.x + s]; }
        __syncthreads();
    }
    if (threadIdx.x == 0) { o1[n] = s1[0]; o2[n] = s2[0]; }
}

// GAT aggregation (complete cliques + self loops), row-major
__global__ void gat_agg(const float* __restrict__ h, const float* __restrict__ as,
                        const float* __restrict__ ad, const float* __restrict__ bias,
                        float* __restrict__ out, int group)
{
    int n = blockIdx.x;
    int base = (n / group) * group;
    __shared__ float alpha[32];
    if (threadIdx.x == 0) {
        float e[32]; float mx = -1e30f;
        for (int s = 0; s < group; s++) {
            float x = as[base + s] + ad[n];
            x = (x > 0.f) ? x : 0.2f * x;
            e[s] = x; mx = fmaxf(mx, x);
        }
        float se = 0.f;
        for (int s = 0; s < group; s++) { e[s] = __expf(e[s] - mx); se += e[s]; }
        for (int s = 0; s < group; s++) alpha[s] = __fdividef(e[s], se);
    }
    __syncthreads();
    for (int dd = threadIdx.x; dd < HD; dd += 256) {
        float acc = 0.f;
        for (int s = 0; s < group; s++)
            acc += alpha[s] * h[(size_t)(base + s) * HD + dd];
        out[(size_t)n * HD + dd] = acc + bias[dd];
    }
}

// fusion concat (row-major)
__global__ void build_fusion(const float* __restrict__ v, const float* __restrict__ catv,
                             const float* __restrict__ inner, float* __restrict__ fin)
{
    int idx = blockIdx.x * 256 + threadIdx.x;
    if (idx >= NB * H3) return;
    int n = idx / H3, k = idx - n * H3;
    float val;
    if (k < HD)            val = v[(size_t)n * HD + k];
    else if (k < 2 * HD)   val = catv[(size_t)(n / 20) * HD + (k - HD)];
    else                   val = inner[(size_t)n * HD + (k - 2 * HD)];
    fin[idx] = val;
}

// heads (row-major)
__global__ void heads(const float* __restrict__ f, const float* __restrict__ rw,
                      const float* __restrict__ rb, const float* __restrict__ cw,
                      const float* __restrict__ cb, float* __restrict__ out)
{
    int n = blockIdx.x;
    __shared__ float s1[256], s2[256];
    float p1 = 0.f, p2 = 0.f;
    for (int k = threadIdx.x; k < HD; k += 256) {
        float fv = f[(size_t)n * HD + k];
        p1 += fv * rw[k]; p2 += fv * cw[k];
    }
    s1[threadIdx.x] = p1; s2[threadIdx.x] = p2;
    __syncthreads();
    for (int s = 128; s > 0; s >>= 1) {
        if (threadIdx.x < s) { s1[threadIdx.x] += s1[threadIdx.x + s]; s2[threadIdx.x] += s2[threadIdx.x + s]; }
        __syncthreads();
    }
    if (threadIdx.x == 0) {
        out[n]      = s1[0] + rb[0];
        out[NB + n] = fsig(s2[0] + cb[0]);
    }
}

// =================================================================
extern "C" void kernel_launch(void* const* d_in, const int* in_sizes, int n_in,
                              void* d_out, int out_size)
{
    const float* weekly  = (const float*)d_in[0];
    const float* Wih     = (const float*)d_in[1];
    const float* Whh     = (const float*)d_in[2];
    const float* bih     = (const float*)d_in[3];
    const float* bhh     = (const float*)d_in[4];
    const float* encW    = (const float*)d_in[5];
    const float* encB    = (const float*)d_in[6];
    const float* poolW   = (const float*)d_in[7];
    const float* poolB   = (const float*)d_in[8];
    const float* innerW  = (const float*)d_in[9];
    const float* innerAs = (const float*)d_in[10];
    const float* innerAd = (const float*)d_in[11];
    const float* innerB  = (const float*)d_in[12];
    const float* catW    = (const float*)d_in[13];
    const float* catAs   = (const float*)d_in[14];
    const float* catAd   = (const float*)d_in[15];
    const float* catB    = (const float*)d_in[16];
    const float* fusW    = (const float*)d_in[17];
    const float* fusB    = (const float*)d_in[18];
    const float* regW    = (const float*)d_in[19];
    const float* regB    = (const float*)d_in[20];
    const float* clsW    = (const float*)d_in[21];
    const float* clsB    = (const float*)d_in[22];
    float* out = (float*)d_out;

    float *xp, *hbt, *hfrag, *v, *hp, *inner, *catv, *hp2, *catg, *as_, *ad_, *as2, *ad2, *fin, *f;
    cudaGetSymbolAddress((void**)&xp,    g_xp);
    cudaGetSymbolAddress((void**)&hbt,   g_hbt);
    cudaGetSymbolAddress((void**)&hfrag, g_hfrag);
    cudaGetSymbolAddress((void**)&v,     g_v);
    cudaGetSymbolAddress((void**)&hp,    g_hp);
    cudaGetSymbolAddress((void**)&inner, g_inner);
    cudaGetSymbolAddress((void**)&catv,  g_catv);
    cudaGetSymbolAddress((void**)&hp2,   g_hp2);
    cudaGetSymbolAddress((void**)&catg,  g_cat);
    cudaGetSymbolAddress((void**)&as_,   g_as);
    cudaGetSymbolAddress((void**)&ad_,   g_ad);
    cudaGetSymbolAddress((void**)&as2,   g_as2);
    cudaGetSymbolAddress((void**)&ad2,   g_ad2);
    cudaGetSymbolAddress((void**)&fin,   g_fin);
    cudaGetSymbolAddress((void**)&f,     g_f);

    // 1) xp = weekly @ Wih^T + bih, written as [t][b][g] (remap=1)
    gemm_nt_tc<<<dim3(H3 / 128, (NB * TT) / 128), 256>>>(weekly, Wih, bih, xp, NB * TT, H3, IND, 0, 1);

    // 2) persistent tf32 mma GRU (fragment-layout h feed)
    cudaFuncSetAttribute(gru_mma, cudaFuncAttributeMaxDynamicSharedMemorySize, GRU_SMEM);
    gru_mma<<<128, 256, GRU_SMEM>>>(xp, Whh, bhh, hbt, hfrag);

    // 3) S(512 x 102400) = encW @ Hflat + encB[u]
    gemm_nn_tc<<<dim3(NDB / 128, TT / 128), 256>>>(encW, hbt, encB, xp, TT, NDB, TT, (size_t)HBT_STRIDE);

    // 4) v[j] = softmax-over-u(S) . H
    att_reduce_flat<<<NDB / 256, 256>>>(xp, hbt, v);

    // 5) inner GAT: hp = v @ innerW^T
    gemm_nt<<<dim3(HD / 128, 1), 256>>>(v, innerW, nullptr, hp, NB, HD, HD, 0);
    dot2<<<NB, 256>>>(hp, innerAs, innerAd, as_, ad_);
    gat_agg<<<NB, 256>>>(hp, as_, ad_, innerB, inner, 20);

    // 6) pool 20 stocks -> category vectors
    pool_att<<<dim3(5, HD / 256), 256>>>(v, poolW, poolB, catv);

    // 7) category GAT
    gemm_nt<<<dim3(HD / 128, 1), 256>>>(catv, catW, nullptr, hp2, 5, HD, HD, 0);
    dot2<<<5, 256>>>(hp2, catAs, catAd, as2, ad2);
    gat_agg<<<5, 256>>>(hp2, as2, ad2, catB, catg, 5);

    // 8) fusion
    build_fusion<<<(NB * H3 + 255) / 256, 256>>>(v, catg, inner, fin);
    gemm_nt<<<dim3(HD / 128, 1), 256>>>(fin, fusW, fusB, f, NB, HD, H3, 1);

    // 9) heads
    heads<<<NB, 256>>>(f, regW, regB, clsW, clsB, out);
}

// round 14
// speedup vs baseline: 11.7185x; 1.2288x over previous
#include <cuda_runtime.h>
#include <cuda_fp16.h>
#include <math.h>
#include <stdint.h>
#include <stddef.h>

typedef unsigned long long u64;

#define NB   100
#define TT   512
#define IND  256
#define HD   1024
#define H3   3072
#define NDB  (HD * NB)          // 102400
#define HBT_STRIDE (128 * 1024) // padded per-t stride (128 batch rows x 1024)
#define HFRAGU_T 28672          // uint32 per t in fp16 fragment layout (8*7*8*32*4)

// ---------------- scratch ----------------
__device__ float    g_xp [(size_t)TT * NB * H3];    // xp [t][b][g]; later reused as S [u][j]
__device__ float    g_hbt[(size_t)TT * HBT_STRIDE]; // h states [t][b(pad128)][k] fp32
__device__ unsigned g_hfrag[(size_t)TT * HFRAGU_T]; // h states, fp16 mma A-fragment layout
__device__ float g_v  [NB * HD];
__device__ float g_hp [NB * HD];
__device__ float g_inner[NB * HD];
__device__ float g_catv[5 * HD];
__device__ float g_hp2 [5 * HD];
__device__ float g_cat [5 * HD];
__device__ float g_as[NB];
__device__ float g_ad[NB];
__device__ float g_as2[8];
__device__ float g_ad2[8];
__device__ float g_fin[NB * H3];
__device__ float g_f  [NB * HD];
__device__ unsigned g_cnt;
__device__ unsigned g_gen;

// ---------------- helpers ----------------
__device__ __forceinline__ u64 bcast2(float x) {
    u64 r; unsigned u = __float_as_uint(x);
    asm("mov.b64 %0, {%1, %1};" : "=l"(r) : "r"(u));
    return r;
}
__device__ __forceinline__ void fma2(u64& d, u64 a, u64 b) {
    asm("fma.rn.f32x2 %0, %1, %2, %0;" : "+l"(d) : "l"(a), "l"(b));
}
__device__ __forceinline__ float2 unpk(u64 v) {
    unsigned lo, hi;
    asm("mov.b64 {%0, %1}, %2;" : "=r"(lo), "=r"(hi) : "l"(v));
    return make_float2(__uint_as_float(lo), __uint_as_float(hi));
}
__device__ __forceinline__ uint32_t f2tf32(float x) {
    uint32_t u;
    asm("cvt.rna.tf32.f32 %0, %1;" : "=r"(u) : "f"(x));
    return u;
}
__device__ __forceinline__ uint32_t packh2(float lo, float hi) {
    __half2 h = __floats2half2_rn(lo, hi);
    return *(uint32_t*)&h;
}
__device__ __forceinline__ float fsig(float x) {
    return __fdividef(1.f, 1.f + __expf(-x));
}
__device__ __forceinline__ float ftanh(float x) {
    float ax = fabsf(x);
    float e = __expf(2.f * ax);
    float t = 1.f - __fdividef(2.f, e + 1.f);
    return copysignf(t, x);
}

// tf32 warp MMA: D(16x8) += A(16x8) * B(8x8)
__device__ __forceinline__ void mma_tf32(
    float& c0, float& c1, float& c2, float& c3,
    uint32_t a0, uint32_t a1, uint32_t a2, uint32_t a3,
    uint32_t b0, uint32_t b1)
{
    asm volatile(
        "mma.sync.aligned.m16n8k8.row.col.f32.tf32.tf32.f32 "
        "{%0,%1,%2,%3}, {%4,%5,%6,%7}, {%8,%9}, {%0,%1,%2,%3};"
        : "+f"(c0), "+f"(c1), "+f"(c2), "+f"(c3)
        : "r"(a0), "r"(a1), "r"(a2), "r"(a3), "r"(b0), "r"(b1));
}
// fp16 warp MMA: D(16x8) += A(16x16) * B(16x8), fp32 accumulate
__device__ __forceinline__ void mma_f16(
    float& c0, float& c1, float& c2, float& c3,
    uint32_t a0, uint32_t a1, uint32_t a2, uint32_t a3,
    uint32_t b0, uint32_t b1)
{
    asm volatile(
        "mma.sync.aligned.m16n8k16.row.col.f32.f16.f16.f32 "
        "{%0,%1,%2,%3}, {%4,%5,%6,%7}, {%8,%9}, {%0,%1,%2,%3};"
        : "+f"(c0), "+f"(c1), "+f"(c2), "+f"(c3)
        : "r"(a0), "r"(a1), "r"(a2), "r"(a3), "r"(b0), "r"(b1));
}

// =================================================================
// tf32 tensor-core GEMM NT (remap: xp stored as [t][b][g])
// =================================================================
#define AST 36
__global__ __launch_bounds__(256) void gemm_nt_tc(
    const float* __restrict__ A, const float* __restrict__ B,
    const float* __restrict__ colbias, float* __restrict__ C,
    int M, int N, int K, int act, int remap)
{
    __shared__ uint32_t As[128 * AST];
    __shared__ uint32_t Bs[128 * AST];
    int tid = threadIdx.x, w = tid >> 5, lane = tid & 31;
    int gid = lane >> 2, tig = lane & 3;
    int wm = w >> 2, wn = w & 3;
    int row0 = blockIdx.y * 128, col0 = blockIdx.x * 128;

    float acc[4][4][4];
#pragma unroll
    for (int i = 0; i < 4; i++)
#pragma unroll
        for (int j = 0; j < 4; j++)
#pragma unroll
            for (int q = 0; q < 4; q++) acc[i][j][q] = 0.f;

    for (int k0 = 0; k0 < K; k0 += 32) {
#pragma unroll
        for (int q = 0; q < 4; q++) {
            int idx = tid + q * 256;
            int row = idx >> 3, k4 = (idx & 7) * 4;
            float4 v = *(const float4*)(A + (size_t)(row0 + row) * K + k0 + k4);
            uint32_t* d = &As[row * AST + k4];
            d[0] = f2tf32(v.x); d[1] = f2tf32(v.y); d[2] = f2tf32(v.z); d[3] = f2tf32(v.w);
        }
#pragma unroll
        for (int q = 0; q < 4; q++) {
            int idx = tid + q * 256;
            int row = idx >> 3, k4 = (idx & 7) * 4;
            float4 v = *(const float4*)(B + (size_t)(col0 + row) * K + k0 + k4);
            uint32_t* d = &Bs[row * AST + k4];
            d[0] = f2tf32(v.x); d[1] = f2tf32(v.y); d[2] = f2tf32(v.z); d[3] = f2tf32(v.w);
        }
        __syncthreads();
#pragma unroll
        for (int kq = 0; kq < 4; kq++) {
            int kb = kq * 8;
            uint32_t af[4][4];
#pragma unroll
            for (int i = 0; i < 4; i++) {
                int base = (wm * 64 + i * 16 + gid) * AST + kb + tig;
                af[i][0] = As[base];
                af[i][1] = As[base + 8 * AST];
                af[i][2] = As[base + 4];
                af[i][3] = As[base + 8 * AST + 4];
            }
#pragma unroll
            for (int j = 0; j < 4; j++) {
                int bbase = (wn * 32 + j * 8 + gid) * AST + kb + tig;
                uint32_t b0 = Bs[bbase], b1 = Bs[bbase + 4];
#pragma unroll
                for (int i = 0; i < 4; i++)
                    mma_tf32(acc[i][j][0], acc[i][j][1], acc[i][j][2], acc[i][j][3],
                             af[i][0], af[i][1], af[i][2], af[i][3], b0, b1);
            }
        }
        __syncthreads();
    }
#pragma unroll
    for (int i = 0; i < 4; i++) {
#pragma unroll
        for (int j = 0; j < 4; j++) {
            int r = row0 + wm * 64 + i * 16 + gid;
            int r2 = r + 8;
            int cix = col0 + wn * 32 + j * 8 + tig * 2;
            float v0 = acc[i][j][0], v1 = acc[i][j][1];
            float v2 = acc[i][j][2], v3 = acc[i][j][3];
            if (colbias) {
                float bb0 = colbias[cix], bb1 = colbias[cix + 1];
                v0 += bb0; v1 += bb1; v2 += bb0; v3 += bb1;
            }
            if (act == 1) {
                v0 = fmaxf(v0, 0.f); v1 = fmaxf(v1, 0.f);
                v2 = fmaxf(v2, 0.f); v3 = fmaxf(v3, 0.f);
            }
            size_t ro = (size_t)r, ro2 = (size_t)r2;
            if (remap) {
                ro  = (size_t)(r  % TT) * NB + (r  / TT);
                ro2 = (size_t)(r2 % TT) * NB + (r2 / TT);
            }
            C[ro  * N + cix]     = v0;
            C[ro  * N + cix + 1] = v1;
            C[ro2 * N + cix]     = v2;
            C[ro2 * N + cix + 1] = v3;
        }
    }
}

// =================================================================
// tf32 tensor-core GEMM NN: C[M,N] = A[M,K] @ B[K(ldB),N] + rowbias[M]
// =================================================================
#define BSTN 132
__global__ __launch_bounds__(256) void gemm_nn_tc(
    const float* __restrict__ A, const float* __restrict__ B,
    const float* __restrict__ rowbias, float* __restrict__ C,
    int M, int N, int K, size_t ldB)
{
    __shared__ uint32_t As[128 * AST];
    __shared__ uint32_t Bs[32 * BSTN];
    int tid = threadIdx.x, w = tid >> 5, lane = tid & 31;
    int gid = lane >> 2, tig = lane & 3;
    int wm = w >> 2, wn = w & 3;
    int row0 = blockIdx.y * 128, col0 = blockIdx.x * 128;

    float acc[4][4][4];
#pragma unroll
    for (int i = 0; i < 4; i++)
#pragma unroll
        for (int j = 0; j < 4; j++)
#pragma unroll
            for (int q = 0; q < 4; q++) acc[i][j][q] = 0.f;

    for (int k0 = 0; k0 < K; k0 += 32) {
#pragma unroll
        for (int q = 0; q < 4; q++) {
            int idx = tid + q * 256;
            int row = idx >> 3, k4 = (idx & 7) * 4;
            float4 v = *(const float4*)(A + (size_t)(row0 + row) * K + k0 + k4);
            uint32_t* d = &As[row * AST + k4];
            d[0] = f2tf32(v.x); d[1] = f2tf32(v.y); d[2] = f2tf32(v.z); d[3] = f2tf32(v.w);
        }
#pragma unroll
        for (int q = 0; q < 4; q++) {
            int idx = tid + q * 256;
            int k = idx >> 5, n4 = (idx & 31) * 4;
            float4 v = *(const float4*)(B + (size_t)(k0 + k) * ldB + col0 + n4);
            uint32_t* d = &Bs[k * BSTN + n4];
            d[0] = f2tf32(v.x); d[1] = f2tf32(v.y); d[2] = f2tf32(v.z); d[3] = f2tf32(v.w);
        }
        __syncthreads();
#pragma unroll
        for (int kq = 0; kq < 4; kq++) {
            int kb = kq * 8;
            uint32_t af[4][4];
#pragma unroll
            for (int i = 0; i < 4; i++) {
                int base = (wm * 64 + i * 16 + gid) * AST + kb + tig;
                af[i][0] = As[base];
                af[i][1] = As[base + 8 * AST];
                af[i][2] = As[base + 4];
                af[i][3] = As[base + 8 * AST + 4];
            }
#pragma unroll
            for (int j = 0; j < 4; j++) {
                int ncol = wn * 32 + j * 8 + gid;
                uint32_t b0 = Bs[(kb + tig) * BSTN + ncol];
                uint32_t b1 = Bs[(kb + tig + 4) * BSTN + ncol];
#pragma unroll
                for (int i = 0; i < 4; i++)
                    mma_tf32(acc[i][j][0], acc[i][j][1], acc[i][j][2], acc[i][j][3],
                             af[i][0], af[i][1], af[i][2], af[i][3], b0, b1);
            }
        }
        __syncthreads();
    }
#pragma unroll
    for (int i = 0; i < 4; i++) {
#pragma unroll
        for (int j = 0; j < 4; j++) {
            int r = row0 + wm * 64 + i * 16 + gid;
            int cix = col0 + wn * 32 + j * 8 + tig * 2;
            float rb0 = rowbias ? rowbias[r] : 0.f;
            float rb8 = rowbias ? rowbias[r + 8] : 0.f;
            C[(size_t)r * N + cix]           = acc[i][j][0] + rb0;
            C[(size_t)r * N + cix + 1]       = acc[i][j][1] + rb0;
            C[(size_t)(r + 8) * N + cix]     = acc[i][j][2] + rb8;
            C[(size_t)(r + 8) * N + cix + 1] = acc[i][j][3] + rb8;
        }
    }
}

// =================================================================
// SIMT SGEMM NT (small GEMMs)
// =================================================================
__global__ __launch_bounds__(256) void gemm_nt(
    const float* __restrict__ A, const float* __restrict__ B,
    const float* __restrict__ colbias, float* __restrict__ C,
    int M, int N, int K, int act)
{
    __shared__ float As[16][128];
    __shared__ float Bs[16][128];
    int tid = threadIdx.x;
    int tx = tid & 15, ty = tid >> 4;
    int row0 = blockIdx.y * 128, col0 = blockIdx.x * 128;

    u64 acc[8][4];
#pragma unroll
    for (int i = 0; i < 8; i++)
#pragma unroll
        for (int j = 0; j < 4; j++) acc[i][j] = 0ull;

    int lr = tid >> 2, lc = tid & 3;
    for (int k0 = 0; k0 < K; k0 += 16) {
#pragma unroll
        for (int p = 0; p < 2; p++) {
            int r = lr + p * 64, gr = row0 + r;
            float4 v = make_float4(0.f, 0.f, 0.f, 0.f);
            if (gr < M) v = *(const float4*)(A + (size_t)gr * K + k0 + lc * 4);
            As[lc*4+0][r] = v.x; As[lc*4+1][r] = v.y; As[lc*4+2][r] = v.z; As[lc*4+3][r] = v.w;
        }
#pragma unroll
        for (int p = 0; p < 2; p++) {
            int r = lr + p * 64, gc = col0 + r;
            float4 v = make_float4(0.f, 0.f, 0.f, 0.f);
            if (gc < N) v = *(const float4*)(B + (size_t)gc * K + k0 + lc * 4);
            Bs[lc*4+0][r] = v.x; Bs[lc*4+1][r] = v.y; Bs[lc*4+2][r] = v.z; Bs[lc*4+3][r] = v.w;
        }
        __syncthreads();
#pragma unroll
        for (int kk = 0; kk < 16; kk++) {
            float a[8];
            *(float4*)&a[0] = *(const float4*)&As[kk][ty * 8];
            *(float4*)&a[4] = *(const float4*)&As[kk][ty * 8 + 4];
            u64 b4[4];
#pragma unroll
            for (int j = 0; j < 4; j++) b4[j] = *(const u64*)&Bs[kk][tx * 8 + 2 * j];
#pragma unroll
            for (int i = 0; i < 8; i++) {
                u64 ai = bcast2(a[i]);
#pragma unroll
                for (int j = 0; j < 4; j++) fma2(acc[i][j], ai, b4[j]);
            }
        }
        __syncthreads();
    }
#pragma unroll
    for (int i = 0; i < 8; i++) {
        int gm = row0 + ty * 8 + i;
        if (gm >= M) continue;
#pragma unroll
        for (int j = 0; j < 4; j++) {
            float2 c2 = unpk(acc[i][j]);
            int gn = col0 + tx * 8 + 2 * j;
            float v0 = c2.x, v1 = c2.y;
            if (colbias) { v0 += colbias[gn]; v1 += colbias[gn + 1]; }
            if (act == 1) { v0 = fmaxf(v0, 0.f); v1 = fmaxf(v1, 0.f); }
            if (gn < N)     C[(size_t)gm * N + gn]     = v0;
            if (gn + 1 < N) C[(size_t)gm * N + gn + 1] = v1;
        }
    }
}

// =================================================================
// Persistent GRU v14: fp16 mma.m16n8k16, A operands direct from
// fp16 fragment-layout hfrag. 128 blocks x 256 threads (8 warps).
// Block owns 8 hidden cols; warp w owns k-slice [128w, 128w+128).
// hfrag slot (per t): (((w*7+mt)*8+kt)*32 + lane) uint4 = 4 f16x2 regs
//   a0={row gid,k 2tig..+1} a1={gid+8,same} a2={gid,k+8} a3={gid+8,k+8}
// =================================================================
#define PBS 9
#define PBUF_F (112 * 24 * PBS)
#define GRU_SMEM (PBUF_F * 4)

__device__ __forceinline__ void gridbar()
{
    __threadfence();
    __syncthreads();
    if (threadIdx.x == 0) {
        volatile unsigned* vg = &g_gen;
        unsigned target = *vg + 1;
        if (atomicAdd(&g_cnt, 1) == gridDim.x - 1) {
            g_cnt = 0;
            __threadfence();
            atomicAdd(&g_gen, 1);
        } else {
            while ((int)(*vg - target) < 0) { }
        }
        __threadfence();
    }
    __syncthreads();
}

__global__ __launch_bounds__(256, 1) void gru_mma(
    const float* __restrict__ xpt, const float* __restrict__ Whh,
    const float* __restrict__ bhh, float* __restrict__ hbt,
    unsigned* __restrict__ hfragu)
{
    extern __shared__ float pbuf[];
    int tid  = threadIdx.x;
    int w    = tid >> 5;
    int lane = tid & 31;
    int gidq = lane >> 2;
    int tig  = lane & 3;
    int col0 = blockIdx.x * 8;
    int k0   = w * 128;

    // register-resident Whh fragments (fp16, 48 regs)
    uint32_t bf[8][3][2];
#pragma unroll
    for (int kt = 0; kt < 8; kt++) {
#pragma unroll
        for (int j = 0; j < 3; j++) {
            int n = j * 8 + gidq;
            int c = n / 3, g = n % 3;
            const float* wrow = Whh + ((size_t)g * HD + col0 + c) * HD;
            int kb = k0 + kt * 16 + 2 * tig;
            bf[kt][j][0] = packh2(wrow[kb],     wrow[kb + 1]);
            bf[kt][j][1] = packh2(wrow[kb + 8], wrow[kb + 9]);
        }
    }

    for (int t = 0; t < TT; t++) {
        if (t > 0) {
            const uint4* fb = (const uint4*)(hfragu + (size_t)(t - 1) * HFRAGU_T)
                              + (size_t)w * 7 * 8 * 32 + lane;
#pragma unroll 1
            for (int mt = 0; mt < 7; mt++) {
                float c0[3], c1[3], c2[3], c3[3];
#pragma unroll
                for (int j = 0; j < 3; j++) { c0[j] = 0.f; c1[j] = 0.f; c2[j] = 0.f; c3[j] = 0.f; }

                const uint4* fm = fb + (size_t)(mt * 8) * 32;
#pragma unroll
                for (int kt = 0; kt < 8; kt++) {
                    uint4 a = fm[(size_t)kt * 32];
#pragma unroll
                    for (int j = 0; j < 3; j++)
                        mma_f16(c0[j], c1[j], c2[j], c3[j],
                                a.x, a.y, a.z, a.w, bf[kt][j][0], bf[kt][j][1]);
                }

                int r0 = mt * 16 + gidq;
#pragma unroll
                for (int j = 0; j < 3; j++) {
                    int n0 = j * 8 + tig * 2;
                    pbuf[((size_t)r0 * 24 + n0) * PBS + w]           = c0[j];
                    pbuf[((size_t)r0 * 24 + n0 + 1) * PBS + w]       = c1[j];
                    pbuf[((size_t)(r0 + 8) * 24 + n0) * PBS + w]     = c2[j];
                    pbuf[((size_t)(r0 + 8) * 24 + n0 + 1) * PBS + w] = c3[j];
                }
            }
        }
        __syncthreads();

        // fused reduction + gate epilogue
        __half* hf = (__half*)(hfragu + (size_t)t * HFRAGU_T);
        for (int idx = tid; idx < NB * 8; idx += 256) {
            int b = idx >> 3, c = idx & 7;
            int col = col0 + c;
            float ar = 0.f, az = 0.f, an = 0.f;
            if (t > 0) {
                const float* pr = pbuf + ((size_t)b * 24 + c * 3) * PBS;
#pragma unroll
                for (int ww = 0; ww < 8; ww++) {
                    ar += pr[ww];
                    az += pr[PBS + ww];
                    an += pr[2 * PBS + ww];
                }
            }
            size_t xbase = ((size_t)t * NB + b) * H3;
            float xr = xpt[xbase + col];
            float xz = xpt[xbase + HD + col];
            float xn = xpt[xbase + 2 * HD + col];
            float hold = (t > 0) ? hbt[(size_t)(t - 1) * HBT_STRIDE + (size_t)b * HD + col] : 0.f;
            float r = fsig(xr + ar + bhh[col]);
            float z = fsig(xz + az + bhh[HD + col]);
            float n = ftanh(xn + r * (an + bhh[2 * HD + col]));
            float hnew = (1.f - z) * n + z * hold;

            hbt[(size_t)t * HBT_STRIDE + (size_t)b * HD + col] = hnew;

            // fp16 fragment-layout write
            int fw  = col >> 7;
            int kl  = col & 127;
            int fkt = kl >> 4;
            int kk  = kl & 15;
            int ah  = kk >> 3;
            int ktg = (kk & 7) >> 1;
            int hlf = kk & 1;
            int fgid = b & 7;
            int rh   = (b >> 3) & 1;
            int fmt  = b >> 4;
            size_t u32idx = ((((size_t)fw * 7 + fmt) * 8 + fkt) * 32 + fgid * 4 + ktg) * 4
                            + (rh + 2 * ah);
            hf[u32idx * 2 + hlf] = __float2half_rn(hnew);
        }

        gridbar();
    }
}

// =================================================================
// one-pass online-softmax reduce
// =================================================================
__global__ void att_reduce_flat(const float* __restrict__ S,
                                const float* __restrict__ H,
                                float* __restrict__ v)
{
    int j = blockIdx.x * 256 + threadIdx.x;
    float mx = -1e30f, se = 0.f, sv = 0.f;
#pragma unroll 4
    for (int u = 0; u < TT; u++) {
        float s = S[(size_t)u * NDB + j];
        float h = H[(size_t)u * HBT_STRIDE + j];
        float m2 = fmaxf(mx, s);
        float cor = __expf(mx - m2);
        float e = __expf(s - m2);
        se = se * cor + e;
        sv = sv * cor + e * h;
        mx = m2;
    }
    v[j] = __fdividef(sv, se);
}

// pool attention, row-major v -> catv[c][d]
__global__ void pool_att(const float* __restrict__ v, const float* __restrict__ pW,
                         const float* __restrict__ pb, float* __restrict__ catv)
{
    int c = blockIdx.x;
    int d = blockIdx.y * 256 + threadIdx.x;
    __shared__ float sW[400];
    __shared__ float sb[20];
    for (int i = threadIdx.x; i < 400; i += 256) sW[i] = pW[i];
    if (threadIdx.x < 20) sb[threadIdx.x] = pb[threadIdx.x];
    __syncthreads();

    float xv[20];
#pragma unroll
    for (int s = 0; s < 20; s++) xv[s] = v[(size_t)(c * 20 + s) * HD + d];
    float wv[20]; float mx = -1e30f;
#pragma unroll
    for (int u = 0; u < 20; u++) {
        float s = sb[u];
#pragma unroll
        for (int t2 = 0; t2 < 20; t2++) s += xv[t2] * sW[u * 20 + t2];
        wv[u] = s; mx = fmaxf(mx, s);
    }
    float se = 0.f, sv = 0.f;
#pragma unroll
    for (int u = 0; u < 20; u++) {
        float e = __expf(wv[u] - mx);
        se += e; sv += e * xv[u];
    }
    catv[(size_t)c * HD + d] = __fdividef(sv, se);
}

// two dots per node (row-major)
__global__ void dot2(const float* __restrict__ h, const float* __restrict__ a1,
                     const float* __restrict__ a2, float* __restrict__ o1,
                     float* __restrict__ o2)
{
    int n = blockIdx.x;
    __shared__ float s1[256], s2[256];
    float p1 = 0.f, p2 = 0.f;
    for (int k = threadIdx.x; k < HD; k += 256) {
        float hv = h[(size_t)n * HD + k];
        p1 += hv * a1[k]; p2 += hv * a2[k];
    }
    s1[threadIdx.x] = p1; s2[threadIdx.x] = p2;
    __syncthreads();
    for (int s = 128; s > 0; s >>= 1) {
        if (threadIdx.x < s) { s1[threadIdx.x] += s1[threadIdx.x + s]; s2[threadIdx.x] += s2[threadIdx.x + s]; }
        __syncthreads();
    }
    if (threadIdx.x == 0) { o1[n] = s1[0]; o2[n] = s2[0]; }
}

// GAT aggregation (complete cliques + self loops), row-major
__global__ void gat_agg(const float* __restrict__ h, const float* __restrict__ as,
                        const float* __restrict__ ad, const float* __restrict__ bias,
                        float* __restrict__ out, int group)
{
    int n = blockIdx.x;
    int base = (n / group) * group;
    __shared__ float alpha[32];
    if (threadIdx.x == 0) {
        float e[32]; float mx = -1e30f;
        for (int s = 0; s < group; s++) {
            float x = as[base + s] + ad[n];
            x = (x > 0.f) ? x : 0.2f * x;
            e[s] = x; mx = fmaxf(mx, x);
        }
        float se = 0.f;
        for (int s = 0; s < group; s++) { e[s] = __expf(e[s] - mx); se += e[s]; }
        for (int s = 0; s < group; s++) alpha[s] = __fdividef(e[s], se);
    }
    __syncthreads();
    for (int dd = threadIdx.x; dd < HD; dd += 256) {
        float acc = 0.f;
        for (int s = 0; s < group; s++)
            acc += alpha[s] * h[(size_t)(base + s) * HD + dd];
        out[(size_t)n * HD + dd] = acc + bias[dd];
    }
}

// fusion concat (row-major)
__global__ void build_fusion(const float* __restrict__ v, const float* __restrict__ catv,
                             const float* __restrict__ inner, float* __restrict__ fin)
{
    int idx = blockIdx.x * 256 + threadIdx.x;
    if (idx >= NB * H3) return;
    int n = idx / H3, k = idx - n * H3;
    float val;
    if (k < HD)            val = v[(size_t)n * HD + k];
    else if (k < 2 * HD)   val = catv[(size_t)(n / 20) * HD + (k - HD)];
    else                   val = inner[(size_t)n * HD + (k - 2 * HD)];
    fin[idx] = val;
}

// heads (row-major)
__global__ void heads(const float* __restrict__ f, const float* __restrict__ rw,
                      const float* __restrict__ rb, const float* __restrict__ cw,
                      const float* __restrict__ cb, float* __restrict__ out)
{
    int n = blockIdx.x;
    __shared__ float s1[256], s2[256];
    float p1 = 0.f, p2 = 0.f;
    for (int k = threadIdx.x; k < HD; k += 256) {
        float fv = f[(size_t)n * HD + k];
        p1 += fv * rw[k]; p2 += fv * cw[k];
    }
    s1[threadIdx.x] = p1; s2[threadIdx.x] = p2;
    __syncthreads();
    for (int s = 128; s > 0; s >>= 1) {
        if (threadIdx.x < s) { s1[threadIdx.x] += s1[threadIdx.x + s]; s2[threadIdx.x] += s2[threadIdx.x + s]; }
        __syncthreads();
    }
    if (threadIdx.x == 0) {
        out[n]      = s1[0] + rb[0];
        out[NB + n] = fsig(s2[0] + cb[0]);
    }
}

// =================================================================
extern "C" void kernel_launch(void* const* d_in, const int* in_sizes, int n_in,
                              void* d_out, int out_size)
{
    const float* weekly  = (const float*)d_in[0];
    const float* Wih     = (const float*)d_in[1];
    const float* Whh     = (const float*)d_in[2];
    const float* bih     = (const float*)d_in[3];
    const float* bhh     = (const float*)d_in[4];
    const float* encW    = (const float*)d_in[5];
    const float* encB    = (const float*)d_in[6];
    const float* poolW   = (const float*)d_in[7];
    const float* poolB   = (const float*)d_in[8];
    const float* innerW  = (const float*)d_in[9];
    const float* innerAs = (const float*)d_in[10];
    const float* innerAd = (const float*)d_in[11];
    const float* innerB  = (const float*)d_in[12];
    const float* catW    = (const float*)d_in[13];
    const float* catAs   = (const float*)d_in[14];
    const float* catAd   = (const float*)d_in[15];
    const float* catB    = (const float*)d_in[16];
    const float* fusW    = (const float*)d_in[17];
    const float* fusB    = (const float*)d_in[18];
    const float* regW    = (const float*)d_in[19];
    const float* regB    = (const float*)d_in[20];
    const float* clsW    = (const float*)d_in[21];
    const float* clsB    = (const float*)d_in[22];
    float* out = (float*)d_out;

    float *xp, *hbt, *v, *hp, *inner, *catv, *hp2, *catg, *as_, *ad_, *as2, *ad2, *fin, *f;
    unsigned* hfragu;
    cudaGetSymbolAddress((void**)&xp,     g_xp);
    cudaGetSymbolAddress((void**)&hbt,    g_hbt);
    cudaGetSymbolAddress((void**)&hfragu, g_hfrag);
    cudaGetSymbolAddress((void**)&v,      g_v);
    cudaGetSymbolAddress((void**)&hp,     g_hp);
    cudaGetSymbolAddress((void**)&inner,  g_inner);
    cudaGetSymbolAddress((void**)&catv,   g_catv);
    cudaGetSymbolAddress((void**)&hp2,    g_hp2);
    cudaGetSymbolAddress((void**)&catg,   g_cat);
    cudaGetSymbolAddress((void**)&as_,    g_as);
    cudaGetSymbolAddress((void**)&ad_,    g_ad);
    cudaGetSymbolAddress((void**)&as2,    g_as2);
    cudaGetSymbolAddress((void**)&ad2,    g_ad2);
    cudaGetSymbolAddress((void**)&fin,    g_fin);
    cudaGetSymbolAddress((void**)&f,      g_f);

    // 1) xp = weekly @ Wih^T + bih, written as [t][b][g] (remap=1)
    gemm_nt_tc<<<dim3(H3 / 128, (NB * TT) / 128), 256>>>(weekly, Wih, bih, xp, NB * TT, H3, IND, 0, 1);

    // 2) persistent fp16 mma GRU (fragment-layout h feed)
    cudaFuncSetAttribute(gru_mma, cudaFuncAttributeMaxDynamicSharedMemorySize, GRU_SMEM);
    gru_mma<<<128, 256, GRU_SMEM>>>(xp, Whh, bhh, hbt, hfragu);

    // 3) S(512 x 102400) = encW @ Hflat + encB[u]
    gemm_nn_tc<<<dim3(NDB / 128, TT / 128), 256>>>(encW, hbt, encB, xp, TT, NDB, TT, (size_t)HBT_STRIDE);

    // 4) v[j] = softmax-over-u(S) . H
    att_reduce_flat<<<NDB / 256, 256>>>(xp, hbt, v);

    // 5) inner GAT: hp = v @ innerW^T
    gemm_nt<<<dim3(HD / 128, 1), 256>>>(v, innerW, nullptr, hp, NB, HD, HD, 0);
    dot2<<<NB, 256>>>(hp, innerAs, innerAd, as_, ad_);
    gat_agg<<<NB, 256>>>(hp, as_, ad_, innerB, inner, 20);

    // 6) pool 20 stocks -> category vectors
    pool_att<<<dim3(5, HD / 256), 256>>>(v, poolW, poolB, catv);

    // 7) category GAT
    gemm_nt<<<dim3(HD / 128, 1), 256>>>(catv, catW, nullptr, hp2, 5, HD, HD, 0);
    dot2<<<5, 256>>>(hp2, catAs, catAd, as2, ad2);
    gat_agg<<<5, 256>>>(hp2, as2, ad2, catB, catg, 5);

    // 8) fusion
    build_fusion<<<(NB * H3 + 255) / 256, 256>>>(v, catg, inner, fin);
    gemm_nt<<<dim3(HD / 128, 1), 256>>>(fin, fusW, fusB, f, NB, HD, H3, 1);

    // 9) heads
    heads<<<NB, 256>>>(f, regW, regB, clsW, clsB, out);
}